// round 4
// baseline (speedup 1.0000x reference)
#include <cuda_runtime.h>
#include <math.h>

// ---------------- problem constants ----------------
#define BB 8
#define CC 512
#define HH 64
#define WW 64
#define PP 4096          // H*W
#define NHH 8
#define HDD 64

// ---------------- scratch (static device globals; no allocation) ----------------
__device__ float g_box1[BB*64*PP];        // 8 MB
__device__ float g_boxes[BB*4*PP];
__device__ float g_edge1[BB*64*PP];       // 8 MB (GN applied in-place)
__device__ float g_edge[BB*NHH*PP];
__device__ float g_qkv[(size_t)BB*1536*PP];   // 201 MB
__device__ float g_attn[(size_t)BB*NHH*HDD*WW*WW]; // 67 MB
__device__ float g_agg[(size_t)BB*CC*PP];     // 67 MB
__device__ float g_y[(size_t)BB*CC*PP];       // 67 MB
__device__ float g_gnstats[BB*8*2];
__device__ float g_bnstats[CC*2];

// ---------------- helpers ----------------
__device__ __forceinline__ float geluf(float x) {
    return 0.5f * x * (1.0f + erff(x * 0.70710678118654752440f));
}
__device__ __forceinline__ float sigm(float x) {
    return 1.0f / (1.0f + __expf(-x));
}

// ---------------- generic 3x3 conv (SAME pad), implicit GEMM ----------------
// grid.x = B*H (one output row per CTA), grid.y = Cout/64. block = 128.
// Input may come from two concatenated tensors (for the fusion conv).
// ACT: 0 = none, 1 = exact GELU
#define CI_CHUNK 8
template<int ACT>
__global__ __launch_bounds__(128) void conv3x3_k(
    const float* __restrict__ in1, int Cin1,
    const float* __restrict__ in2, int Cin2,
    const float* __restrict__ wgt, const float* __restrict__ bias,
    float* __restrict__ out, int Cout)
{
    const int Cin = Cin1 + Cin2;
    const int bh = blockIdx.x;
    const int b = bh >> 6;
    const int h = bh & 63;
    const int co0 = blockIdx.y * 64;
    const int t = threadIdx.x;
    const int tx = t & 7;    // w group of 8: w = tx*8 .. tx*8+7
    const int ty = t >> 3;   // co group of 4: co = co0 + ty*4 .. +3

    __shared__ float sIn[CI_CHUNK][3][66];
    __shared__ float sW[64][CI_CHUNK * 9];

    float acc[4][8];
#pragma unroll
    for (int a = 0; a < 4; a++)
#pragma unroll
        for (int j = 0; j < 8; j++) acc[a][j] = 0.f;

    for (int cb = 0; cb < Cin; cb += CI_CHUNK) {
        __syncthreads();
        // load input slab: CI_CHUNK channels x 3 rows x 66 cols (zero padded)
        for (int idx = t; idx < CI_CHUNK * 3 * 66; idx += 128) {
            int ci = idx / 198;
            int rem = idx - ci * 198;
            int r = rem / 66;
            int col = rem - r * 66;
            int cg = cb + ci;
            float v = 0.f;
            int gh = h - 1 + r;
            int gw = col - 1;
            if (cg < Cin && (unsigned)gh < 64u && (unsigned)gw < 64u) {
                const float* p = (cg < Cin1)
                    ? (in1 + ((size_t)(b * Cin1 + cg)) * PP)
                    : (in2 + ((size_t)(b * Cin2 + (cg - Cin1))) * PP);
                v = p[gh * 64 + gw];
            }
            sIn[ci][r][col] = v;
        }
        // load weight slab: 64 co x CI_CHUNK ci x 9
        for (int idx = t; idx < 64 * CI_CHUNK * 9; idx += 128) {
            int co = idx / (CI_CHUNK * 9);
            int rem = idx - co * (CI_CHUNK * 9);
            int ci = rem / 9;
            int kk = rem - ci * 9;
            int cg = cb + ci;
            float v = 0.f;
            if (cg < Cin) v = wgt[((size_t)(co0 + co) * Cin + cg) * 9 + kk];
            sW[co][ci * 9 + kk] = v;
        }
        __syncthreads();

#pragma unroll 2
        for (int ci = 0; ci < CI_CHUNK; ci++) {
#pragma unroll
            for (int r = 0; r < 3; r++) {
                float iv[10];
#pragma unroll
                for (int j = 0; j < 10; j++) iv[j] = sIn[ci][r][tx * 8 + j];
#pragma unroll
                for (int cj = 0; cj < 4; cj++) {
                    float w0 = sW[ty * 4 + cj][ci * 9 + r * 3 + 0];
                    float w1 = sW[ty * 4 + cj][ci * 9 + r * 3 + 1];
                    float w2 = sW[ty * 4 + cj][ci * 9 + r * 3 + 2];
#pragma unroll
                    for (int wj = 0; wj < 8; wj++) {
                        acc[cj][wj] = fmaf(w0, iv[wj + 0], acc[cj][wj]);
                        acc[cj][wj] = fmaf(w1, iv[wj + 1], acc[cj][wj]);
                        acc[cj][wj] = fmaf(w2, iv[wj + 2], acc[cj][wj]);
                    }
                }
            }
        }
    }

#pragma unroll
    for (int cj = 0; cj < 4; cj++) {
        int co = co0 + ty * 4 + cj;
        float bv = bias[co];
#pragma unroll
        for (int wj = 0; wj < 8; wj++) {
            float v = acc[cj][wj] + bv;
            if (ACT == 1) v = geluf(v);
            out[(((size_t)b * Cout + co) * 64 + h) * 64 + tx * 8 + wj] = v;
        }
    }
}

// ---------------- small 1x1 conv (Cout small): one CTA per (b, co) x p-tile ----------
// ACT: 0 none, 2 sigmoid
template<int ACT>
__global__ void conv1x1_small_k(
    const float* __restrict__ in, const float* __restrict__ wgt,
    const float* __restrict__ bias, float* __restrict__ out,
    int Cin, int Cout)
{
    int bc = blockIdx.x;
    int b = bc / Cout;
    int co = bc - b * Cout;
    int p = blockIdx.y * 256 + threadIdx.x;
    float acc = bias[co];
    const float* ip = in + (size_t)b * Cin * PP + p;
    const float* wp = wgt + (size_t)co * Cin;
    for (int ci = 0; ci < Cin; ci++)
        acc = fmaf(wp[ci], ip[(size_t)ci * PP], acc);
    if (ACT == 2) acc = sigm(acc);
    out[((size_t)b * Cout + co) * PP + p] = acc;
}

// ---------------- big 1x1 conv = GEMM (qkv) ----------------
// grid.x = B*32 (p tiles of 128), grid.y = Cout/64. block = 128.
__global__ __launch_bounds__(128) void gemm1x1_k(
    const float* __restrict__ in, const float* __restrict__ wgt,
    const float* __restrict__ bias, float* __restrict__ out,
    int Cin, int Cout)
{
    int bp = blockIdx.x;
    int b = bp >> 5;
    int p0 = (bp & 31) * 128;
    int co0 = blockIdx.y * 64;
    int t = threadIdx.x;
    int tx = t & 15;   // p group of 8
    int ty = t >> 4;   // co group of 8

    __shared__ float sW[64][17];
    __shared__ float sB[16][132];

    float acc[8][8];
#pragma unroll
    for (int j = 0; j < 8; j++)
#pragma unroll
        for (int c = 0; c < 8; c++) acc[j][c] = 0.f;

    const float* inb = in + (size_t)b * Cin * PP;

    for (int k0 = 0; k0 < Cin; k0 += 16) {
        __syncthreads();
        for (int idx = t; idx < 1024; idx += 128) {
            int co = idx >> 4, k = idx & 15;
            sW[co][k] = wgt[((size_t)(co0 + co)) * Cin + k0 + k];
        }
        for (int idx = t; idx < 2048; idx += 128) {
            int k = idx >> 7, p = idx & 127;
            sB[k][p] = inb[(size_t)(k0 + k) * PP + p0 + p];
        }
        __syncthreads();
#pragma unroll 4
        for (int k = 0; k < 16; k++) {
            float a[8], bb[8];
#pragma unroll
            for (int j = 0; j < 8; j++) a[j] = sW[ty * 8 + j][k];
            float4 b0 = *(const float4*)&sB[k][tx * 8];
            float4 b1 = *(const float4*)&sB[k][tx * 8 + 4];
            bb[0] = b0.x; bb[1] = b0.y; bb[2] = b0.z; bb[3] = b0.w;
            bb[4] = b1.x; bb[5] = b1.y; bb[6] = b1.z; bb[7] = b1.w;
#pragma unroll
            for (int j = 0; j < 8; j++)
#pragma unroll
                for (int c = 0; c < 8; c++)
                    acc[j][c] = fmaf(a[j], bb[c], acc[j][c]);
        }
    }
#pragma unroll
    for (int j = 0; j < 8; j++) {
        int co = co0 + ty * 8 + j;
        float bv = bias[co];
        float* op = out + ((size_t)b * Cout + co) * PP + p0 + tx * 8;
#pragma unroll
        for (int c = 0; c < 8; c++) op[c] = acc[j][c] + bv;
    }
}

// ---------------- GroupNorm stats (per (b, group of 8 ch)) ----------------
__global__ void gn_stats_k(const float* __restrict__ x, float* __restrict__ stats)
{
    int bg = blockIdx.x;              // b*8 + g
    int b = bg >> 3;
    int g = bg & 7;
    const float* p = x + ((size_t)b * 64 + g * 8) * PP;
    float s = 0.f, s2 = 0.f;
    for (int i = threadIdx.x; i < 8 * PP; i += 256) {
        float v = p[i];
        s += v; s2 += v * v;
    }
    __shared__ float rs[8], rs2[8];
#pragma unroll
    for (int o = 16; o > 0; o >>= 1) {
        s  += __shfl_down_sync(0xffffffffu, s,  o);
        s2 += __shfl_down_sync(0xffffffffu, s2, o);
    }
    int w = threadIdx.x >> 5, l = threadIdx.x & 31;
    if (l == 0) { rs[w] = s; rs2[w] = s2; }
    __syncthreads();
    if (w == 0) {
        s  = (l < 8) ? rs[l]  : 0.f;
        s2 = (l < 8) ? rs2[l] : 0.f;
#pragma unroll
        for (int o = 4; o > 0; o >>= 1) {
            s  += __shfl_down_sync(0xffffffffu, s,  o);
            s2 += __shfl_down_sync(0xffffffffu, s2, o);
        }
        if (l == 0) {
            float m = s / 32768.f;
            stats[bg * 2] = m;
            stats[bg * 2 + 1] = s2 / 32768.f - m * m;
        }
    }
}

// ---------------- GroupNorm apply + GELU (in place) ----------------
__global__ void gn_apply_k(float* __restrict__ x, const float* __restrict__ stats,
                           const float* __restrict__ gamma, const float* __restrict__ beta)
{
    size_t idx = (size_t)blockIdx.x * 256 + threadIdx.x;  // total 8*64*4096
    int c = (int)((idx >> 12) & 63);
    int b = (int)(idx >> 18);
    int bg = b * 8 + (c >> 3);
    float m = stats[bg * 2], v = stats[bg * 2 + 1];
    float xn = (x[idx] - m) * rsqrtf(v + 1e-5f) * gamma[c] + beta[c];
    x[idx] = geluf(xn);
}

// ---------------- attention logits: per (b,h,i) do 64x64x64 GEMM + edge bias ----------
__global__ __launch_bounds__(128) void attn_logits_k(
    const float* __restrict__ qkv, const float* __restrict__ edge,
    float* __restrict__ attn)
{
    int id = blockIdx.x;           // (b*8+h)*64 + i
    int i = id & 63;
    int h = (id >> 6) & 7;
    int b = id >> 9;
    const float* Q = qkv + ((size_t)(b * 1536 + h * 64 + i)) * PP;        // (y,w)
    const float* K = qkv + ((size_t)(b * 1536 + 512 + h * 64 + i)) * PP;  // (y,W')
    __shared__ float sQ[64][65], sK[64][65];
    int t = threadIdx.x;
    for (int idx = t; idx < 4096; idx += 128) {
        int r = idx >> 6, c = idx & 63;
        sQ[r][c] = Q[idx];
        sK[r][c] = K[idx];
    }
    __syncthreads();
    int tx = t & 15, ty = t >> 4;   // w = ty*8+j, W' = tx*4+c
    float acc[8][4];
#pragma unroll
    for (int j = 0; j < 8; j++)
#pragma unroll
        for (int c = 0; c < 4; c++) acc[j][c] = 0.f;

#pragma unroll 8
    for (int y = 0; y < 64; y++) {
        float qv[8], kv[4];
#pragma unroll
        for (int j = 0; j < 8; j++) qv[j] = sQ[y][ty * 8 + j];
#pragma unroll
        for (int c = 0; c < 4; c++) kv[c] = sK[y][tx * 4 + c];
#pragma unroll
        for (int j = 0; j < 8; j++)
#pragma unroll
            for (int c = 0; c < 4; c++)
                acc[j][c] = fmaf(qv[j], kv[c], acc[j][c]);
    }
    float* op = attn + (size_t)id * 4096;
    const float* ep = edge + (size_t)id * 64;
#pragma unroll
    for (int j = 0; j < 8; j++) {
        int w = ty * 8 + j;
        float e = ep[w];
#pragma unroll
        for (int c = 0; c < 4; c++)
            op[w * 64 + tx * 4 + c] = acc[j][c] * 0.125f + e;  // scale = 64^-0.5
    }
}

// ---------------- softmax over i (stride 4096 within a (b,h) block) ----------------
__global__ __launch_bounds__(128) void softmax_i_k(float* __restrict__ attn)
{
    int n = blockIdx.x * 128 + threadIdx.x;  // 64 bh * 4096 ww = 262144
    int bh = n >> 12;
    int ww = n & 4095;
    float* p = attn + (size_t)bh * 262144 + ww;
    float x[64];
    float mx = -1e30f;
#pragma unroll
    for (int i = 0; i < 64; i++) {
        x[i] = p[(size_t)i * 4096];
        mx = fmaxf(mx, x[i]);
    }
    float s = 0.f;
#pragma unroll
    for (int i = 0; i < 64; i++) {
        x[i] = __expf(x[i] - mx);
        s += x[i];
    }
    float inv = 1.f / s;
#pragma unroll
    for (int i = 0; i < 64; i++) p[(size_t)i * 4096] = x[i] * inv;
}

// ---------------- AV: agg[d,w] = sum_W' A[w,W'] * V[d,W'] per (b,h,i) -------------
__global__ __launch_bounds__(128) void attn_av_k(
    const float* __restrict__ qkv, const float* __restrict__ attn,
    float* __restrict__ agg)
{
    int id = blockIdx.x;
    int i = id & 63;
    int h = (id >> 6) & 7;
    int b = id >> 9;
    const float* V = qkv + ((size_t)(b * 1536 + 1024 + h * 64 + i)) * PP;  // (d,W')
    const float* A = attn + (size_t)id * 4096;                            // (w,W')
    __shared__ float sV[64][65], sA[64][65];
    int t = threadIdx.x;
    for (int idx = t; idx < 4096; idx += 128) {
        int r = idx >> 6, c = idx & 63;
        sV[r][c] = V[idx];
        sA[r][c] = A[idx];
    }
    __syncthreads();
    int tx = t & 15, ty = t >> 4;   // d = ty*8+j, w = tx*4+c
    float acc[8][4];
#pragma unroll
    for (int j = 0; j < 8; j++)
#pragma unroll
        for (int c = 0; c < 4; c++) acc[j][c] = 0.f;

#pragma unroll 8
    for (int kk = 0; kk < 64; kk++) {
        float vv[8], av[4];
#pragma unroll
        for (int j = 0; j < 8; j++) vv[j] = sV[ty * 8 + j][kk];
#pragma unroll
        for (int c = 0; c < 4; c++) av[c] = sA[tx * 4 + c][kk];
#pragma unroll
        for (int j = 0; j < 8; j++)
#pragma unroll
            for (int c = 0; c < 4; c++)
                acc[j][c] = fmaf(vv[j], av[c], acc[j][c]);
    }
    float* op = agg + ((size_t)(b * 512 + h * 64 + i)) * PP;
#pragma unroll
    for (int j = 0; j < 8; j++)
#pragma unroll
        for (int c = 0; c < 4; c++)
            op[(ty * 8 + j) * 64 + tx * 4 + c] = acc[j][c];
}

// ---------------- BatchNorm stats (per channel over B,H,W) ----------------
__global__ void bn_stats_k(const float* __restrict__ y, float* __restrict__ stats)
{
    int c = blockIdx.x;
    float s = 0.f, s2 = 0.f;
    for (int n = threadIdx.x; n < 32768; n += 256) {
        int b = n >> 12, p = n & 4095;
        float v = y[((size_t)b * CC + c) * PP + p];
        s += v; s2 += v * v;
    }
    __shared__ float rs[8], rs2[8];
#pragma unroll
    for (int o = 16; o > 0; o >>= 1) {
        s  += __shfl_down_sync(0xffffffffu, s,  o);
        s2 += __shfl_down_sync(0xffffffffu, s2, o);
    }
    int w = threadIdx.x >> 5, l = threadIdx.x & 31;
    if (l == 0) { rs[w] = s; rs2[w] = s2; }
    __syncthreads();
    if (w == 0) {
        s  = (l < 8) ? rs[l]  : 0.f;
        s2 = (l < 8) ? rs2[l] : 0.f;
#pragma unroll
        for (int o = 4; o > 0; o >>= 1) {
            s  += __shfl_down_sync(0xffffffffu, s,  o);
            s2 += __shfl_down_sync(0xffffffffu, s2, o);
        }
        if (l == 0) {
            float m = s / 32768.f;
            stats[c * 2] = m;
            stats[c * 2 + 1] = s2 / 32768.f - m * m;
        }
    }
}

// ---------------- BN apply + SiLU -> output ----------------
__global__ void bn_apply_k(const float* __restrict__ y, const float* __restrict__ stats,
                           const float* __restrict__ g, const float* __restrict__ bt,
                           float* __restrict__ out)
{
    size_t idx = (size_t)blockIdx.x * 256 + threadIdx.x;  // 8*512*4096
    int c = (int)((idx >> 12) & 511);
    float m = stats[c * 2], v = stats[c * 2 + 1];
    float yn = (y[idx] - m) * rsqrtf(v + 1e-5f) * g[c] + bt[c];
    out[idx] = yn * (1.f / (1.f + __expf(-yn)));
}

// ---------------- launch ----------------
extern "C" void kernel_launch(void* const* d_in, const int* in_sizes, int n_in,
                              void* d_out, int out_size)
{
    const float* x       = (const float*)d_in[0];
    const float* box_w1  = (const float*)d_in[1];
    const float* box_b1  = (const float*)d_in[2];
    const float* box_w2  = (const float*)d_in[3];
    const float* box_b2  = (const float*)d_in[4];
    const float* edge_w1 = (const float*)d_in[5];
    const float* edge_b1 = (const float*)d_in[6];
    const float* gn_g    = (const float*)d_in[7];
    const float* gn_b    = (const float*)d_in[8];
    const float* edge_w2 = (const float*)d_in[9];
    const float* edge_b2 = (const float*)d_in[10];
    const float* qkv_w   = (const float*)d_in[11];
    const float* qkv_b   = (const float*)d_in[12];
    const float* fus_w   = (const float*)d_in[13];
    const float* fus_b   = (const float*)d_in[14];
    const float* bn_g    = (const float*)d_in[15];
    const float* bn_b    = (const float*)d_in[16];
    float* out = (float*)d_out;

    float *box1, *boxes, *edge1, *edge, *qkv, *attn, *agg, *y, *gnst, *bnst;
    cudaGetSymbolAddress((void**)&box1,  g_box1);
    cudaGetSymbolAddress((void**)&boxes, g_boxes);
    cudaGetSymbolAddress((void**)&edge1, g_edge1);
    cudaGetSymbolAddress((void**)&edge,  g_edge);
    cudaGetSymbolAddress((void**)&qkv,   g_qkv);
    cudaGetSymbolAddress((void**)&attn,  g_attn);
    cudaGetSymbolAddress((void**)&agg,   g_agg);
    cudaGetSymbolAddress((void**)&y,     g_y);
    cudaGetSymbolAddress((void**)&gnst,  g_gnstats);
    cudaGetSymbolAddress((void**)&bnst,  g_bnstats);

    // box net: conv3x3(512->64)+GELU ; conv1x1(64->4)+sigmoid
    conv3x3_k<1><<<dim3(BB * HH, 1), 128>>>(x, 512, nullptr, 0, box_w1, box_b1, box1, 64);
    conv1x1_small_k<2><<<dim3(BB * 4, 16), 256>>>(box1, box_w2, box_b2, boxes, 64, 4);

    // edge net: conv3x3(4->64) ; GN(8) ; GELU ; conv1x1(64->8)
    conv3x3_k<0><<<dim3(BB * HH, 1), 128>>>(boxes, 4, nullptr, 0, edge_w1, edge_b1, edge1, 64);
    gn_stats_k<<<64, 256>>>(edge1, gnst);
    gn_apply_k<<<8192, 256>>>(edge1, gnst, gn_g, gn_b);
    conv1x1_small_k<0><<<dim3(BB * 8, 16), 256>>>(edge1, edge_w2, edge_b2, edge, 64, 8);

    // qkv 1x1 conv (512 -> 1536)
    gemm1x1_k<<<dim3(BB * 32, 24), 128>>>(x, qkv_w, qkv_b, qkv, 512, 1536);

    // attention
    attn_logits_k<<<4096, 128>>>(qkv, edge, attn);
    softmax_i_k<<<2048, 128>>>(attn);
    attn_av_k<<<4096, 128>>>(qkv, attn, agg);

    // fusion conv3x3(concat(x,agg): 1024 -> 512)
    conv3x3_k<0><<<dim3(BB * HH, 8), 128>>>(x, 512, agg, 512, fus_w, fus_b, y, 512);

    // batchnorm (training stats) + SiLU
    bn_stats_k<<<512, 256>>>(y, bnst);
    bn_apply_k<<<65536, 256>>>(y, bnst, bn_g, bn_b, out);
}

// round 6
// speedup vs baseline: 3.1509x; 3.1509x over previous
#include <cuda_runtime.h>
#include <cuda_bf16.h>
#include <cstdint>
#include <math.h>

#define BB 8
#define CC 512
#define PP 4096
#define NHH 8

// ---- scratch (static device globals; no allocation) ----
__device__ float g_box1[BB*64*PP];
__device__ float g_boxes[BB*4*PP];
__device__ float g_edge1[BB*64*PP];
__device__ float g_edge[BB*NHH*PP];
__device__ float g_qkv[(size_t)BB*1536*PP];
__device__ float g_attn[(size_t)BB*NHH*64*64*64];
__device__ float g_agg[(size_t)BB*CC*PP];
__device__ float g_y[(size_t)BB*CC*PP];
__device__ float g_gnstats[BB*8*2];
__device__ float g_bnstats[CC*2];
__device__ __nv_bfloat16 g_xhi[(size_t)BB*PP*1024];   // [b][p][ci]
__device__ __nv_bfloat16 g_xlo[(size_t)BB*PP*1024];
__device__ __nv_bfloat16 g_wfhi[512*9*1024];          // [co][tap][ci]
__device__ __nv_bfloat16 g_wflo[512*9*1024];
__device__ __nv_bfloat16 g_wqhi[1536*512];            // [co][ci]
__device__ __nv_bfloat16 g_wqlo[1536*512];

__device__ __forceinline__ float geluf(float x) {
    return 0.5f * x * (1.0f + erff(x * 0.70710678118654752440f));
}
__device__ __forceinline__ float sigm(float x) { return 1.0f / (1.0f + __expf(-x)); }

// ---- arch-neutral tensor-core helpers (sm_80+ PTX only) ----
__device__ __forceinline__ uint32_t smem_u32(const void* p) {
    uint32_t a;
    asm("{ .reg .u64 t; cvta.to.shared.u64 t, %1; cvt.u32.u64 %0, t; }" : "=r"(a) : "l"(p));
    return a;
}
__device__ __forceinline__ void ldsm_x4(uint32_t* r, uint32_t addr) {
    asm volatile("ldmatrix.sync.aligned.m8n8.x4.shared.b16 {%0,%1,%2,%3}, [%4];"
        : "=r"(r[0]), "=r"(r[1]), "=r"(r[2]), "=r"(r[3]) : "r"(addr));
}
__device__ __forceinline__ void mma16816(float* d, const uint32_t* a, const uint32_t* b) {
    asm volatile("mma.sync.aligned.m16n8k16.row.col.f32.bf16.bf16.f32 "
        "{%0,%1,%2,%3}, {%4,%5,%6,%7}, {%8,%9}, {%0,%1,%2,%3};"
        : "+f"(d[0]), "+f"(d[1]), "+f"(d[2]), "+f"(d[3])
        : "r"(a[0]), "r"(a[1]), "r"(a[2]), "r"(a[3]), "r"(b[0]), "r"(b[1]));
}
__device__ __forceinline__ void cpa16(uint32_t dst, const void* src, uint32_t sz) {
    asm volatile("cp.async.cg.shared.global [%0], [%1], 16, %2;\n" :: "r"(dst), "l"(src), "r"(sz));
}
#define CP_COMMIT() asm volatile("cp.async.commit_group;\n" ::: "memory")
#define CP_WAIT1()  asm volatile("cp.async.wait_group 1;\n" ::: "memory")
#define CP_WAIT0()  asm volatile("cp.async.wait_group 0;\n" ::: "memory")

// ---- split / transpose: NCHW fp32 -> [b][p][ci] bf16 hi/lo ----
__global__ void split_k(const float* __restrict__ src, __nv_bfloat16* __restrict__ xhi,
                        __nv_bfloat16* __restrict__ xlo, int Cn, int cibase)
{
    __shared__ float tile[32][33];
    int bz = blockIdx.z, c0 = blockIdx.x * 32, p0 = blockIdx.y * 32;
    int tx = threadIdx.x, ty = threadIdx.y;
#pragma unroll
    for (int i = 0; i < 32; i += 8)
        tile[ty + i][tx] = src[((size_t)bz * Cn + c0 + ty + i) * 4096 + p0 + tx];
    __syncthreads();
#pragma unroll
    for (int i = 0; i < 32; i += 8) {
        float v = tile[tx][ty + i];
        __nv_bfloat16 h = __float2bfloat16(v);
        size_t o = ((size_t)bz * 4096 + p0 + ty + i) * 1024 + cibase + c0 + tx;
        xhi[o] = h;
        xlo[o] = __float2bfloat16(v - __bfloat162float(h));
    }
}

// OIHW fp32 -> [co][tap][ci] bf16 hi/lo
__global__ void wsplit_k(const float* __restrict__ w, __nv_bfloat16* __restrict__ whi,
                         __nv_bfloat16* __restrict__ wlo, int Cin, int taps, size_t total)
{
    size_t i = (size_t)blockIdx.x * 256 + threadIdx.x;
    if (i >= total) return;
    int tap = (int)(i % taps);
    size_t t2 = i / taps;
    int ci = (int)(t2 % Cin);
    int co = (int)(t2 / Cin);
    float v = w[i];
    __nv_bfloat16 h = __float2bfloat16(v);
    size_t dst = ((size_t)co * taps + tap) * Cin + ci;
    whi[dst] = h;
    wlo[dst] = __float2bfloat16(v - __bfloat162float(h));
}

// ---- mma.sync implicit GEMM: 128(co) x 128(px) CTA tile, K folded taps*ci ----
// smem stage: Ahi[128][72] Alo Bhi[128][72] Blo (rows padded to 144B, ldmatrix conflict-free)
#define MSTAGE 73728
#define A_LO 18432
#define B_HI 36864
#define B_LO 55296

template<int TAPS>
__device__ __forceinline__ void mm_load(uint32_t sb, int t,
    const __nv_bfloat16* __restrict__ whi, const __nv_bfloat16* __restrict__ wlo,
    const __nv_bfloat16* __restrict__ xhi, const __nv_bfloat16* __restrict__ xlo,
    int co0, int WCin, int b, int pbase, int c)
{
    int cik = c / TAPS, tap = c - cik * TAPS;
    int dh = (TAPS == 9) ? tap / 3 - 1 : 0;
    int dw = (TAPS == 9) ? tap % 3 - 1 : 0;
    int ci0 = cik * 64;
#pragma unroll
    for (int i = 0; i < 8; i++) {           // A: 2(hl) x 128 rows x 8 segs
        int idx = t + i * 256;
        int hl = idx >> 10, rem = idx & 1023, row = rem >> 3, seg = rem & 7;
        const __nv_bfloat16* src = (hl ? wlo : whi)
            + ((size_t)(co0 + row) * TAPS + tap) * WCin + ci0 + seg * 8;
        cpa16(sb + hl * A_LO + row * 144 + seg * 16, src, 16u);
    }
#pragma unroll
    for (int i = 0; i < 8; i++) {           // B: 2(hl) x 128 px rows x 8 segs
        int idx = t + i * 256;
        int hl = idx >> 10, rem = idx & 1023, row = rem >> 3, seg = rem & 7;
        int p = pbase + row;
        int ih = (p >> 6) + dh, iw = (p & 63) + dw;
        bool ok = (TAPS == 1) || (((unsigned)ih < 64u) && ((unsigned)iw < 64u));
        const __nv_bfloat16* src = (hl ? xlo : xhi)
            + ((size_t)(b * 4096 + (ok ? ih * 64 + iw : 0))) * 1024 + ci0 + seg * 8;
        cpa16(sb + B_HI + hl * (B_LO - B_HI) + row * 144 + seg * 16, src, ok ? 16u : 0u);
    }
}

template<int TAPS>
__global__ __launch_bounds__(256) void mma_mm(
    const __nv_bfloat16* __restrict__ whi, const __nv_bfloat16* __restrict__ wlo,
    const __nv_bfloat16* __restrict__ xhi, const __nv_bfloat16* __restrict__ xlo,
    const float* __restrict__ bias, float* __restrict__ out, int WCin, int Cout)
{
    extern __shared__ char dynsmem[];
    const int b = blockIdx.x >> 5;
    const int pbase = (blockIdx.x & 31) * 128;
    const int co0 = blockIdx.y * 128;
    const int t = threadIdx.x, lane = t & 31, warp = t >> 5;
    const int wm = warp & 1, wn = warp >> 1;      // 2 m-warps x 4 n-warps
    const uint32_t sb0 = smem_u32(dynsmem);
    const int NCH = (WCin / 64) * TAPS;

    float acc[4][4][4];
#pragma unroll
    for (int fm = 0; fm < 4; fm++)
#pragma unroll
        for (int fn = 0; fn < 4; fn++)
#pragma unroll
            for (int k = 0; k < 4; k++) acc[fm][fn][k] = 0.f;

    mm_load<TAPS>(sb0, t, whi, wlo, xhi, xlo, co0, WCin, b, pbase, 0); CP_COMMIT();
    mm_load<TAPS>(sb0 + MSTAGE, t, whi, wlo, xhi, xlo, co0, WCin, b, pbase, 1); CP_COMMIT();

    // per-lane ldmatrix base offsets
    const int arow = wm * 64 + (lane & 15);
    const int akoff = (lane >> 4) * 16;           // bytes: (lane>>4)*8 bf16
    const int l8 = lane & 7, grp = lane >> 3;
    const int brow = wn * 32 + l8 + (grp >> 1) * 8;
    const int bkoff = (grp & 1) * 16;             // bytes

    for (int c = 0; c < NCH; c++) {
        const uint32_t sb = sb0 + (c & 1) * MSTAGE;
        if (c == NCH - 1) { CP_WAIT0(); } else { CP_WAIT1(); }
        __syncthreads();
        const uint32_t abase = sb + arow * 144 + akoff;
        const uint32_t bbase = sb + B_HI + brow * 144 + bkoff;
#pragma unroll
        for (int ks = 0; ks < 4; ks++) {
            const int kb = ks * 32;               // 16 bf16 per kstep
            uint32_t ah[4][4], al[4][4];
#pragma unroll
            for (int fm = 0; fm < 4; fm++) {
                ldsm_x4(ah[fm], abase + fm * 16 * 144 + kb);
                ldsm_x4(al[fm], abase + A_LO + fm * 16 * 144 + kb);
            }
            uint32_t bh[4][2], bl[4][2];
#pragma unroll
            for (int fp = 0; fp < 2; fp++) {
                uint32_t r[4];
                uint32_t addr = bbase + fp * 16 * 144 + kb;
                ldsm_x4(r, addr);
                bh[fp*2][0] = r[0]; bh[fp*2][1] = r[1];
                bh[fp*2+1][0] = r[2]; bh[fp*2+1][1] = r[3];
                ldsm_x4(r, addr + (B_LO - B_HI));
                bl[fp*2][0] = r[0]; bl[fp*2][1] = r[1];
                bl[fp*2+1][0] = r[2]; bl[fp*2+1][1] = r[3];
            }
#pragma unroll
            for (int fm = 0; fm < 4; fm++)
#pragma unroll
                for (int fn = 0; fn < 4; fn++) {
                    mma16816(acc[fm][fn], ah[fm], bh[fn]);
                    mma16816(acc[fm][fn], ah[fm], bl[fn]);
                    mma16816(acc[fm][fn], al[fm], bh[fn]);
                }
        }
        __syncthreads();
        if (c + 2 < NCH) {
            mm_load<TAPS>(sb, t, whi, wlo, xhi, xlo, co0, WCin, b, pbase, c + 2);
            CP_COMMIT();
        }
    }

    // epilogue: D[m][n]: rows lane>>2 (+8), cols 2*(lane&3)+{0,1}
    const int r0 = lane >> 2, c0 = (lane & 3) * 2;
#pragma unroll
    for (int fm = 0; fm < 4; fm++) {
        int co = co0 + wm * 64 + fm * 16 + r0;
        float bv0 = bias[co], bv8 = bias[co + 8];
        float* op0 = out + ((size_t)b * Cout + co) * 4096 + pbase;
        float* op8 = op0 + (size_t)8 * 4096;
#pragma unroll
        for (int fn = 0; fn < 4; fn++) {
            int p = wn * 32 + fn * 8 + c0;
            float2 v0 = make_float2(acc[fm][fn][0] + bv0, acc[fm][fn][1] + bv0);
            float2 v8 = make_float2(acc[fm][fn][2] + bv8, acc[fm][fn][3] + bv8);
            *(float2*)(op0 + p) = v0;
            *(float2*)(op8 + p) = v8;
        }
    }
}

// ---- FFMA 3x3 conv (box 512->64, edge 4->64) ----
#define CI_CHUNK 8
template<int ACT>
__global__ __launch_bounds__(128) void conv3x3_k(
    const float* __restrict__ in1, int Cin,
    const float* __restrict__ wgt, const float* __restrict__ bias,
    float* __restrict__ out, int Cout)
{
    const int bh = blockIdx.x, b = bh >> 6, h = bh & 63;
    const int co0 = blockIdx.y * 64;
    const int t = threadIdx.x, tx = t & 7, ty = t >> 3;
    __shared__ float sIn[CI_CHUNK][3][66];
    __shared__ float sW[64][CI_CHUNK * 9];
    float acc[4][8];
#pragma unroll
    for (int a = 0; a < 4; a++)
#pragma unroll
        for (int j = 0; j < 8; j++) acc[a][j] = 0.f;

    for (int cb = 0; cb < Cin; cb += CI_CHUNK) {
        __syncthreads();
        for (int idx = t; idx < CI_CHUNK * 3 * 66; idx += 128) {
            int ci = idx / 198, rem = idx - ci * 198, r = rem / 66, col = rem - r * 66;
            int cg = cb + ci;
            float v = 0.f;
            int gh = h - 1 + r, gw = col - 1;
            if (cg < Cin && (unsigned)gh < 64u && (unsigned)gw < 64u)
                v = in1[((size_t)(b * Cin + cg)) * PP + gh * 64 + gw];
            sIn[ci][r][col] = v;
        }
        for (int idx = t; idx < 64 * CI_CHUNK * 9; idx += 128) {
            int co = idx / (CI_CHUNK * 9), rem = idx - co * (CI_CHUNK * 9);
            int ci = rem / 9, kk = rem - ci * 9, cg = cb + ci;
            sW[co][ci * 9 + kk] = (cg < Cin) ? wgt[((size_t)(co0 + co) * Cin + cg) * 9 + kk] : 0.f;
        }
        __syncthreads();
#pragma unroll 2
        for (int ci = 0; ci < CI_CHUNK; ci++) {
#pragma unroll
            for (int r = 0; r < 3; r++) {
                float iv[10];
#pragma unroll
                for (int j = 0; j < 10; j++) iv[j] = sIn[ci][r][tx * 8 + j];
#pragma unroll
                for (int cj = 0; cj < 4; cj++) {
                    float w0 = sW[ty * 4 + cj][ci * 9 + r * 3 + 0];
                    float w1 = sW[ty * 4 + cj][ci * 9 + r * 3 + 1];
                    float w2 = sW[ty * 4 + cj][ci * 9 + r * 3 + 2];
#pragma unroll
                    for (int wj = 0; wj < 8; wj++) {
                        acc[cj][wj] = fmaf(w0, iv[wj + 0], acc[cj][wj]);
                        acc[cj][wj] = fmaf(w1, iv[wj + 1], acc[cj][wj]);
                        acc[cj][wj] = fmaf(w2, iv[wj + 2], acc[cj][wj]);
                    }
                }
            }
        }
    }
#pragma unroll
    for (int cj = 0; cj < 4; cj++) {
        int co = co0 + ty * 4 + cj;
        float bv = bias[co];
#pragma unroll
        for (int wj = 0; wj < 8; wj++) {
            float v = acc[cj][wj] + bv;
            if (ACT == 1) v = geluf(v);
            out[(((size_t)b * Cout + co) * 64 + h) * 64 + tx * 8 + wj] = v;
        }
    }
}

template<int ACT>
__global__ void conv1x1_small_k(const float* __restrict__ in, const float* __restrict__ wgt,
                                const float* __restrict__ bias, float* __restrict__ out,
                                int Cin, int Cout)
{
    int bc = blockIdx.x, b = bc / Cout, co = bc - b * Cout;
    int p = blockIdx.y * 256 + threadIdx.x;
    float acc = bias[co];
    const float* ip = in + (size_t)b * Cin * PP + p;
    const float* wp = wgt + (size_t)co * Cin;
    for (int ci = 0; ci < Cin; ci++)
        acc = fmaf(wp[ci], ip[(size_t)ci * PP], acc);
    if (ACT == 2) acc = sigm(acc);
    out[((size_t)b * Cout + co) * PP + p] = acc;
}

// ---- GroupNorm ----
__global__ void gn_stats_k(const float* __restrict__ x, float* __restrict__ stats)
{
    int bg = blockIdx.x, b = bg >> 3, g = bg & 7;
    const float* p = x + ((size_t)b * 64 + g * 8) * PP;
    float s = 0.f, s2 = 0.f;
    for (int i = threadIdx.x; i < 8 * PP; i += 256) {
        float v = p[i]; s += v; s2 += v * v;
    }
    __shared__ float rs[8], rs2[8];
#pragma unroll
    for (int o = 16; o > 0; o >>= 1) {
        s += __shfl_down_sync(0xffffffffu, s, o);
        s2 += __shfl_down_sync(0xffffffffu, s2, o);
    }
    int w = threadIdx.x >> 5, l = threadIdx.x & 31;
    if (l == 0) { rs[w] = s; rs2[w] = s2; }
    __syncthreads();
    if (w == 0) {
        s = (l < 8) ? rs[l] : 0.f; s2 = (l < 8) ? rs2[l] : 0.f;
#pragma unroll
        for (int o = 4; o > 0; o >>= 1) {
            s += __shfl_down_sync(0xffffffffu, s, o);
            s2 += __shfl_down_sync(0xffffffffu, s2, o);
        }
        if (l == 0) {
            float m = s / 32768.f;
            stats[bg * 2] = m;
            stats[bg * 2 + 1] = s2 / 32768.f - m * m;
        }
    }
}

__global__ void gn_apply_k(float* __restrict__ x, const float* __restrict__ stats,
                           const float* __restrict__ gamma, const float* __restrict__ beta)
{
    size_t idx = (size_t)blockIdx.x * 256 + threadIdx.x;
    int c = (int)((idx >> 12) & 63);
    int b = (int)(idx >> 18);
    int bg = b * 8 + (c >> 3);
    float m = stats[bg * 2], v = stats[bg * 2 + 1];
    float xn = (x[idx] - m) * rsqrtf(v + 1e-5f) * gamma[c] + beta[c];
    x[idx] = geluf(xn);
}

// ---- attention ----
__global__ __launch_bounds__(128) void attn_logits_k(
    const float* __restrict__ qkv, const float* __restrict__ edge, float* __restrict__ attn)
{
    int id = blockIdx.x;
    int i = id & 63, h = (id >> 6) & 7, b = id >> 9;
    const float* Q = qkv + ((size_t)(b * 1536 + h * 64 + i)) * PP;
    const float* K = qkv + ((size_t)(b * 1536 + 512 + h * 64 + i)) * PP;
    __shared__ float sQ[64][65], sK[64][65];
    int t = threadIdx.x;
    for (int idx = t; idx < 4096; idx += 128) {
        int r = idx >> 6, c = idx & 63;
        sQ[r][c] = Q[idx]; sK[r][c] = K[idx];
    }
    __syncthreads();
    int tx = t & 15, ty = t >> 4;
    float acc[8][4];
#pragma unroll
    for (int j = 0; j < 8; j++)
#pragma unroll
        for (int c = 0; c < 4; c++) acc[j][c] = 0.f;
#pragma unroll 8
    for (int y = 0; y < 64; y++) {
        float qv[8], kv[4];
#pragma unroll
        for (int j = 0; j < 8; j++) qv[j] = sQ[y][ty * 8 + j];
#pragma unroll
        for (int c = 0; c < 4; c++) kv[c] = sK[y][tx * 4 + c];
#pragma unroll
        for (int j = 0; j < 8; j++)
#pragma unroll
            for (int c = 0; c < 4; c++)
                acc[j][c] = fmaf(qv[j], kv[c], acc[j][c]);
    }
    float* op = attn + (size_t)id * 4096;
    const float* ep = edge + (size_t)id * 64;
#pragma unroll
    for (int j = 0; j < 8; j++) {
        int w = ty * 8 + j;
        float e = ep[w];
#pragma unroll
        for (int c = 0; c < 4; c++)
            op[w * 64 + tx * 4 + c] = acc[j][c] * 0.125f + e;
    }
}

__global__ __launch_bounds__(128) void softmax_i_k(float* __restrict__ attn)
{
    int n = blockIdx.x * 128 + threadIdx.x;
    int bh = n >> 12, ww = n & 4095;
    float* p = attn + (size_t)bh * 262144 + ww;
    float x[64], mx = -1e30f;
#pragma unroll
    for (int i = 0; i < 64; i++) { x[i] = p[(size_t)i * 4096]; mx = fmaxf(mx, x[i]); }
    float s = 0.f;
#pragma unroll
    for (int i = 0; i < 64; i++) { x[i] = __expf(x[i] - mx); s += x[i]; }
    float inv = 1.f / s;
#pragma unroll
    for (int i = 0; i < 64; i++) p[(size_t)i * 4096] = x[i] * inv;
}

__global__ __launch_bounds__(128) void attn_av_k(
    const float* __restrict__ qkv, const float* __restrict__ attn, float* __restrict__ agg)
{
    int id = blockIdx.x;
    int i = id & 63, h = (id >> 6) & 7, b = id >> 9;
    const float* V = qkv + ((size_t)(b * 1536 + 1024 + h * 64 + i)) * PP;
    const float* A = attn + (size_t)id * 4096;
    __shared__ float sV[64][65], sA[64][65];
    int t = threadIdx.x;
    for (int idx = t; idx < 4096; idx += 128) {
        int r = idx >> 6, c = idx & 63;
        sV[r][c] = V[idx]; sA[r][c] = A[idx];
    }
    __syncthreads();
    int tx = t & 15, ty = t >> 4;
    float acc[8][4];
#pragma unroll
    for (int j = 0; j < 8; j++)
#pragma unroll
        for (int c = 0; c < 4; c++) acc[j][c] = 0.f;
#pragma unroll 8
    for (int kk = 0; kk < 64; kk++) {
        float vv[8], av[4];
#pragma unroll
        for (int j = 0; j < 8; j++) vv[j] = sV[ty * 8 + j][kk];
#pragma unroll
        for (int c = 0; c < 4; c++) av[c] = sA[tx * 4 + c][kk];
#pragma unroll
        for (int j = 0; j < 8; j++)
#pragma unroll
            for (int c = 0; c < 4; c++)
                acc[j][c] = fmaf(vv[j], av[c], acc[j][c]);
    }
    float* op = agg + ((size_t)(b * 512 + h * 64 + i)) * PP;
#pragma unroll
    for (int j = 0; j < 8; j++)
#pragma unroll
        for (int c = 0; c < 4; c++)
            op[(ty * 8 + j) * 64 + tx * 4 + c] = acc[j][c];
}

// ---- BatchNorm ----
__global__ void bn_stats_k(const float* __restrict__ y, float* __restrict__ stats)
{
    int c = blockIdx.x;
    float s = 0.f, s2 = 0.f;
    for (int n = threadIdx.x; n < 32768; n += 256) {
        int b = n >> 12, p = n & 4095;
        float v = y[((size_t)b * CC + c) * PP + p];
        s += v; s2 += v * v;
    }
    __shared__ float rs[8], rs2[8];
#pragma unroll
    for (int o = 16; o > 0; o >>= 1) {
        s += __shfl_down_sync(0xffffffffu, s, o);
        s2 += __shfl_down_sync(0xffffffffu, s2, o);
    }
    int w = threadIdx.x >> 5, l = threadIdx.x & 31;
    if (l == 0) { rs[w] = s; rs2[w] = s2; }
    __syncthreads();
    if (w == 0) {
        s = (l < 8) ? rs[l] : 0.f; s2 = (l < 8) ? rs2[l] : 0.f;
#pragma unroll
        for (int o = 4; o > 0; o >>= 1) {
            s += __shfl_down_sync(0xffffffffu, s, o);
            s2 += __shfl_down_sync(0xffffffffu, s2, o);
        }
        if (l == 0) {
            float m = s / 32768.f;
            stats[c * 2] = m;
            stats[c * 2 + 1] = s2 / 32768.f - m * m;
        }
    }
}

__global__ void bn_apply_k(const float* __restrict__ y, const float* __restrict__ stats,
                           const float* __restrict__ g, const float* __restrict__ bt,
                           float* __restrict__ out)
{
    size_t idx = (size_t)blockIdx.x * 256 + threadIdx.x;
    int c = (int)((idx >> 12) & 511);
    float m = stats[c * 2], v = stats[c * 2 + 1];
    float yn = (y[idx] - m) * rsqrtf(v + 1e-5f) * g[c] + bt[c];
    out[idx] = yn * (1.f / (1.f + __expf(-yn)));
}

// ---- launch ----
extern "C" void kernel_launch(void* const* d_in, const int* in_sizes, int n_in,
                              void* d_out, int out_size)
{
    const float* x       = (const float*)d_in[0];
    const float* box_w1  = (const float*)d_in[1];
    const float* box_b1  = (const float*)d_in[2];
    const float* box_w2  = (const float*)d_in[3];
    const float* box_b2  = (const float*)d_in[4];
    const float* edge_w1 = (const float*)d_in[5];
    const float* edge_b1 = (const float*)d_in[6];
    const float* gn_g    = (const float*)d_in[7];
    const float* gn_b    = (const float*)d_in[8];
    const float* edge_w2 = (const float*)d_in[9];
    const float* edge_b2 = (const float*)d_in[10];
    const float* qkv_w   = (const float*)d_in[11];
    const float* qkv_b   = (const float*)d_in[12];
    const float* fus_w   = (const float*)d_in[13];
    const float* fus_b   = (const float*)d_in[14];
    const float* bn_g    = (const float*)d_in[15];
    const float* bn_b    = (const float*)d_in[16];
    float* out = (float*)d_out;

    float *box1, *boxes, *edge1, *edge, *qkv, *attn, *agg, *y, *gnst, *bnst;
    __nv_bfloat16 *xhi, *xlo, *wfhi, *wflo, *wqhi, *wqlo;
    cudaGetSymbolAddress((void**)&box1,  g_box1);
    cudaGetSymbolAddress((void**)&boxes, g_boxes);
    cudaGetSymbolAddress((void**)&edge1, g_edge1);
    cudaGetSymbolAddress((void**)&edge,  g_edge);
    cudaGetSymbolAddress((void**)&qkv,   g_qkv);
    cudaGetSymbolAddress((void**)&attn,  g_attn);
    cudaGetSymbolAddress((void**)&agg,   g_agg);
    cudaGetSymbolAddress((void**)&y,     g_y);
    cudaGetSymbolAddress((void**)&gnst,  g_gnstats);
    cudaGetSymbolAddress((void**)&bnst,  g_bnstats);
    cudaGetSymbolAddress((void**)&xhi,   g_xhi);
    cudaGetSymbolAddress((void**)&xlo,   g_xlo);
    cudaGetSymbolAddress((void**)&wfhi,  g_wfhi);
    cudaGetSymbolAddress((void**)&wflo,  g_wflo);
    cudaGetSymbolAddress((void**)&wqhi,  g_wqhi);
    cudaGetSymbolAddress((void**)&wqlo,  g_wqlo);

    cudaFuncSetAttribute(mma_mm<1>, cudaFuncAttributeMaxDynamicSharedMemorySize, 2 * MSTAGE);
    cudaFuncSetAttribute(mma_mm<9>, cudaFuncAttributeMaxDynamicSharedMemorySize, 2 * MSTAGE);

    // preprocessing: bf16 hi/lo splits
    split_k<<<dim3(16, 128, 8), dim3(32, 8)>>>(x, xhi, xlo, 512, 0);
    wsplit_k<<<(512 * 1024 * 9 + 255) / 256, 256>>>(fus_w, wfhi, wflo, 1024, 9, (size_t)512 * 1024 * 9);
    wsplit_k<<<(1536 * 512 + 255) / 256, 256>>>(qkv_w, wqhi, wqlo, 512, 1, (size_t)1536 * 512);

    // box net (FFMA): conv3x3(512->64)+GELU ; conv1x1(64->4)+sigmoid
    conv3x3_k<1><<<dim3(512, 1), 128>>>(x, 512, box_w1, box_b1, box1, 64);
    conv1x1_small_k<2><<<dim3(32, 16), 256>>>(box1, box_w2, box_b2, boxes, 64, 4);

    // edge net: conv3x3(4->64) ; GN ; GELU ; conv1x1(64->8)
    conv3x3_k<0><<<dim3(512, 1), 128>>>(boxes, 4, edge_w1, edge_b1, edge1, 64);
    gn_stats_k<<<64, 256>>>(edge1, gnst);
    gn_apply_k<<<8192, 256>>>(edge1, gnst, gn_g, gn_b);
    conv1x1_small_k<0><<<dim3(64, 16), 256>>>(edge1, edge_w2, edge_b2, edge, 64, 8);

    // qkv 1x1 (512->1536) on tensor cores (mma.sync bf16 split)
    mma_mm<1><<<dim3(256, 12), 256, 2 * MSTAGE>>>(wqhi, wqlo, xhi, xlo, qkv_b, qkv, 512, 1536);

    // attention
    attn_logits_k<<<4096, 128>>>(qkv, edge, attn);
    softmax_i_k<<<2048, 128>>>(attn);
    attn_av_k<<<4096, 128>>>(qkv, attn, agg);

    // split agg into ci[512:1024) of the bf16 buffer
    split_k<<<dim3(16, 128, 8), dim3(32, 8)>>>(agg, xhi, xlo, 512, 512);

    // fusion conv3x3 (1024->512) on tensor cores
    mma_mm<9><<<dim3(256, 4), 256, 2 * MSTAGE>>>(wfhi, wflo, xhi, xlo, fus_b, y, 1024, 512);

    // batchnorm + SiLU
    bn_stats_k<<<512, 256>>>(y, bnst);
    bn_apply_k<<<65536, 256>>>(y, bnst, bn_g, bn_b, out);
}

// round 7
// speedup vs baseline: 3.5904x; 1.1395x over previous
#include <cuda_runtime.h>
#include <cuda_bf16.h>
#include <cstdint>
#include <math.h>

#define BB 8
#define CC 512
#define PP 4096
#define NHH 8

// ---- scratch (static device globals; no allocation) ----
__device__ float g_box1[BB*64*PP];
__device__ float g_boxes[BB*4*PP];
__device__ float g_edge1[BB*64*PP];
__device__ float g_edge[BB*NHH*PP];
__device__ float g_qkv[(size_t)BB*1536*PP];
__device__ float g_attn[(size_t)BB*NHH*64*64*64];
__device__ float g_agg[(size_t)BB*CC*PP];
__device__ float g_y[(size_t)BB*CC*PP];
__device__ float g_gnstats[BB*8*2];
__device__ float g_bnstats[CC*2];
__device__ __nv_bfloat16 g_xhi[(size_t)BB*PP*1024];   // [b][p][ci]
__device__ __nv_bfloat16 g_xlo[(size_t)BB*PP*1024];
__device__ __nv_bfloat16 g_wfhi[512*9*1024];          // [co][tap][ci]
__device__ __nv_bfloat16 g_wflo[512*9*1024];
__device__ __nv_bfloat16 g_wbhi[64*9*512];            // box weights [co][tap][ci]
__device__ __nv_bfloat16 g_wblo[64*9*512];
__device__ __nv_bfloat16 g_wqhi[1536*512];            // [co][ci]
__device__ __nv_bfloat16 g_wqlo[1536*512];

__device__ __forceinline__ float geluf(float x) {
    return 0.5f * x * (1.0f + erff(x * 0.70710678118654752440f));
}
__device__ __forceinline__ float sigm(float x) { return 1.0f / (1.0f + __expf(-x)); }

// ---- arch-neutral tensor-core helpers (sm_80+ PTX only) ----
__device__ __forceinline__ uint32_t smem_u32(const void* p) {
    uint32_t a;
    asm("{ .reg .u64 t; cvta.to.shared.u64 t, %1; cvt.u32.u64 %0, t; }" : "=r"(a) : "l"(p));
    return a;
}
__device__ __forceinline__ void ldsm_x4(uint32_t* r, uint32_t addr) {
    asm volatile("ldmatrix.sync.aligned.m8n8.x4.shared.b16 {%0,%1,%2,%3}, [%4];"
        : "=r"(r[0]), "=r"(r[1]), "=r"(r[2]), "=r"(r[3]) : "r"(addr));
}
__device__ __forceinline__ void mma16816(float* d, const uint32_t* a, const uint32_t* b) {
    asm volatile("mma.sync.aligned.m16n8k16.row.col.f32.bf16.bf16.f32 "
        "{%0,%1,%2,%3}, {%4,%5,%6,%7}, {%8,%9}, {%0,%1,%2,%3};"
        : "+f"(d[0]), "+f"(d[1]), "+f"(d[2]), "+f"(d[3])
        : "r"(a[0]), "r"(a[1]), "r"(a[2]), "r"(a[3]), "r"(b[0]), "r"(b[1]));
}
__device__ __forceinline__ void cpa16(uint32_t dst, const void* src, uint32_t sz) {
    asm volatile("cp.async.cg.shared.global [%0], [%1], 16, %2;\n" :: "r"(dst), "l"(src), "r"(sz));
}
#define CP_COMMIT() asm volatile("cp.async.commit_group;\n" ::: "memory")
#define CP_WAIT1()  asm volatile("cp.async.wait_group 1;\n" ::: "memory")
#define CP_WAIT0()  asm volatile("cp.async.wait_group 0;\n" ::: "memory")

// ---- split / transpose: NCHW fp32 -> [b][p][ci] bf16 hi/lo ----
__global__ void split_k(const float* __restrict__ src, __nv_bfloat16* __restrict__ xhi,
                        __nv_bfloat16* __restrict__ xlo, int Cn, int cibase)
{
    __shared__ float tile[32][33];
    int bz = blockIdx.z, c0 = blockIdx.x * 32, p0 = blockIdx.y * 32;
    int tx = threadIdx.x, ty = threadIdx.y;
#pragma unroll
    for (int i = 0; i < 32; i += 8)
        tile[ty + i][tx] = src[((size_t)bz * Cn + c0 + ty + i) * 4096 + p0 + tx];
    __syncthreads();
#pragma unroll
    for (int i = 0; i < 32; i += 8) {
        float v = tile[tx][ty + i];
        __nv_bfloat16 h = __float2bfloat16(v);
        size_t o = ((size_t)bz * 4096 + p0 + ty + i) * 1024 + cibase + c0 + tx;
        xhi[o] = h;
        xlo[o] = __float2bfloat16(v - __bfloat162float(h));
    }
}

// OIHW fp32 -> [co][tap][ci] bf16 hi/lo
__global__ void wsplit_k(const float* __restrict__ w, __nv_bfloat16* __restrict__ whi,
                         __nv_bfloat16* __restrict__ wlo, int Cin, int taps, size_t total)
{
    size_t i = (size_t)blockIdx.x * 256 + threadIdx.x;
    if (i >= total) return;
    int tap = (int)(i % taps);
    size_t t2 = i / taps;
    int ci = (int)(t2 % Cin);
    int co = (int)(t2 / Cin);
    float v = w[i];
    __nv_bfloat16 h = __float2bfloat16(v);
    size_t dst = ((size_t)co * taps + tap) * Cin + ci;
    whi[dst] = h;
    wlo[dst] = __float2bfloat16(v - __bfloat162float(h));
}

// ---- mma.sync implicit GEMM: 128(co) x 128(px) CTA tile, K folded taps*ci ----
// smem stage: Ahi[128][72] Alo Bhi[128][72] Blo (rows padded to 144B)
#define MSTAGE 73728
#define A_LO 18432
#define B_HI 36864
#define B_LO 55296

template<int TAPS, int COUTV>
__device__ __forceinline__ void mm_load(uint32_t sb, int t,
    const __nv_bfloat16* __restrict__ whi, const __nv_bfloat16* __restrict__ wlo,
    const __nv_bfloat16* __restrict__ xhi, const __nv_bfloat16* __restrict__ xlo,
    int co0, int WCin, int b, int pbase, int c)
{
    int cik = c / TAPS, tap = c - cik * TAPS;
    int dh = (TAPS == 9) ? tap / 3 - 1 : 0;
    int dw = (TAPS == 9) ? tap % 3 - 1 : 0;
    int ci0 = cik * 64;
#pragma unroll
    for (int i = 0; i < 8; i++) {           // A: 2(hl) x 128 rows x 8 segs
        int idx = t + i * 256;
        int hl = idx >> 10, rem = idx & 1023, row = rem >> 3, seg = rem & 7;
        int rr = (COUTV < 128 && row >= COUTV) ? 0 : row;   // safe addr for dead rows
        const __nv_bfloat16* src = (hl ? wlo : whi)
            + ((size_t)(co0 + rr) * TAPS + tap) * WCin + ci0 + seg * 8;
        cpa16(sb + hl * A_LO + row * 144 + seg * 16, src,
              (COUTV < 128 && row >= COUTV) ? 0u : 16u);    // zero-fill dead rows
    }
#pragma unroll
    for (int i = 0; i < 8; i++) {           // B: 2(hl) x 128 px rows x 8 segs
        int idx = t + i * 256;
        int hl = idx >> 10, rem = idx & 1023, row = rem >> 3, seg = rem & 7;
        int p = pbase + row;
        int ih = (p >> 6) + dh, iw = (p & 63) + dw;
        bool ok = (TAPS == 1) || (((unsigned)ih < 64u) && ((unsigned)iw < 64u));
        const __nv_bfloat16* src = (hl ? xlo : xhi)
            + ((size_t)(b * 4096 + (ok ? ih * 64 + iw : 0))) * 1024 + ci0 + seg * 8;
        cpa16(sb + B_HI + hl * (B_LO - B_HI) + row * 144 + seg * 16, src, ok ? 16u : 0u);
    }
}

template<int TAPS, int ACT, int COUTV>
__global__ __launch_bounds__(256) void mma_mm(
    const __nv_bfloat16* __restrict__ whi, const __nv_bfloat16* __restrict__ wlo,
    const __nv_bfloat16* __restrict__ xhi, const __nv_bfloat16* __restrict__ xlo,
    const float* __restrict__ bias, float* __restrict__ out, int WCin, int Cout)
{
    extern __shared__ char dynsmem[];
    const int b = blockIdx.x >> 5;
    const int pbase = (blockIdx.x & 31) * 128;
    const int co0 = blockIdx.y * 128;
    const int t = threadIdx.x, lane = t & 31, warp = t >> 5;
    const int wm = warp & 1, wn = warp >> 1;      // 2 m-warps x 4 n-warps
    const uint32_t sb0 = smem_u32(dynsmem);
    const int NCH = (WCin / 64) * TAPS;

    float acc[4][4][4];
#pragma unroll
    for (int fm = 0; fm < 4; fm++)
#pragma unroll
        for (int fn = 0; fn < 4; fn++)
#pragma unroll
            for (int k = 0; k < 4; k++) acc[fm][fn][k] = 0.f;

    mm_load<TAPS, COUTV>(sb0, t, whi, wlo, xhi, xlo, co0, WCin, b, pbase, 0); CP_COMMIT();
    mm_load<TAPS, COUTV>(sb0 + MSTAGE, t, whi, wlo, xhi, xlo, co0, WCin, b, pbase, 1); CP_COMMIT();

    const int arow = wm * 64 + (lane & 15);
    const int akoff = (lane >> 4) * 16;
    const int l8 = lane & 7, grp = lane >> 3;
    const int brow = wn * 32 + l8 + (grp >> 1) * 8;
    const int bkoff = (grp & 1) * 16;

    for (int c = 0; c < NCH; c++) {
        const uint32_t sb = sb0 + (c & 1) * MSTAGE;
        if (c == NCH - 1) { CP_WAIT0(); } else { CP_WAIT1(); }
        __syncthreads();
        const uint32_t abase = sb + arow * 144 + akoff;
        const uint32_t bbase = sb + B_HI + brow * 144 + bkoff;
#pragma unroll
        for (int ks = 0; ks < 4; ks++) {
            const int kb = ks * 32;
            uint32_t ah[4][4], al[4][4];
#pragma unroll
            for (int fm = 0; fm < 4; fm++) {
                ldsm_x4(ah[fm], abase + fm * 16 * 144 + kb);
                ldsm_x4(al[fm], abase + A_LO + fm * 16 * 144 + kb);
            }
            uint32_t bh[4][2], bl[4][2];
#pragma unroll
            for (int fp = 0; fp < 2; fp++) {
                uint32_t r[4];
                uint32_t addr = bbase + fp * 16 * 144 + kb;
                ldsm_x4(r, addr);
                bh[fp*2][0] = r[0]; bh[fp*2][1] = r[1];
                bh[fp*2+1][0] = r[2]; bh[fp*2+1][1] = r[3];
                ldsm_x4(r, addr + (B_LO - B_HI));
                bl[fp*2][0] = r[0]; bl[fp*2][1] = r[1];
                bl[fp*2+1][0] = r[2]; bl[fp*2+1][1] = r[3];
            }
#pragma unroll
            for (int fm = 0; fm < 4; fm++)
#pragma unroll
                for (int fn = 0; fn < 4; fn++) {
                    mma16816(acc[fm][fn], ah[fm], bh[fn]);
                    mma16816(acc[fm][fn], ah[fm], bl[fn]);
                    mma16816(acc[fm][fn], al[fm], bh[fn]);
                }
        }
        __syncthreads();
        if (c + 2 < NCH) {
            mm_load<TAPS, COUTV>(sb, t, whi, wlo, xhi, xlo, co0, WCin, b, pbase, c + 2);
            CP_COMMIT();
        }
    }

    // epilogue
    const int r0 = lane >> 2, c0 = (lane & 3) * 2;
#pragma unroll
    for (int fm = 0; fm < 4; fm++) {
        int co = co0 + wm * 64 + fm * 16 + r0;
        bool v0ok = (COUTV >= 128) || (co < COUTV);
        bool v8ok = (COUTV >= 128) || (co + 8 < COUTV);
        float bv0 = v0ok ? bias[co] : 0.f;
        float bv8 = v8ok ? bias[co + 8] : 0.f;
        float* op0 = out + ((size_t)b * Cout + co) * 4096 + pbase;
        float* op8 = op0 + (size_t)8 * 4096;
#pragma unroll
        for (int fn = 0; fn < 4; fn++) {
            int p = wn * 32 + fn * 8 + c0;
            float a0 = acc[fm][fn][0] + bv0, a1 = acc[fm][fn][1] + bv0;
            float a2 = acc[fm][fn][2] + bv8, a3 = acc[fm][fn][3] + bv8;
            if (ACT == 1) { a0 = geluf(a0); a1 = geluf(a1); a2 = geluf(a2); a3 = geluf(a3); }
            if (v0ok) *(float2*)(op0 + p) = make_float2(a0, a1);
            if (v8ok) *(float2*)(op8 + p) = make_float2(a2, a3);
        }
    }
}

// ---- FFMA 3x3 conv (edge net: Cin=4 -> 64 only) ----
#define CI_CHUNK 8
template<int ACT>
__global__ __launch_bounds__(128) void conv3x3_k(
    const float* __restrict__ in1, int Cin,
    const float* __restrict__ wgt, const float* __restrict__ bias,
    float* __restrict__ out, int Cout)
{
    const int bh = blockIdx.x, b = bh >> 6, h = bh & 63;
    const int co0 = blockIdx.y * 64;
    const int t = threadIdx.x, tx = t & 7, ty = t >> 3;
    __shared__ float sIn[CI_CHUNK][3][66];
    __shared__ float sW[64][CI_CHUNK * 9];
    float acc[4][8];
#pragma unroll
    for (int a = 0; a < 4; a++)
#pragma unroll
        for (int j = 0; j < 8; j++) acc[a][j] = 0.f;

    for (int cb = 0; cb < Cin; cb += CI_CHUNK) {
        __syncthreads();
        for (int idx = t; idx < CI_CHUNK * 3 * 66; idx += 128) {
            int ci = idx / 198, rem = idx - ci * 198, r = rem / 66, col = rem - r * 66;
            int cg = cb + ci;
            float v = 0.f;
            int gh = h - 1 + r, gw = col - 1;
            if (cg < Cin && (unsigned)gh < 64u && (unsigned)gw < 64u)
                v = in1[((size_t)(b * Cin + cg)) * PP + gh * 64 + gw];
            sIn[ci][r][col] = v;
        }
        for (int idx = t; idx < 64 * CI_CHUNK * 9; idx += 128) {
            int co = idx / (CI_CHUNK * 9), rem = idx - co * (CI_CHUNK * 9);
            int ci = rem / 9, kk = rem - ci * 9, cg = cb + ci;
            sW[co][ci * 9 + kk] = (cg < Cin) ? wgt[((size_t)(co0 + co) * Cin + cg) * 9 + kk] : 0.f;
        }
        __syncthreads();
#pragma unroll 2
        for (int ci = 0; ci < CI_CHUNK; ci++) {
#pragma unroll
            for (int r = 0; r < 3; r++) {
                float iv[10];
#pragma unroll
                for (int j = 0; j < 10; j++) iv[j] = sIn[ci][r][tx * 8 + j];
#pragma unroll
                for (int cj = 0; cj < 4; cj++) {
                    float w0 = sW[ty * 4 + cj][ci * 9 + r * 3 + 0];
                    float w1 = sW[ty * 4 + cj][ci * 9 + r * 3 + 1];
                    float w2 = sW[ty * 4 + cj][ci * 9 + r * 3 + 2];
#pragma unroll
                    for (int wj = 0; wj < 8; wj++) {
                        acc[cj][wj] = fmaf(w0, iv[wj + 0], acc[cj][wj]);
                        acc[cj][wj] = fmaf(w1, iv[wj + 1], acc[cj][wj]);
                        acc[cj][wj] = fmaf(w2, iv[wj + 2], acc[cj][wj]);
                    }
                }
            }
        }
    }
#pragma unroll
    for (int cj = 0; cj < 4; cj++) {
        int co = co0 + ty * 4 + cj;
        float bv = bias[co];
#pragma unroll
        for (int wj = 0; wj < 8; wj++) {
            float v = acc[cj][wj] + bv;
            if (ACT == 1) v = geluf(v);
            out[(((size_t)b * Cout + co) * 64 + h) * 64 + tx * 8 + wj] = v;
        }
    }
}

template<int ACT>
__global__ void conv1x1_small_k(const float* __restrict__ in, const float* __restrict__ wgt,
                                const float* __restrict__ bias, float* __restrict__ out,
                                int Cin, int Cout)
{
    int bc = blockIdx.x, b = bc / Cout, co = bc - b * Cout;
    int p = blockIdx.y * 256 + threadIdx.x;
    float acc = bias[co];
    const float* ip = in + (size_t)b * Cin * PP + p;
    const float* wp = wgt + (size_t)co * Cin;
    for (int ci = 0; ci < Cin; ci++)
        acc = fmaf(wp[ci], ip[(size_t)ci * PP], acc);
    if (ACT == 2) acc = sigm(acc);
    out[((size_t)b * Cout + co) * PP + p] = acc;
}

// ---- GroupNorm ----
__global__ void gn_stats_k(const float* __restrict__ x, float* __restrict__ stats)
{
    int bg = blockIdx.x, b = bg >> 3, g = bg & 7;
    const float* p = x + ((size_t)b * 64 + g * 8) * PP;
    float s = 0.f, s2 = 0.f;
    for (int i = threadIdx.x; i < 8 * PP; i += 256) {
        float v = p[i]; s += v; s2 += v * v;
    }
    __shared__ float rs[8], rs2[8];
#pragma unroll
    for (int o = 16; o > 0; o >>= 1) {
        s += __shfl_down_sync(0xffffffffu, s, o);
        s2 += __shfl_down_sync(0xffffffffu, s2, o);
    }
    int w = threadIdx.x >> 5, l = threadIdx.x & 31;
    if (l == 0) { rs[w] = s; rs2[w] = s2; }
    __syncthreads();
    if (w == 0) {
        s = (l < 8) ? rs[l] : 0.f; s2 = (l < 8) ? rs2[l] : 0.f;
#pragma unroll
        for (int o = 4; o > 0; o >>= 1) {
            s += __shfl_down_sync(0xffffffffu, s, o);
            s2 += __shfl_down_sync(0xffffffffu, s2, o);
        }
        if (l == 0) {
            float m = s / 32768.f;
            stats[bg * 2] = m;
            stats[bg * 2 + 1] = s2 / 32768.f - m * m;
        }
    }
}

__global__ void gn_apply_k(float* __restrict__ x, const float* __restrict__ stats,
                           const float* __restrict__ gamma, const float* __restrict__ beta)
{
    size_t idx = (size_t)blockIdx.x * 256 + threadIdx.x;
    int c = (int)((idx >> 12) & 63);
    int b = (int)(idx >> 18);
    int bg = b * 8 + (c >> 3);
    float m = stats[bg * 2], v = stats[bg * 2 + 1];
    float xn = (x[idx] - m) * rsqrtf(v + 1e-5f) * gamma[c] + beta[c];
    x[idx] = geluf(xn);
}

// ---- attention ----
__global__ __launch_bounds__(128) void attn_logits_k(
    const float* __restrict__ qkv, const float* __restrict__ edge, float* __restrict__ attn)
{
    int id = blockIdx.x;
    int i = id & 63, h = (id >> 6) & 7, b = id >> 9;
    const float* Q = qkv + ((size_t)(b * 1536 + h * 64 + i)) * PP;
    const float* K = qkv + ((size_t)(b * 1536 + 512 + h * 64 + i)) * PP;
    __shared__ float sQ[64][65], sK[64][65];
    int t = threadIdx.x;
    for (int idx = t; idx < 4096; idx += 128) {
        int r = idx >> 6, c = idx & 63;
        sQ[r][c] = Q[idx]; sK[r][c] = K[idx];
    }
    __syncthreads();
    int tx = t & 15, ty = t >> 4;
    float acc[8][4];
#pragma unroll
    for (int j = 0; j < 8; j++)
#pragma unroll
        for (int c = 0; c < 4; c++) acc[j][c] = 0.f;
#pragma unroll 8
    for (int y = 0; y < 64; y++) {
        float qv[8], kv[4];
#pragma unroll
        for (int j = 0; j < 8; j++) qv[j] = sQ[y][ty * 8 + j];
#pragma unroll
        for (int c = 0; c < 4; c++) kv[c] = sK[y][tx * 4 + c];
#pragma unroll
        for (int j = 0; j < 8; j++)
#pragma unroll
            for (int c = 0; c < 4; c++)
                acc[j][c] = fmaf(qv[j], kv[c], acc[j][c]);
    }
    float* op = attn + (size_t)id * 4096;
    const float* ep = edge + (size_t)id * 64;
#pragma unroll
    for (int j = 0; j < 8; j++) {
        int w = ty * 8 + j;
        float e = ep[w];
#pragma unroll
        for (int c = 0; c < 4; c++)
            op[w * 64 + tx * 4 + c] = acc[j][c] * 0.125f + e;
    }
}

__global__ __launch_bounds__(128) void softmax_i_k(float* __restrict__ attn)
{
    int n = blockIdx.x * 128 + threadIdx.x;
    int bh = n >> 12, ww = n & 4095;
    float* p = attn + (size_t)bh * 262144 + ww;
    float x[64], mx = -1e30f;
#pragma unroll
    for (int i = 0; i < 64; i++) { x[i] = p[(size_t)i * 4096]; mx = fmaxf(mx, x[i]); }
    float s = 0.f;
#pragma unroll
    for (int i = 0; i < 64; i++) { x[i] = __expf(x[i] - mx); s += x[i]; }
    float inv = 1.f / s;
#pragma unroll
    for (int i = 0; i < 64; i++) p[(size_t)i * 4096] = x[i] * inv;
}

__global__ __launch_bounds__(128) void attn_av_k(
    const float* __restrict__ qkv, const float* __restrict__ attn, float* __restrict__ agg)
{
    int id = blockIdx.x;
    int i = id & 63, h = (id >> 6) & 7, b = id >> 9;
    const float* V = qkv + ((size_t)(b * 1536 + 1024 + h * 64 + i)) * PP;
    const float* A = attn + (size_t)id * 4096;
    __shared__ float sV[64][65], sA[64][65];
    int t = threadIdx.x;
    for (int idx = t; idx < 4096; idx += 128) {
        int r = idx >> 6, c = idx & 63;
        sV[r][c] = V[idx]; sA[r][c] = A[idx];
    }
    __syncthreads();
    int tx = t & 15, ty = t >> 4;
    float acc[8][4];
#pragma unroll
    for (int j = 0; j < 8; j++)
#pragma unroll
        for (int c = 0; c < 4; c++) acc[j][c] = 0.f;
#pragma unroll 8
    for (int kk = 0; kk < 64; kk++) {
        float vv[8], av[4];
#pragma unroll
        for (int j = 0; j < 8; j++) vv[j] = sV[ty * 8 + j][kk];
#pragma unroll
        for (int c = 0; c < 4; c++) av[c] = sA[tx * 4 + c][kk];
#pragma unroll
        for (int j = 0; j < 8; j++)
#pragma unroll
            for (int c = 0; c < 4; c++)
                acc[j][c] = fmaf(vv[j], av[c], acc[j][c]);
    }
    float* op = agg + ((size_t)(b * 512 + h * 64 + i)) * PP;
#pragma unroll
    for (int j = 0; j < 8; j++)
#pragma unroll
        for (int c = 0; c < 4; c++)
            op[(ty * 8 + j) * 64 + tx * 4 + c] = acc[j][c];
}

// ---- BatchNorm ----
__global__ void bn_stats_k(const float* __restrict__ y, float* __restrict__ stats)
{
    int c = blockIdx.x;
    float s = 0.f, s2 = 0.f;
    for (int n = threadIdx.x; n < 32768; n += 256) {
        int b = n >> 12, p = n & 4095;
        float v = y[((size_t)b * CC + c) * PP + p];
        s += v; s2 += v * v;
    }
    __shared__ float rs[8], rs2[8];
#pragma unroll
    for (int o = 16; o > 0; o >>= 1) {
        s += __shfl_down_sync(0xffffffffu, s, o);
        s2 += __shfl_down_sync(0xffffffffu, s2, o);
    }
    int w = threadIdx.x >> 5, l = threadIdx.x & 31;
    if (l == 0) { rs[w] = s; rs2[w] = s2; }
    __syncthreads();
    if (w == 0) {
        s = (l < 8) ? rs[l] : 0.f; s2 = (l < 8) ? rs2[l] : 0.f;
#pragma unroll
        for (int o = 4; o > 0; o >>= 1) {
            s += __shfl_down_sync(0xffffffffu, s, o);
            s2 += __shfl_down_sync(0xffffffffu, s2, o);
        }
        if (l == 0) {
            float m = s / 32768.f;
            stats[c * 2] = m;
            stats[c * 2 + 1] = s2 / 32768.f - m * m;
        }
    }
}

__global__ void bn_apply_k(const float* __restrict__ y, const float* __restrict__ stats,
                           const float* __restrict__ g, const float* __restrict__ bt,
                           float* __restrict__ out)
{
    size_t idx = (size_t)blockIdx.x * 256 + threadIdx.x;
    int c = (int)((idx >> 12) & 511);
    float m = stats[c * 2], v = stats[c * 2 + 1];
    float yn = (y[idx] - m) * rsqrtf(v + 1e-5f) * g[c] + bt[c];
    out[idx] = yn * (1.f / (1.f + __expf(-yn)));
}

// ---- launch ----
extern "C" void kernel_launch(void* const* d_in, const int* in_sizes, int n_in,
                              void* d_out, int out_size)
{
    const float* x       = (const float*)d_in[0];
    const float* box_w1  = (const float*)d_in[1];
    const float* box_b1  = (const float*)d_in[2];
    const float* box_w2  = (const float*)d_in[3];
    const float* box_b2  = (const float*)d_in[4];
    const float* edge_w1 = (const float*)d_in[5];
    const float* edge_b1 = (const float*)d_in[6];
    const float* gn_g    = (const float*)d_in[7];
    const float* gn_b    = (const float*)d_in[8];
    const float* edge_w2 = (const float*)d_in[9];
    const float* edge_b2 = (const float*)d_in[10];
    const float* qkv_w   = (const float*)d_in[11];
    const float* qkv_b   = (const float*)d_in[12];
    const float* fus_w   = (const float*)d_in[13];
    const float* fus_b   = (const float*)d_in[14];
    const float* bn_g    = (const float*)d_in[15];
    const float* bn_b    = (const float*)d_in[16];
    float* out = (float*)d_out;

    float *box1, *boxes, *edge1, *edge, *qkv, *attn, *agg, *y, *gnst, *bnst;
    __nv_bfloat16 *xhi, *xlo, *wfhi, *wflo, *wbhi, *wblo, *wqhi, *wqlo;
    cudaGetSymbolAddress((void**)&box1,  g_box1);
    cudaGetSymbolAddress((void**)&boxes, g_boxes);
    cudaGetSymbolAddress((void**)&edge1, g_edge1);
    cudaGetSymbolAddress((void**)&edge,  g_edge);
    cudaGetSymbolAddress((void**)&qkv,   g_qkv);
    cudaGetSymbolAddress((void**)&attn,  g_attn);
    cudaGetSymbolAddress((void**)&agg,   g_agg);
    cudaGetSymbolAddress((void**)&y,     g_y);
    cudaGetSymbolAddress((void**)&gnst,  g_gnstats);
    cudaGetSymbolAddress((void**)&bnst,  g_bnstats);
    cudaGetSymbolAddress((void**)&xhi,   g_xhi);
    cudaGetSymbolAddress((void**)&xlo,   g_xlo);
    cudaGetSymbolAddress((void**)&wfhi,  g_wfhi);
    cudaGetSymbolAddress((void**)&wflo,  g_wflo);
    cudaGetSymbolAddress((void**)&wbhi,  g_wbhi);
    cudaGetSymbolAddress((void**)&wblo,  g_wblo);
    cudaGetSymbolAddress((void**)&wqhi,  g_wqhi);
    cudaGetSymbolAddress((void**)&wqlo,  g_wqlo);

    cudaFuncSetAttribute((const void*)mma_mm<1, 0, 128>, cudaFuncAttributeMaxDynamicSharedMemorySize, 2 * MSTAGE);
    cudaFuncSetAttribute((const void*)mma_mm<9, 0, 128>, cudaFuncAttributeMaxDynamicSharedMemorySize, 2 * MSTAGE);
    cudaFuncSetAttribute((const void*)mma_mm<9, 1, 64>,  cudaFuncAttributeMaxDynamicSharedMemorySize, 2 * MSTAGE);

    // preprocessing: bf16 hi/lo splits
    split_k<<<dim3(16, 128, 8), dim3(32, 8)>>>(x, xhi, xlo, 512, 0);
    wsplit_k<<<(512 * 1024 * 9 + 255) / 256, 256>>>(fus_w, wfhi, wflo, 1024, 9, (size_t)512 * 1024 * 9);
    wsplit_k<<<(64 * 512 * 9 + 255) / 256, 256>>>(box_w1, wbhi, wblo, 512, 9, (size_t)64 * 512 * 9);
    wsplit_k<<<(1536 * 512 + 255) / 256, 256>>>(qkv_w, wqhi, wqlo, 512, 1, (size_t)1536 * 512);

    // box net: conv3x3(512->64)+GELU on tensor cores ; conv1x1(64->4)+sigmoid
    mma_mm<9, 1, 64><<<dim3(256, 1), 256, 2 * MSTAGE>>>(wbhi, wblo, xhi, xlo, box_b1, box1, 512, 64);
    conv1x1_small_k<2><<<dim3(32, 16), 256>>>(box1, box_w2, box_b2, boxes, 64, 4);

    // edge net: conv3x3(4->64) ; GN ; GELU ; conv1x1(64->8)
    conv3x3_k<0><<<dim3(512, 1), 128>>>(boxes, 4, edge_w1, edge_b1, edge1, 64);
    gn_stats_k<<<64, 256>>>(edge1, gnst);
    gn_apply_k<<<8192, 256>>>(edge1, gnst, gn_g, gn_b);
    conv1x1_small_k<0><<<dim3(64, 16), 256>>>(edge1, edge_w2, edge_b2, edge, 64, 8);

    // qkv 1x1 (512->1536) on tensor cores
    mma_mm<1, 0, 128><<<dim3(256, 12), 256, 2 * MSTAGE>>>(wqhi, wqlo, xhi, xlo, qkv_b, qkv, 512, 1536);

    // attention
    attn_logits_k<<<4096, 128>>>(qkv, edge, attn);
    softmax_i_k<<<2048, 128>>>(attn);
    attn_av_k<<<4096, 128>>>(qkv, attn, agg);

    // split agg into ci[512:1024) of the bf16 buffer
    split_k<<<dim3(16, 128, 8), dim3(32, 8)>>>(agg, xhi, xlo, 512, 512);

    // fusion conv3x3 (1024->512) on tensor cores
    mma_mm<9, 0, 128><<<dim3(256, 4), 256, 2 * MSTAGE>>>(wfhi, wflo, xhi, xlo, fus_b, y, 1024, 512);

    // batchnorm + SiLU
    bn_stats_k<<<512, 256>>>(y, bnst);
    bn_apply_k<<<65536, 256>>>(y, bnst, bn_g, bn_b, out);
}

// round 8
// speedup vs baseline: 3.7655x; 1.0488x over previous
#include <cuda_runtime.h>
#include <cuda_bf16.h>
#include <cstdint>
#include <math.h>

#define BB 8
#define CC 512
#define PP 4096
#define NHH 8

// ---- scratch (static device globals; no allocation) ----
__device__ float g_box1[BB*64*PP];
__device__ float g_boxes[BB*4*PP];
__device__ float g_edge1[BB*64*PP];
__device__ float g_edge[BB*NHH*PP];
__device__ float g_qkv[(size_t)BB*1536*PP];
__device__ float g_attn[(size_t)BB*NHH*64*64*64];
__device__ float g_agg[(size_t)BB*CC*PP];
__device__ float g_y[(size_t)BB*CC*PP];
__device__ float g_gnstats[BB*8*2];
__device__ float g_bnstats[CC*2];
__device__ __nv_bfloat16 g_xhi[(size_t)BB*PP*1024];   // [b][p][ci]
__device__ __nv_bfloat16 g_xlo[(size_t)BB*PP*1024];
__device__ __nv_bfloat16 g_wfhi[512*9*1024];          // [co][tap][ci]
__device__ __nv_bfloat16 g_wflo[512*9*1024];
__device__ __nv_bfloat16 g_wbhi[64*9*512];
__device__ __nv_bfloat16 g_wblo[64*9*512];
__device__ __nv_bfloat16 g_wqhi[1536*512];
__device__ __nv_bfloat16 g_wqlo[1536*512];

__device__ __forceinline__ float geluf(float x) {
    return 0.5f * x * (1.0f + erff(x * 0.70710678118654752440f));
}
__device__ __forceinline__ float sigm(float x) { return 1.0f / (1.0f + __expf(-x)); }

// ---- arch-neutral tensor-core helpers (sm_80+ PTX only) ----
__device__ __forceinline__ uint32_t smem_u32(const void* p) {
    uint32_t a;
    asm("{ .reg .u64 t; cvta.to.shared.u64 t, %1; cvt.u32.u64 %0, t; }" : "=r"(a) : "l"(p));
    return a;
}
__device__ __forceinline__ void ldsm_x4(uint32_t* r, uint32_t addr) {
    asm volatile("ldmatrix.sync.aligned.m8n8.x4.shared.b16 {%0,%1,%2,%3}, [%4];"
        : "=r"(r[0]), "=r"(r[1]), "=r"(r[2]), "=r"(r[3]) : "r"(addr));
}
__device__ __forceinline__ void mma16816(float* d, const uint32_t* a, const uint32_t* b) {
    asm volatile("mma.sync.aligned.m16n8k16.row.col.f32.bf16.bf16.f32 "
        "{%0,%1,%2,%3}, {%4,%5,%6,%7}, {%8,%9}, {%0,%1,%2,%3};"
        : "+f"(d[0]), "+f"(d[1]), "+f"(d[2]), "+f"(d[3])
        : "r"(a[0]), "r"(a[1]), "r"(a[2]), "r"(a[3]), "r"(b[0]), "r"(b[1]));
}
__device__ __forceinline__ void cpa16(uint32_t dst, const void* src, uint32_t sz) {
    asm volatile("cp.async.cg.shared.global [%0], [%1], 16, %2;\n" :: "r"(dst), "l"(src), "r"(sz));
}
#define CP_COMMIT() asm volatile("cp.async.commit_group;\n" ::: "memory")
#define CP_WAIT1()  asm volatile("cp.async.wait_group 1;\n" ::: "memory")
#define CP_WAIT0()  asm volatile("cp.async.wait_group 0;\n" ::: "memory")

// ---- split / transpose: NCHW fp32 -> [b][p][ci] bf16 hi/lo ----
__global__ void split_k(const float* __restrict__ src, __nv_bfloat16* __restrict__ xhi,
                        __nv_bfloat16* __restrict__ xlo, int Cn, int cibase)
{
    __shared__ float tile[32][33];
    int bz = blockIdx.z, c0 = blockIdx.x * 32, p0 = blockIdx.y * 32;
    int tx = threadIdx.x, ty = threadIdx.y;
#pragma unroll
    for (int i = 0; i < 32; i += 8)
        tile[ty + i][tx] = src[((size_t)bz * Cn + c0 + ty + i) * 4096 + p0 + tx];
    __syncthreads();
#pragma unroll
    for (int i = 0; i < 32; i += 8) {
        float v = tile[tx][ty + i];
        __nv_bfloat16 h = __float2bfloat16(v);
        size_t o = ((size_t)bz * 4096 + p0 + ty + i) * 1024 + cibase + c0 + tx;
        xhi[o] = h;
        xlo[o] = __float2bfloat16(v - __bfloat162float(h));
    }
}

// OIHW fp32 -> [co][tap][ci] bf16 hi/lo
__global__ void wsplit_k(const float* __restrict__ w, __nv_bfloat16* __restrict__ whi,
                         __nv_bfloat16* __restrict__ wlo, int Cin, int taps, size_t total)
{
    size_t i = (size_t)blockIdx.x * 256 + threadIdx.x;
    if (i >= total) return;
    int tap = (int)(i % taps);
    size_t t2 = i / taps;
    int ci = (int)(t2 % Cin);
    int co = (int)(t2 / Cin);
    float v = w[i];
    __nv_bfloat16 h = __float2bfloat16(v);
    size_t dst = ((size_t)co * taps + tap) * Cin + ci;
    whi[dst] = h;
    wlo[dst] = __float2bfloat16(v - __bfloat162float(h));
}

// ---- mma.sync implicit GEMM: ROWSA(co) x ROWSB(px) CTA tile ----
// smem stage: Ahi[ROWSA][72] Alo Bhi[ROWSB][72] Blo (rows padded to 144B)
template<int TAPS, int COUTV, int ROWSA, int ROWSB>
__device__ __forceinline__ void mm_load(uint32_t sb, int t,
    const __nv_bfloat16* __restrict__ whi, const __nv_bfloat16* __restrict__ wlo,
    const __nv_bfloat16* __restrict__ xhi, const __nv_bfloat16* __restrict__ xlo,
    int co0, int WCin, int b, int pbase, int c)
{
    const int A_LO_ = ROWSA * 144;
    const int B_HI_ = 2 * ROWSA * 144;
    const int B_LO_D = ROWSB * 144;
    int cik = c / TAPS, tap = c - cik * TAPS;
    int dh = (TAPS == 9) ? tap / 3 - 1 : 0;
    int dw = (TAPS == 9) ? tap % 3 - 1 : 0;
    int ci0 = cik * 64;
#pragma unroll
    for (int i = 0; i < ROWSA / 16; i++) {     // A: 2(hl) x ROWSA rows x 8 segs
        int idx = t + i * 256;
        int hl = idx / (ROWSA * 8), rem = idx % (ROWSA * 8), row = rem >> 3, seg = rem & 7;
        int rr = (COUTV < ROWSA && row >= COUTV) ? 0 : row;
        const __nv_bfloat16* src = (hl ? wlo : whi)
            + ((size_t)(co0 + rr) * TAPS + tap) * WCin + ci0 + seg * 8;
        cpa16(sb + hl * A_LO_ + row * 144 + seg * 16, src,
              (COUTV < ROWSA && row >= COUTV) ? 0u : 16u);
    }
#pragma unroll
    for (int i = 0; i < ROWSB / 16; i++) {     // B: 2(hl) x ROWSB px rows x 8 segs
        int idx = t + i * 256;
        int hl = idx / (ROWSB * 8), rem = idx % (ROWSB * 8), row = rem >> 3, seg = rem & 7;
        int p = pbase + row;
        int ih = (p >> 6) + dh, iw = (p & 63) + dw;
        bool ok = (TAPS == 1) || (((unsigned)ih < 64u) && ((unsigned)iw < 64u));
        const __nv_bfloat16* src = (hl ? xlo : xhi)
            + ((size_t)(b * 4096 + (ok ? ih * 64 + iw : 0))) * 1024 + ci0 + seg * 8;
        cpa16(sb + B_HI_ + hl * B_LO_D + row * 144 + seg * 16, src, ok ? 16u : 0u);
    }
}

template<int TAPS, int ACT, int COUTV, int ROWSA, int ROWSB>
__global__ __launch_bounds__(256) void mma_mm(
    const __nv_bfloat16* __restrict__ whi, const __nv_bfloat16* __restrict__ wlo,
    const __nv_bfloat16* __restrict__ xhi, const __nv_bfloat16* __restrict__ xlo,
    const float* __restrict__ bias, float* __restrict__ out, int WCin, int Cout)
{
    extern __shared__ char dynsmem[];
    const int A_LO_ = ROWSA * 144;
    const int B_HI_ = 2 * ROWSA * 144;
    const int B_LO_D = ROWSB * 144;
    const int MSTAGE_ = 2 * (ROWSA + ROWSB) * 144;
    const int NPT = 4096 / ROWSB;
    const int b = blockIdx.x / NPT;
    const int pbase = (blockIdx.x % NPT) * ROWSB;
    const int co0 = blockIdx.y * ROWSA;
    const int t = threadIdx.x, lane = t & 31, warp = t >> 5;
    const int wm = (ROWSA == 128) ? (warp & 1) : 0;
    const int wn = (ROWSA == 128) ? (warp >> 1) : warp;
    const uint32_t sb0 = smem_u32(dynsmem);
    const int NCH = (WCin / 64) * TAPS;

    float acc[4][4][4];
#pragma unroll
    for (int fm = 0; fm < 4; fm++)
#pragma unroll
        for (int fn = 0; fn < 4; fn++)
#pragma unroll
            for (int k = 0; k < 4; k++) acc[fm][fn][k] = 0.f;

    mm_load<TAPS, COUTV, ROWSA, ROWSB>(sb0, t, whi, wlo, xhi, xlo, co0, WCin, b, pbase, 0); CP_COMMIT();
    mm_load<TAPS, COUTV, ROWSA, ROWSB>(sb0 + MSTAGE_, t, whi, wlo, xhi, xlo, co0, WCin, b, pbase, 1); CP_COMMIT();

    const int arow = wm * 64 + (lane & 15);
    const int akoff = (lane >> 4) * 16;
    const int l8 = lane & 7, grp = lane >> 3;
    const int brow = wn * 32 + l8 + (grp >> 1) * 8;
    const int bkoff = (grp & 1) * 16;

    for (int c = 0; c < NCH; c++) {
        const uint32_t sb = sb0 + (c & 1) * MSTAGE_;
        if (c == NCH - 1) { CP_WAIT0(); } else { CP_WAIT1(); }
        __syncthreads();
        const uint32_t abase = sb + arow * 144 + akoff;
        const uint32_t bbase = sb + B_HI_ + brow * 144 + bkoff;
#pragma unroll
        for (int ks = 0; ks < 4; ks++) {
            const int kb = ks * 32;
            uint32_t ah[4][4], al[4][4];
#pragma unroll
            for (int fm = 0; fm < 4; fm++) {
                ldsm_x4(ah[fm], abase + fm * 16 * 144 + kb);
                ldsm_x4(al[fm], abase + A_LO_ + fm * 16 * 144 + kb);
            }
            uint32_t bh[4][2], bl[4][2];
#pragma unroll
            for (int fp = 0; fp < 2; fp++) {
                uint32_t r[4];
                uint32_t addr = bbase + fp * 16 * 144 + kb;
                ldsm_x4(r, addr);
                bh[fp*2][0] = r[0]; bh[fp*2][1] = r[1];
                bh[fp*2+1][0] = r[2]; bh[fp*2+1][1] = r[3];
                ldsm_x4(r, addr + B_LO_D);
                bl[fp*2][0] = r[0]; bl[fp*2][1] = r[1];
                bl[fp*2+1][0] = r[2]; bl[fp*2+1][1] = r[3];
            }
#pragma unroll
            for (int fm = 0; fm < 4; fm++)
#pragma unroll
                for (int fn = 0; fn < 4; fn++) {
                    mma16816(acc[fm][fn], ah[fm], bh[fn]);
                    mma16816(acc[fm][fn], ah[fm], bl[fn]);
                    mma16816(acc[fm][fn], al[fm], bh[fn]);
                }
        }
        __syncthreads();
        if (c + 2 < NCH) {
            mm_load<TAPS, COUTV, ROWSA, ROWSB>(sb, t, whi, wlo, xhi, xlo, co0, WCin, b, pbase, c + 2);
            CP_COMMIT();
        }
    }

    // epilogue
    const int r0 = lane >> 2, c0 = (lane & 3) * 2;
#pragma unroll
    for (int fm = 0; fm < 4; fm++) {
        int co = co0 + wm * 64 + fm * 16 + r0;
        bool v0ok = (COUTV >= ROWSA) || (co < COUTV);
        bool v8ok = (COUTV >= ROWSA) || (co + 8 < COUTV);
        float bv0 = v0ok ? bias[co] : 0.f;
        float bv8 = v8ok ? bias[co + 8] : 0.f;
        float* op0 = out + ((size_t)b * Cout + co) * 4096 + pbase;
        float* op8 = op0 + (size_t)8 * 4096;
#pragma unroll
        for (int fn = 0; fn < 4; fn++) {
            int p = wn * 32 + fn * 8 + c0;
            float a0 = acc[fm][fn][0] + bv0, a1 = acc[fm][fn][1] + bv0;
            float a2 = acc[fm][fn][2] + bv8, a3 = acc[fm][fn][3] + bv8;
            if (ACT == 1) { a0 = geluf(a0); a1 = geluf(a1); a2 = geluf(a2); a3 = geluf(a3); }
            if (v0ok) *(float2*)(op0 + p) = make_float2(a0, a1);
            if (v8ok) *(float2*)(op8 + p) = make_float2(a2, a3);
        }
    }
}

// ---- attention QK logits via mma: per (b,h,i): L[w][W'] = sum_y Q[y][w] K[y][W'] ----
__global__ __launch_bounds__(128) void attn_qk_mma(
    const float* __restrict__ qkv, const float* __restrict__ edge, float* __restrict__ attn)
{
    int id = blockIdx.x;
    int i = id & 63, h = (id >> 6) & 7, b = id >> 9;
    const float* Q = qkv + ((size_t)(b * 1536 + h * 64 + i)) * PP;
    const float* K = qkv + ((size_t)(b * 1536 + 512 + h * 64 + i)) * PP;
    __shared__ __nv_bfloat16 sQh[64*72], sQl[64*72], sKh[64*72], sKl[64*72];
    int t = threadIdx.x, lane = t & 31, warp = t >> 5;
    int wm = warp & 1, wn = warp >> 1;
    // convert + transpose: smem [w][y] / [W'][y]
    for (int idx = t; idx < 4096; idx += 128) {
        int y = idx >> 6, c = idx & 63;
        float q = Q[idx];
        __nv_bfloat16 qh = __float2bfloat16(q);
        sQh[c*72 + y] = qh; sQl[c*72 + y] = __float2bfloat16(q - __bfloat162float(qh));
        float k = K[idx];
        __nv_bfloat16 kh = __float2bfloat16(k);
        sKh[c*72 + y] = kh; sKl[c*72 + y] = __float2bfloat16(k - __bfloat162float(kh));
    }
    __syncthreads();
    float acc[2][4][4];
#pragma unroll
    for (int fm = 0; fm < 2; fm++)
#pragma unroll
        for (int fn = 0; fn < 4; fn++)
#pragma unroll
            for (int k = 0; k < 4; k++) acc[fm][fn][k] = 0.f;

    const uint32_t aQh = smem_u32(sQh), aQl = smem_u32(sQl);
    const uint32_t aKh = smem_u32(sKh), aKl = smem_u32(sKl);
    const int arow = wm * 32 + (lane & 15), akoff = (lane >> 4) * 16;
    const int l8 = lane & 7, grp = lane >> 3;
    const int brow = wn * 32 + l8 + (grp >> 1) * 8, bkoff = (grp & 1) * 16;
#pragma unroll
    for (int ks = 0; ks < 4; ks++) {
        const int kb = ks * 32;
        uint32_t ah[2][4], al[2][4];
#pragma unroll
        for (int fm = 0; fm < 2; fm++) {
            ldsm_x4(ah[fm], aQh + (arow + fm*16) * 144 + akoff + kb);
            ldsm_x4(al[fm], aQl + (arow + fm*16) * 144 + akoff + kb);
        }
        uint32_t bh[4][2], bl[4][2];
#pragma unroll
        for (int fp = 0; fp < 2; fp++) {
            uint32_t r[4];
            ldsm_x4(r, aKh + (brow + fp*16) * 144 + bkoff + kb);
            bh[fp*2][0] = r[0]; bh[fp*2][1] = r[1];
            bh[fp*2+1][0] = r[2]; bh[fp*2+1][1] = r[3];
            ldsm_x4(r, aKl + (brow + fp*16) * 144 + bkoff + kb);
            bl[fp*2][0] = r[0]; bl[fp*2][1] = r[1];
            bl[fp*2+1][0] = r[2]; bl[fp*2+1][1] = r[3];
        }
#pragma unroll
        for (int fm = 0; fm < 2; fm++)
#pragma unroll
            for (int fn = 0; fn < 4; fn++) {
                mma16816(acc[fm][fn], ah[fm], bh[fn]);
                mma16816(acc[fm][fn], ah[fm], bl[fn]);
                mma16816(acc[fm][fn], al[fm], bh[fn]);
            }
    }
    const int r0 = lane >> 2, c0 = (lane & 3) * 2;
    float* op = attn + (size_t)id * 4096;
    const float* ep = edge + (size_t)id * 64;
#pragma unroll
    for (int fm = 0; fm < 2; fm++) {
        int w0 = wm * 32 + fm * 16 + r0;
        float e0 = ep[w0], e8 = ep[w0 + 8];
#pragma unroll
        for (int fn = 0; fn < 4; fn++) {
            int Wp = wn * 32 + fn * 8 + c0;
            op[w0*64 + Wp]       = acc[fm][fn][0] * 0.125f + e0;
            op[w0*64 + Wp + 1]   = acc[fm][fn][1] * 0.125f + e0;
            op[(w0+8)*64 + Wp]   = acc[fm][fn][2] * 0.125f + e8;
            op[(w0+8)*64 + Wp+1] = acc[fm][fn][3] * 0.125f + e8;
        }
    }
}

// ---- attention AV via mma: per (b,h,i): out[d][w] = sum_W' attn[w][W'] V[d][W'] ----
__global__ __launch_bounds__(128) void attn_av_mma(
    const float* __restrict__ qkv, const float* __restrict__ attn, float* __restrict__ agg)
{
    int id = blockIdx.x;
    int i = id & 63, h = (id >> 6) & 7, b = id >> 9;
    const float* V = qkv + ((size_t)(b * 1536 + 1024 + h * 64 + i)) * PP;  // [d][W']
    const float* A = attn + (size_t)id * 4096;                            // [w][W']
    __shared__ __nv_bfloat16 sVh[64*72], sVl[64*72], sAh[64*72], sAl[64*72];
    int t = threadIdx.x, lane = t & 31, warp = t >> 5;
    int wm = warp & 1, wn = warp >> 1;
    for (int idx = t; idx < 4096; idx += 128) {
        int r = idx >> 6, c = idx & 63;
        float v = V[idx];
        __nv_bfloat16 vh = __float2bfloat16(v);
        sVh[r*72 + c] = vh; sVl[r*72 + c] = __float2bfloat16(v - __bfloat162float(vh));
        float a = A[idx];
        __nv_bfloat16 ahv = __float2bfloat16(a);
        sAh[r*72 + c] = ahv; sAl[r*72 + c] = __float2bfloat16(a - __bfloat162float(ahv));
    }
    __syncthreads();
    float acc[2][4][4];
#pragma unroll
    for (int fm = 0; fm < 2; fm++)
#pragma unroll
        for (int fn = 0; fn < 4; fn++)
#pragma unroll
            for (int k = 0; k < 4; k++) acc[fm][fn][k] = 0.f;

    const uint32_t aVh = smem_u32(sVh), aVl = smem_u32(sVl);
    const uint32_t aAh = smem_u32(sAh), aAl = smem_u32(sAl);
    const int arow = wm * 32 + (lane & 15), akoff = (lane >> 4) * 16;
    const int l8 = lane & 7, grp = lane >> 3;
    const int brow = wn * 32 + l8 + (grp >> 1) * 8, bkoff = (grp & 1) * 16;
#pragma unroll
    for (int ks = 0; ks < 4; ks++) {
        const int kb = ks * 32;
        uint32_t ah[2][4], al[2][4];
#pragma unroll
        for (int fm = 0; fm < 2; fm++) {
            ldsm_x4(ah[fm], aVh + (arow + fm*16) * 144 + akoff + kb);
            ldsm_x4(al[fm], aVl + (arow + fm*16) * 144 + akoff + kb);
        }
        uint32_t bh[4][2], bl[4][2];
#pragma unroll
        for (int fp = 0; fp < 2; fp++) {
            uint32_t r[4];
            ldsm_x4(r, aAh + (brow + fp*16) * 144 + bkoff + kb);
            bh[fp*2][0] = r[0]; bh[fp*2][1] = r[1];
            bh[fp*2+1][0] = r[2]; bh[fp*2+1][1] = r[3];
            ldsm_x4(r, aAl + (brow + fp*16) * 144 + bkoff + kb);
            bl[fp*2][0] = r[0]; bl[fp*2][1] = r[1];
            bl[fp*2+1][0] = r[2]; bl[fp*2+1][1] = r[3];
        }
#pragma unroll
        for (int fm = 0; fm < 2; fm++)
#pragma unroll
            for (int fn = 0; fn < 4; fn++) {
                mma16816(acc[fm][fn], ah[fm], bh[fn]);
                mma16816(acc[fm][fn], ah[fm], bl[fn]);
                mma16816(acc[fm][fn], al[fm], bh[fn]);
            }
    }
    const int r0 = lane >> 2, c0 = (lane & 3) * 2;
    float* op = agg + ((size_t)(b * 512 + h * 64 + i)) * PP;
#pragma unroll
    for (int fm = 0; fm < 2; fm++) {
        int d0 = wm * 32 + fm * 16 + r0;
#pragma unroll
        for (int fn = 0; fn < 4; fn++) {
            int w = wn * 32 + fn * 8 + c0;
            op[d0*64 + w]       = acc[fm][fn][0];
            op[d0*64 + w + 1]   = acc[fm][fn][1];
            op[(d0+8)*64 + w]   = acc[fm][fn][2];
            op[(d0+8)*64 + w+1] = acc[fm][fn][3];
        }
    }
}

// ---- FFMA 3x3 conv (edge net: Cin=4 -> 64 only) ----
#define CI_CHUNK 8
template<int ACT>
__global__ __launch_bounds__(128) void conv3x3_k(
    const float* __restrict__ in1, int Cin,
    const float* __restrict__ wgt, const float* __restrict__ bias,
    float* __restrict__ out, int Cout)
{
    const int bh = blockIdx.x, b = bh >> 6, h = bh & 63;
    const int co0 = blockIdx.y * 64;
    const int t = threadIdx.x, tx = t & 7, ty = t >> 3;
    __shared__ float sIn[CI_CHUNK][3][66];
    __shared__ float sW[64][CI_CHUNK * 9];
    float acc[4][8];
#pragma unroll
    for (int a = 0; a < 4; a++)
#pragma unroll
        for (int j = 0; j < 8; j++) acc[a][j] = 0.f;

    for (int cb = 0; cb < Cin; cb += CI_CHUNK) {
        __syncthreads();
        for (int idx = t; idx < CI_CHUNK * 3 * 66; idx += 128) {
            int ci = idx / 198, rem = idx - ci * 198, r = rem / 66, col = rem - r * 66;
            int cg = cb + ci;
            float v = 0.f;
            int gh = h - 1 + r, gw = col - 1;
            if (cg < Cin && (unsigned)gh < 64u && (unsigned)gw < 64u)
                v = in1[((size_t)(b * Cin + cg)) * PP + gh * 64 + gw];
            sIn[ci][r][col] = v;
        }
        for (int idx = t; idx < 64 * CI_CHUNK * 9; idx += 128) {
            int co = idx / (CI_CHUNK * 9), rem = idx - co * (CI_CHUNK * 9);
            int ci = rem / 9, kk = rem - ci * 9, cg = cb + ci;
            sW[co][ci * 9 + kk] = (cg < Cin) ? wgt[((size_t)(co0 + co) * Cin + cg) * 9 + kk] : 0.f;
        }
        __syncthreads();
#pragma unroll 2
        for (int ci = 0; ci < CI_CHUNK; ci++) {
#pragma unroll
            for (int r = 0; r < 3; r++) {
                float iv[10];
#pragma unroll
                for (int j = 0; j < 10; j++) iv[j] = sIn[ci][r][tx * 8 + j];
#pragma unroll
                for (int cj = 0; cj < 4; cj++) {
                    float w0 = sW[ty * 4 + cj][ci * 9 + r * 3 + 0];
                    float w1 = sW[ty * 4 + cj][ci * 9 + r * 3 + 1];
                    float w2 = sW[ty * 4 + cj][ci * 9 + r * 3 + 2];
#pragma unroll
                    for (int wj = 0; wj < 8; wj++) {
                        acc[cj][wj] = fmaf(w0, iv[wj + 0], acc[cj][wj]);
                        acc[cj][wj] = fmaf(w1, iv[wj + 1], acc[cj][wj]);
                        acc[cj][wj] = fmaf(w2, iv[wj + 2], acc[cj][wj]);
                    }
                }
            }
        }
    }
#pragma unroll
    for (int cj = 0; cj < 4; cj++) {
        int co = co0 + ty * 4 + cj;
        float bv = bias[co];
#pragma unroll
        for (int wj = 0; wj < 8; wj++) {
            float v = acc[cj][wj] + bv;
            if (ACT == 1) v = geluf(v);
            out[(((size_t)b * Cout + co) * 64 + h) * 64 + tx * 8 + wj] = v;
        }
    }
}

template<int ACT>
__global__ void conv1x1_small_k(const float* __restrict__ in, const float* __restrict__ wgt,
                                const float* __restrict__ bias, float* __restrict__ out,
                                int Cin, int Cout)
{
    int bc = blockIdx.x, b = bc / Cout, co = bc - b * Cout;
    int p = blockIdx.y * 256 + threadIdx.x;
    float acc = bias[co];
    const float* ip = in + (size_t)b * Cin * PP + p;
    const float* wp = wgt + (size_t)co * Cin;
    for (int ci = 0; ci < Cin; ci++)
        acc = fmaf(wp[ci], ip[(size_t)ci * PP], acc);
    if (ACT == 2) acc = sigm(acc);
    out[((size_t)b * Cout + co) * PP + p] = acc;
}

// ---- GroupNorm ----
__global__ void gn_stats_k(const float* __restrict__ x, float* __restrict__ stats)
{
    int bg = blockIdx.x, b = bg >> 3, g = bg & 7;
    const float* p = x + ((size_t)b * 64 + g * 8) * PP;
    float s = 0.f, s2 = 0.f;
    for (int i = threadIdx.x; i < 8 * PP; i += 256) {
        float v = p[i]; s += v; s2 += v * v;
    }
    __shared__ float rs[8], rs2[8];
#pragma unroll
    for (int o = 16; o > 0; o >>= 1) {
        s += __shfl_down_sync(0xffffffffu, s, o);
        s2 += __shfl_down_sync(0xffffffffu, s2, o);
    }
    int w = threadIdx.x >> 5, l = threadIdx.x & 31;
    if (l == 0) { rs[w] = s; rs2[w] = s2; }
    __syncthreads();
    if (w == 0) {
        s = (l < 8) ? rs[l] : 0.f; s2 = (l < 8) ? rs2[l] : 0.f;
#pragma unroll
        for (int o = 4; o > 0; o >>= 1) {
            s += __shfl_down_sync(0xffffffffu, s, o);
            s2 += __shfl_down_sync(0xffffffffu, s2, o);
        }
        if (l == 0) {
            float m = s / 32768.f;
            stats[bg * 2] = m;
            stats[bg * 2 + 1] = s2 / 32768.f - m * m;
        }
    }
}

__global__ void gn_apply_k(float* __restrict__ x, const float* __restrict__ stats,
                           const float* __restrict__ gamma, const float* __restrict__ beta)
{
    size_t idx = (size_t)blockIdx.x * 256 + threadIdx.x;
    int c = (int)((idx >> 12) & 63);
    int b = (int)(idx >> 18);
    int bg = b * 8 + (c >> 3);
    float m = stats[bg * 2], v = stats[bg * 2 + 1];
    float xn = (x[idx] - m) * rsqrtf(v + 1e-5f) * gamma[c] + beta[c];
    x[idx] = geluf(xn);
}

// ---- softmax over i (stride 4096 within a (b,h) block) ----
__global__ __launch_bounds__(128) void softmax_i_k(float* __restrict__ attn)
{
    int n = blockIdx.x * 128 + threadIdx.x;
    int bh = n >> 12, ww = n & 4095;
    float* p = attn + (size_t)bh * 262144 + ww;
    float x[64], mx = -1e30f;
#pragma unroll
    for (int i = 0; i < 64; i++) { x[i] = p[(size_t)i * 4096]; mx = fmaxf(mx, x[i]); }
    float s = 0.f;
#pragma unroll
    for (int i = 0; i < 64; i++) { x[i] = __expf(x[i] - mx); s += x[i]; }
    float inv = 1.f / s;
#pragma unroll
    for (int i = 0; i < 64; i++) p[(size_t)i * 4096] = x[i] * inv;
}

// ---- BatchNorm ----
__global__ void bn_stats_k(const float* __restrict__ y, float* __restrict__ stats)
{
    int c = blockIdx.x;
    float s = 0.f, s2 = 0.f;
    for (int n = threadIdx.x; n < 32768; n += 256) {
        int b = n >> 12, p = n & 4095;
        float v = y[((size_t)b * CC + c) * PP + p];
        s += v; s2 += v * v;
    }
    __shared__ float rs[8], rs2[8];
#pragma unroll
    for (int o = 16; o > 0; o >>= 1) {
        s += __shfl_down_sync(0xffffffffu, s, o);
        s2 += __shfl_down_sync(0xffffffffu, s2, o);
    }
    int w = threadIdx.x >> 5, l = threadIdx.x & 31;
    if (l == 0) { rs[w] = s; rs2[w] = s2; }
    __syncthreads();
    if (w == 0) {
        s = (l < 8) ? rs[l] : 0.f; s2 = (l < 8) ? rs2[l] : 0.f;
#pragma unroll
        for (int o = 4; o > 0; o >>= 1) {
            s += __shfl_down_sync(0xffffffffu, s, o);
            s2 += __shfl_down_sync(0xffffffffu, s2, o);
        }
        if (l == 0) {
            float m = s / 32768.f;
            stats[c * 2] = m;
            stats[c * 2 + 1] = s2 / 32768.f - m * m;
        }
    }
}

__global__ void bn_apply_k(const float* __restrict__ y, const float* __restrict__ stats,
                           const float* __restrict__ g, const float* __restrict__ bt,
                           float* __restrict__ out)
{
    size_t idx = (size_t)blockIdx.x * 256 + threadIdx.x;
    int c = (int)((idx >> 12) & 511);
    float m = stats[c * 2], v = stats[c * 2 + 1];
    float yn = (y[idx] - m) * rsqrtf(v + 1e-5f) * g[c] + bt[c];
    out[idx] = yn * (1.f / (1.f + __expf(-yn)));
}

// ---- launch ----
extern "C" void kernel_launch(void* const* d_in, const int* in_sizes, int n_in,
                              void* d_out, int out_size)
{
    const float* x       = (const float*)d_in[0];
    const float* box_w1  = (const float*)d_in[1];
    const float* box_b1  = (const float*)d_in[2];
    const float* box_w2  = (const float*)d_in[3];
    const float* box_b2  = (const float*)d_in[4];
    const float* edge_w1 = (const float*)d_in[5];
    const float* edge_b1 = (const float*)d_in[6];
    const float* gn_g    = (const float*)d_in[7];
    const float* gn_b    = (const float*)d_in[8];
    const float* edge_w2 = (const float*)d_in[9];
    const float* edge_b2 = (const float*)d_in[10];
    const float* qkv_w   = (const float*)d_in[11];
    const float* qkv_b   = (const float*)d_in[12];
    const float* fus_w   = (const float*)d_in[13];
    const float* fus_b   = (const float*)d_in[14];
    const float* bn_g    = (const float*)d_in[15];
    const float* bn_b    = (const float*)d_in[16];
    float* out = (float*)d_out;

    float *box1, *boxes, *edge1, *edge, *qkv, *attn, *agg, *y, *gnst, *bnst;
    __nv_bfloat16 *xhi, *xlo, *wfhi, *wflo, *wbhi, *wblo, *wqhi, *wqlo;
    cudaGetSymbolAddress((void**)&box1,  g_box1);
    cudaGetSymbolAddress((void**)&boxes, g_boxes);
    cudaGetSymbolAddress((void**)&edge1, g_edge1);
    cudaGetSymbolAddress((void**)&edge,  g_edge);
    cudaGetSymbolAddress((void**)&qkv,   g_qkv);
    cudaGetSymbolAddress((void**)&attn,  g_attn);
    cudaGetSymbolAddress((void**)&agg,   g_agg);
    cudaGetSymbolAddress((void**)&y,     g_y);
    cudaGetSymbolAddress((void**)&gnst,  g_gnstats);
    cudaGetSymbolAddress((void**)&bnst,  g_bnstats);
    cudaGetSymbolAddress((void**)&xhi,   g_xhi);
    cudaGetSymbolAddress((void**)&xlo,   g_xlo);
    cudaGetSymbolAddress((void**)&wfhi,  g_wfhi);
    cudaGetSymbolAddress((void**)&wflo,  g_wflo);
    cudaGetSymbolAddress((void**)&wbhi,  g_wbhi);
    cudaGetSymbolAddress((void**)&wblo,  g_wblo);
    cudaGetSymbolAddress((void**)&wqhi,  g_wqhi);
    cudaGetSymbolAddress((void**)&wqlo,  g_wqlo);

    cudaFuncSetAttribute((const void*)mma_mm<1, 0, 128, 128, 128>, cudaFuncAttributeMaxDynamicSharedMemorySize, 147456);
    cudaFuncSetAttribute((const void*)mma_mm<9, 0, 128, 128, 128>, cudaFuncAttributeMaxDynamicSharedMemorySize, 147456);
    cudaFuncSetAttribute((const void*)mma_mm<9, 1, 64, 64, 256>,   cudaFuncAttributeMaxDynamicSharedMemorySize, 184320);

    // 1-4: preprocessing (bf16 hi/lo splits)
    split_k<<<dim3(16, 128, 8), dim3(32, 8)>>>(x, xhi, xlo, 512, 0);
    wsplit_k<<<(512 * 1024 * 9 + 255) / 256, 256>>>(fus_w, wfhi, wflo, 1024, 9, (size_t)512 * 1024 * 9);
    wsplit_k<<<(64 * 512 * 9 + 255) / 256, 256>>>(box_w1, wbhi, wblo, 512, 9, (size_t)64 * 512 * 9);
    wsplit_k<<<(1536 * 512 + 255) / 256, 256>>>(qkv_w, wqhi, wqlo, 512, 1, (size_t)1536 * 512);

    // 5: box conv3x3(512->64)+GELU, M=64 x N=256 tiles (no dead rows)
    mma_mm<9, 1, 64, 64, 256><<<dim3(128, 1), 256, 184320>>>(wbhi, wblo, xhi, xlo, box_b1, box1, 512, 64);

    // 6: qkv 1x1 (512->1536)  [profiled by ncu -s 5 -c 1]
    mma_mm<1, 0, 128, 128, 128><<<dim3(256, 12), 256, 147456>>>(wqhi, wqlo, xhi, xlo, qkv_b, qkv, 512, 1536);

    // box tail + edge net
    conv1x1_small_k<2><<<dim3(32, 16), 256>>>(box1, box_w2, box_b2, boxes, 64, 4);
    conv3x3_k<0><<<dim3(512, 1), 128>>>(boxes, 4, edge_w1, edge_b1, edge1, 64);
    gn_stats_k<<<64, 256>>>(edge1, gnst);
    gn_apply_k<<<8192, 256>>>(edge1, gnst, gn_g, gn_b);
    conv1x1_small_k<0><<<dim3(64, 16), 256>>>(edge1, edge_w2, edge_b2, edge, 64, 8);

    // attention (tensor cores)
    attn_qk_mma<<<4096, 128>>>(qkv, edge, attn);
    softmax_i_k<<<2048, 128>>>(attn);
    attn_av_mma<<<4096, 128>>>(qkv, attn, agg);

    // split agg into ci[512:1024) of the bf16 buffer
    split_k<<<dim3(16, 128, 8), dim3(32, 8)>>>(agg, xhi, xlo, 512, 512);

    // fusion conv3x3 (1024->512) on tensor cores
    mma_mm<9, 0, 128, 128, 128><<<dim3(256, 4), 256, 147456>>>(wfhi, wflo, xhi, xlo, fus_b, y, 1024, 512);

    // batchnorm + SiLU
    bn_stats_k<<<512, 256>>>(y, bnst);
    bn_apply_k<<<65536, 256>>>(y, bnst, bn_g, bn_b, out);
}

// round 9
// speedup vs baseline: 4.1452x; 1.1008x over previous
#include <cuda_runtime.h>
#include <cuda_bf16.h>
#include <cstdint>
#include <math.h>

#define BB 8
#define CC 512
#define PP 4096
#define NHH 8

// ---- scratch (static device globals; no allocation) ----
__device__ float g_box1[BB*64*PP];
__device__ float g_boxes[BB*4*PP];
__device__ float g_edge1[BB*64*PP];
__device__ float g_edge[BB*NHH*PP];
__device__ float g_qkv[(size_t)BB*1536*PP];
__device__ float g_attn[(size_t)BB*NHH*64*64*64];
__device__ float g_agg[(size_t)BB*CC*PP];
__device__ float g_y[(size_t)BB*CC*PP];
__device__ float g_gnstats[BB*8*2];
__device__ float g_bnstats[CC*2];
__device__ __nv_bfloat16 g_xhi[(size_t)BB*PP*1024];   // [b][p][ci]
__device__ __nv_bfloat16 g_xlo[(size_t)BB*PP*1024];
__device__ __nv_bfloat16 g_wfhi[512*9*1024];          // [co][tap][ci]
__device__ __nv_bfloat16 g_wflo[512*9*1024];
__device__ __nv_bfloat16 g_wbhi[64*9*512];
__device__ __nv_bfloat16 g_wblo[64*9*512];
__device__ __nv_bfloat16 g_wqhi[1536*512];
__device__ __nv_bfloat16 g_wqlo[1536*512];

__device__ __forceinline__ float geluf(float x) {
    return 0.5f * x * (1.0f + erff(x * 0.70710678118654752440f));
}
__device__ __forceinline__ float sigm(float x) { return 1.0f / (1.0f + __expf(-x)); }

// ---- arch-neutral tensor-core helpers (sm_80+ PTX only) ----
__device__ __forceinline__ uint32_t smem_u32(const void* p) {
    uint32_t a;
    asm("{ .reg .u64 t; cvta.to.shared.u64 t, %1; cvt.u32.u64 %0, t; }" : "=r"(a) : "l"(p));
    return a;
}
__device__ __forceinline__ void ldsm_x4(uint32_t* r, uint32_t addr) {
    asm volatile("ldmatrix.sync.aligned.m8n8.x4.shared.b16 {%0,%1,%2,%3}, [%4];"
        : "=r"(r[0]), "=r"(r[1]), "=r"(r[2]), "=r"(r[3]) : "r"(addr));
}
__device__ __forceinline__ void mma16816(float* d, const uint32_t* a, const uint32_t* b) {
    asm volatile("mma.sync.aligned.m16n8k16.row.col.f32.bf16.bf16.f32 "
        "{%0,%1,%2,%3}, {%4,%5,%6,%7}, {%8,%9}, {%0,%1,%2,%3};"
        : "+f"(d[0]), "+f"(d[1]), "+f"(d[2]), "+f"(d[3])
        : "r"(a[0]), "r"(a[1]), "r"(a[2]), "r"(a[3]), "r"(b[0]), "r"(b[1]));
}
__device__ __forceinline__ void cpa16(uint32_t dst, const void* src, uint32_t sz) {
    asm volatile("cp.async.cg.shared.global [%0], [%1], 16, %2;\n" :: "r"(dst), "l"(src), "r"(sz));
}
#define CP_COMMIT() asm volatile("cp.async.commit_group;\n" ::: "memory")
#define CP_WAIT1()  asm volatile("cp.async.wait_group 1;\n" ::: "memory")
#define CP_WAIT0()  asm volatile("cp.async.wait_group 0;\n" ::: "memory")

// ---- split / transpose: NCHW fp32 -> [b][p][ci] bf16 hi/lo ----
__global__ void split_k(const float* __restrict__ src, __nv_bfloat16* __restrict__ xhi,
                        __nv_bfloat16* __restrict__ xlo, int Cn, int cibase)
{
    __shared__ float tile[32][33];
    int bz = blockIdx.z, c0 = blockIdx.x * 32, p0 = blockIdx.y * 32;
    int tx = threadIdx.x, ty = threadIdx.y;
#pragma unroll
    for (int i = 0; i < 32; i += 8)
        tile[ty + i][tx] = src[((size_t)bz * Cn + c0 + ty + i) * 4096 + p0 + tx];
    __syncthreads();
#pragma unroll
    for (int i = 0; i < 32; i += 8) {
        float v = tile[tx][ty + i];
        __nv_bfloat16 h = __float2bfloat16(v);
        size_t o = ((size_t)bz * 4096 + p0 + ty + i) * 1024 + cibase + c0 + tx;
        xhi[o] = h;
        xlo[o] = __float2bfloat16(v - __bfloat162float(h));
    }
}

// OIHW fp32 -> [co][tap][ci] bf16 hi/lo
__global__ void wsplit_k(const float* __restrict__ w, __nv_bfloat16* __restrict__ whi,
                         __nv_bfloat16* __restrict__ wlo, int Cin, int taps, size_t total)
{
    size_t i = (size_t)blockIdx.x * 256 + threadIdx.x;
    if (i >= total) return;
    int tap = (int)(i % taps);
    size_t t2 = i / taps;
    int ci = (int)(t2 % Cin);
    int co = (int)(t2 / Cin);
    float v = w[i];
    __nv_bfloat16 h = __float2bfloat16(v);
    size_t dst = ((size_t)co * taps + tap) * Cin + ci;
    whi[dst] = h;
    wlo[dst] = __float2bfloat16(v - __bfloat162float(h));
}

// ================= specialized fusion conv3x3 (1024->512) with B-halo reuse ==========
// CTA: 128 co x 128 px (2 h-rows x 64 w). A double-buffered per (ci,tap) chunk;
// B: haloed pixel tile (4 h-rows x 66 w) per ci-chunk, serves all 9 taps.
#define FA_ST 36864            // A stage: 2(hl) x 128 rows x 144B
#define FA_LO 18432
#define FB0   73728            // B stages start (= 2*FA_ST)
#define FB_ST 76032            // B stage: 2(hl) x 264 rows x 144B
#define FB_HL 38016
#define FUS_SMEM 225792        // 2*FA_ST + 2*FB_ST

__device__ __forceinline__ void fus_loadA(uint32_t sb, int t,
    const __nv_bfloat16* __restrict__ whi, const __nv_bfloat16* __restrict__ wlo,
    int co0, int c)
{
    int cik = c / 9, tap = c - cik * 9, ci0 = cik * 64;
#pragma unroll
    for (int i = 0; i < 8; i++) {
        int idx = t + i * 256;
        int hl = idx >> 10, rem = idx & 1023, row = rem >> 3, seg = rem & 7;
        const __nv_bfloat16* src = (hl ? wlo : whi)
            + ((size_t)(co0 + row) * 9 + tap) * 1024 + ci0 + seg * 8;
        cpa16(sb + hl * FA_LO + row * 144 + seg * 16, src, 16u);
    }
}

__device__ __forceinline__ void fus_loadB(uint32_t sb, int t,
    const __nv_bfloat16* __restrict__ xhi, const __nv_bfloat16* __restrict__ xlo,
    int b, int h0, int cik)
{
    int ci0 = cik * 64;
    for (int idx = t; idx < 4224; idx += 256) {     // 2(hl) x 264 rows x 8 segs
        int hl = idx / 2112, rem = idx % 2112, row = rem >> 3, seg = rem & 7;
        int hrel = row / 66, wrel = row - hrel * 66;
        int h = h0 - 1 + hrel, w = wrel - 1;
        bool ok = ((unsigned)h < 64u) && ((unsigned)w < 64u);
        const __nv_bfloat16* src = (hl ? xlo : xhi)
            + ((size_t)(b * 4096 + (ok ? h * 64 + w : 0))) * 1024 + ci0 + seg * 8;
        cpa16(sb + hl * FB_HL + row * 144 + seg * 16, src, ok ? 16u : 0u);
    }
}

__global__ __launch_bounds__(256) void fus_mm(
    const __nv_bfloat16* __restrict__ whi, const __nv_bfloat16* __restrict__ wlo,
    const __nv_bfloat16* __restrict__ xhi, const __nv_bfloat16* __restrict__ xlo,
    const float* __restrict__ bias, float* __restrict__ out)
{
    extern __shared__ char dynsmem[];
    const int b = blockIdx.x >> 5;
    const int pbase = (blockIdx.x & 31) * 128;
    const int h0 = pbase >> 6;
    const int co0 = blockIdx.y * 128;
    const int t = threadIdx.x, lane = t & 31, warp = t >> 5;
    const int wm = warp & 1, wn = warp >> 1;
    const uint32_t sb = smem_u32(dynsmem);

    float acc[4][4][4];
#pragma unroll
    for (int fm = 0; fm < 4; fm++)
#pragma unroll
        for (int fn = 0; fn < 4; fn++)
#pragma unroll
            for (int k = 0; k < 4; k++) acc[fm][fn][k] = 0.f;

    // prologue: B(ci0)+A0 | A1
    fus_loadB(sb + FB0, t, xhi, xlo, b, h0, 0);
    fus_loadA(sb, t, whi, wlo, co0, 0);
    CP_COMMIT();
    fus_loadA(sb + FA_ST, t, whi, wlo, co0, 1);
    CP_COMMIT();

    const int arow = wm * 64 + (lane & 15);
    const int akoff = (lane >> 4) * 16;
    const int l8 = lane & 7, grp = lane >> 3;
    const int bprel = wn * 32 + l8 + (grp >> 1) * 8;   // px-rel row 0..127 (warp-aligned 32)
    const int bkoff = (grp & 1) * 16;
    const int bhw = (bprel >> 6) * 66 + (bprel & 63);  // halo row before tap offset

    for (int c = 0; c < 144; c++) {
        if (c == 143) { CP_WAIT0(); } else { CP_WAIT1(); }
        __syncthreads();
        const int cik = c / 9, tap = c - cik * 9;
        const int tapoff = (tap / 3) * 66 + (tap % 3); // (1+dh)*66 + (1+dw)
        const uint32_t Ast = sb + (c & 1) * FA_ST;
        const uint32_t Bst = sb + FB0 + (cik & 1) * FB_ST;
        const uint32_t abase = Ast + arow * 144 + akoff;
        const uint32_t bbase = Bst + (bhw + tapoff) * 144 + bkoff;
#pragma unroll
        for (int ks = 0; ks < 4; ks++) {
            const int kb = ks * 32;
            uint32_t ah[4][4], al[4][4];
#pragma unroll
            for (int fm = 0; fm < 4; fm++) {
                ldsm_x4(ah[fm], abase + fm * 16 * 144 + kb);
                ldsm_x4(al[fm], abase + FA_LO + fm * 16 * 144 + kb);
            }
            uint32_t bh[4][2], bl[4][2];
#pragma unroll
            for (int fp = 0; fp < 2; fp++) {
                uint32_t r[4];
                uint32_t addr = bbase + fp * 16 * 144 + kb;    // +16 w stays in same h-row
                ldsm_x4(r, addr);
                bh[fp*2][0] = r[0]; bh[fp*2][1] = r[1];
                bh[fp*2+1][0] = r[2]; bh[fp*2+1][1] = r[3];
                ldsm_x4(r, addr + FB_HL);
                bl[fp*2][0] = r[0]; bl[fp*2][1] = r[1];
                bl[fp*2+1][0] = r[2]; bl[fp*2+1][1] = r[3];
            }
#pragma unroll
            for (int fm = 0; fm < 4; fm++)
#pragma unroll
                for (int fn = 0; fn < 4; fn++) {
                    mma16816(acc[fm][fn], ah[fm], bh[fn]);
                    mma16816(acc[fm][fn], ah[fm], bl[fn]);
                    mma16816(acc[fm][fn], al[fm], bh[fn]);
                }
        }
        __syncthreads();
        if (c + 2 < 144)
            fus_loadA(Ast, t, whi, wlo, co0, c + 2);
        if (tap == 0 && cik + 1 < 16)
            fus_loadB(sb + FB0 + ((cik + 1) & 1) * FB_ST, t, xhi, xlo, b, h0, cik + 1);
        CP_COMMIT();
    }

    // epilogue
    const int r0 = lane >> 2, c0 = (lane & 3) * 2;
#pragma unroll
    for (int fm = 0; fm < 4; fm++) {
        int co = co0 + wm * 64 + fm * 16 + r0;
        float bv0 = bias[co], bv8 = bias[co + 8];
        float* op0 = out + ((size_t)b * 512 + co) * 4096 + pbase;
        float* op8 = op0 + (size_t)8 * 4096;
#pragma unroll
        for (int fn = 0; fn < 4; fn++) {
            int p = wn * 32 + fn * 8 + c0;
            *(float2*)(op0 + p) = make_float2(acc[fm][fn][0] + bv0, acc[fm][fn][1] + bv0);
            *(float2*)(op8 + p) = make_float2(acc[fm][fn][2] + bv8, acc[fm][fn][3] + bv8);
        }
    }
}

// ---- generic mma.sync implicit GEMM (qkv 1x1, box conv) ----
template<int TAPS, int COUTV, int ROWSA, int ROWSB>
__device__ __forceinline__ void mm_load(uint32_t sb, int t,
    const __nv_bfloat16* __restrict__ whi, const __nv_bfloat16* __restrict__ wlo,
    const __nv_bfloat16* __restrict__ xhi, const __nv_bfloat16* __restrict__ xlo,
    int co0, int WCin, int b, int pbase, int c)
{
    const int A_LO_ = ROWSA * 144;
    const int B_HI_ = 2 * ROWSA * 144;
    const int B_LO_D = ROWSB * 144;
    int cik = c / TAPS, tap = c - cik * TAPS;
    int dh = (TAPS == 9) ? tap / 3 - 1 : 0;
    int dw = (TAPS == 9) ? tap % 3 - 1 : 0;
    int ci0 = cik * 64;
#pragma unroll
    for (int i = 0; i < ROWSA / 16; i++) {
        int idx = t + i * 256;
        int hl = idx / (ROWSA * 8), rem = idx % (ROWSA * 8), row = rem >> 3, seg = rem & 7;
        int rr = (COUTV < ROWSA && row >= COUTV) ? 0 : row;
        const __nv_bfloat16* src = (hl ? wlo : whi)
            + ((size_t)(co0 + rr) * TAPS + tap) * WCin + ci0 + seg * 8;
        cpa16(sb + hl * A_LO_ + row * 144 + seg * 16, src,
              (COUTV < ROWSA && row >= COUTV) ? 0u : 16u);
    }
#pragma unroll
    for (int i = 0; i < ROWSB / 16; i++) {
        int idx = t + i * 256;
        int hl = idx / (ROWSB * 8), rem = idx % (ROWSB * 8), row = rem >> 3, seg = rem & 7;
        int p = pbase + row;
        int ih = (p >> 6) + dh, iw = (p & 63) + dw;
        bool ok = (TAPS == 1) || (((unsigned)ih < 64u) && ((unsigned)iw < 64u));
        const __nv_bfloat16* src = (hl ? xlo : xhi)
            + ((size_t)(b * 4096 + (ok ? ih * 64 + iw : 0))) * 1024 + ci0 + seg * 8;
        cpa16(sb + B_HI_ + hl * B_LO_D + row * 144 + seg * 16, src, ok ? 16u : 0u);
    }
}

template<int TAPS, int ACT, int COUTV, int ROWSA, int ROWSB>
__global__ __launch_bounds__(256) void mma_mm(
    const __nv_bfloat16* __restrict__ whi, const __nv_bfloat16* __restrict__ wlo,
    const __nv_bfloat16* __restrict__ xhi, const __nv_bfloat16* __restrict__ xlo,
    const float* __restrict__ bias, float* __restrict__ out, int WCin, int Cout)
{
    extern __shared__ char dynsmem[];
    const int A_LO_ = ROWSA * 144;
    const int B_HI_ = 2 * ROWSA * 144;
    const int B_LO_D = ROWSB * 144;
    const int MSTAGE_ = 2 * (ROWSA + ROWSB) * 144;
    const int NPT = 4096 / ROWSB;
    const int b = blockIdx.x / NPT;
    const int pbase = (blockIdx.x % NPT) * ROWSB;
    const int co0 = blockIdx.y * ROWSA;
    const int t = threadIdx.x, lane = t & 31, warp = t >> 5;
    const int wm = (ROWSA == 128) ? (warp & 1) : 0;
    const int wn = (ROWSA == 128) ? (warp >> 1) : warp;
    const uint32_t sb0 = smem_u32(dynsmem);
    const int NCH = (WCin / 64) * TAPS;

    float acc[4][4][4];
#pragma unroll
    for (int fm = 0; fm < 4; fm++)
#pragma unroll
        for (int fn = 0; fn < 4; fn++)
#pragma unroll
            for (int k = 0; k < 4; k++) acc[fm][fn][k] = 0.f;

    mm_load<TAPS, COUTV, ROWSA, ROWSB>(sb0, t, whi, wlo, xhi, xlo, co0, WCin, b, pbase, 0); CP_COMMIT();
    mm_load<TAPS, COUTV, ROWSA, ROWSB>(sb0 + MSTAGE_, t, whi, wlo, xhi, xlo, co0, WCin, b, pbase, 1); CP_COMMIT();

    const int arow = wm * 64 + (lane & 15);
    const int akoff = (lane >> 4) * 16;
    const int l8 = lane & 7, grp = lane >> 3;
    const int brow = wn * 32 + l8 + (grp >> 1) * 8;
    const int bkoff = (grp & 1) * 16;

    for (int c = 0; c < NCH; c++) {
        const uint32_t sb = sb0 + (c & 1) * MSTAGE_;
        if (c == NCH - 1) { CP_WAIT0(); } else { CP_WAIT1(); }
        __syncthreads();
        const uint32_t abase = sb + arow * 144 + akoff;
        const uint32_t bbase = sb + B_HI_ + brow * 144 + bkoff;
#pragma unroll
        for (int ks = 0; ks < 4; ks++) {
            const int kb = ks * 32;
            uint32_t ah[4][4], al[4][4];
#pragma unroll
            for (int fm = 0; fm < 4; fm++) {
                ldsm_x4(ah[fm], abase + fm * 16 * 144 + kb);
                ldsm_x4(al[fm], abase + A_LO_ + fm * 16 * 144 + kb);
            }
            uint32_t bh[4][2], bl[4][2];
#pragma unroll
            for (int fp = 0; fp < 2; fp++) {
                uint32_t r[4];
                uint32_t addr = bbase + fp * 16 * 144 + kb;
                ldsm_x4(r, addr);
                bh[fp*2][0] = r[0]; bh[fp*2][1] = r[1];
                bh[fp*2+1][0] = r[2]; bh[fp*2+1][1] = r[3];
                ldsm_x4(r, addr + B_LO_D);
                bl[fp*2][0] = r[0]; bl[fp*2][1] = r[1];
                bl[fp*2+1][0] = r[2]; bl[fp*2+1][1] = r[3];
            }
#pragma unroll
            for (int fm = 0; fm < 4; fm++)
#pragma unroll
                for (int fn = 0; fn < 4; fn++) {
                    mma16816(acc[fm][fn], ah[fm], bh[fn]);
                    mma16816(acc[fm][fn], ah[fm], bl[fn]);
                    mma16816(acc[fm][fn], al[fm], bh[fn]);
                }
        }
        __syncthreads();
        if (c + 2 < NCH) {
            mm_load<TAPS, COUTV, ROWSA, ROWSB>(sb, t, whi, wlo, xhi, xlo, co0, WCin, b, pbase, c + 2);
            CP_COMMIT();
        }
    }

    const int r0 = lane >> 2, c0 = (lane & 3) * 2;
#pragma unroll
    for (int fm = 0; fm < 4; fm++) {
        int co = co0 + wm * 64 + fm * 16 + r0;
        bool v0ok = (COUTV >= ROWSA) || (co < COUTV);
        bool v8ok = (COUTV >= ROWSA) || (co + 8 < COUTV);
        float bv0 = v0ok ? bias[co] : 0.f;
        float bv8 = v8ok ? bias[co + 8] : 0.f;
        float* op0 = out + ((size_t)b * Cout + co) * 4096 + pbase;
        float* op8 = op0 + (size_t)8 * 4096;
#pragma unroll
        for (int fn = 0; fn < 4; fn++) {
            int p = wn * 32 + fn * 8 + c0;
            float a0 = acc[fm][fn][0] + bv0, a1 = acc[fm][fn][1] + bv0;
            float a2 = acc[fm][fn][2] + bv8, a3 = acc[fm][fn][3] + bv8;
            if (ACT == 1) { a0 = geluf(a0); a1 = geluf(a1); a2 = geluf(a2); a3 = geluf(a3); }
            if (v0ok) *(float2*)(op0 + p) = make_float2(a0, a1);
            if (v8ok) *(float2*)(op8 + p) = make_float2(a2, a3);
        }
    }
}

// ---- attention QK logits via mma ----
__global__ __launch_bounds__(128) void attn_qk_mma(
    const float* __restrict__ qkv, const float* __restrict__ edge, float* __restrict__ attn)
{
    int id = blockIdx.x;
    int i = id & 63, h = (id >> 6) & 7, b = id >> 9;
    const float* Q = qkv + ((size_t)(b * 1536 + h * 64 + i)) * PP;
    const float* K = qkv + ((size_t)(b * 1536 + 512 + h * 64 + i)) * PP;
    __shared__ __nv_bfloat16 sQh[64*72], sQl[64*72], sKh[64*72], sKl[64*72];
    int t = threadIdx.x, lane = t & 31, warp = t >> 5;
    int wm = warp & 1, wn = warp >> 1;
    for (int idx = t; idx < 4096; idx += 128) {
        int y = idx >> 6, c = idx & 63;
        float q = Q[idx];
        __nv_bfloat16 qh = __float2bfloat16(q);
        sQh[c*72 + y] = qh; sQl[c*72 + y] = __float2bfloat16(q - __bfloat162float(qh));
        float k = K[idx];
        __nv_bfloat16 kh = __float2bfloat16(k);
        sKh[c*72 + y] = kh; sKl[c*72 + y] = __float2bfloat16(k - __bfloat162float(kh));
    }
    __syncthreads();
    float acc[2][4][4];
#pragma unroll
    for (int fm = 0; fm < 2; fm++)
#pragma unroll
        for (int fn = 0; fn < 4; fn++)
#pragma unroll
            for (int k = 0; k < 4; k++) acc[fm][fn][k] = 0.f;

    const uint32_t aQh = smem_u32(sQh), aQl = smem_u32(sQl);
    const uint32_t aKh = smem_u32(sKh), aKl = smem_u32(sKl);
    const int arow = wm * 32 + (lane & 15), akoff = (lane >> 4) * 16;
    const int l8 = lane & 7, grp = lane >> 3;
    const int brow = wn * 32 + l8 + (grp >> 1) * 8, bkoff = (grp & 1) * 16;
#pragma unroll
    for (int ks = 0; ks < 4; ks++) {
        const int kb = ks * 32;
        uint32_t ah[2][4], al[2][4];
#pragma unroll
        for (int fm = 0; fm < 2; fm++) {
            ldsm_x4(ah[fm], aQh + (arow + fm*16) * 144 + akoff + kb);
            ldsm_x4(al[fm], aQl + (arow + fm*16) * 144 + akoff + kb);
        }
        uint32_t bh[4][2], bl[4][2];
#pragma unroll
        for (int fp = 0; fp < 2; fp++) {
            uint32_t r[4];
            ldsm_x4(r, aKh + (brow + fp*16) * 144 + bkoff + kb);
            bh[fp*2][0] = r[0]; bh[fp*2][1] = r[1];
            bh[fp*2+1][0] = r[2]; bh[fp*2+1][1] = r[3];
            ldsm_x4(r, aKl + (brow + fp*16) * 144 + bkoff + kb);
            bl[fp*2][0] = r[0]; bl[fp*2][1] = r[1];
            bl[fp*2+1][0] = r[2]; bl[fp*2+1][1] = r[3];
        }
#pragma unroll
        for (int fm = 0; fm < 2; fm++)
#pragma unroll
            for (int fn = 0; fn < 4; fn++) {
                mma16816(acc[fm][fn], ah[fm], bh[fn]);
                mma16816(acc[fm][fn], ah[fm], bl[fn]);
                mma16816(acc[fm][fn], al[fm], bh[fn]);
            }
    }
    const int r0 = lane >> 2, c0 = (lane & 3) * 2;
    float* op = attn + (size_t)id * 4096;
    const float* ep = edge + (size_t)id * 64;
#pragma unroll
    for (int fm = 0; fm < 2; fm++) {
        int w0 = wm * 32 + fm * 16 + r0;
        float e0 = ep[w0], e8 = ep[w0 + 8];
#pragma unroll
        for (int fn = 0; fn < 4; fn++) {
            int Wp = wn * 32 + fn * 8 + c0;
            op[w0*64 + Wp]       = acc[fm][fn][0] * 0.125f + e0;
            op[w0*64 + Wp + 1]   = acc[fm][fn][1] * 0.125f + e0;
            op[(w0+8)*64 + Wp]   = acc[fm][fn][2] * 0.125f + e8;
            op[(w0+8)*64 + Wp+1] = acc[fm][fn][3] * 0.125f + e8;
        }
    }
}

// ---- attention AV via mma ----
__global__ __launch_bounds__(128) void attn_av_mma(
    const float* __restrict__ qkv, const float* __restrict__ attn, float* __restrict__ agg)
{
    int id = blockIdx.x;
    int i = id & 63, h = (id >> 6) & 7, b = id >> 9;
    const float* V = qkv + ((size_t)(b * 1536 + 1024 + h * 64 + i)) * PP;
    const float* A = attn + (size_t)id * 4096;
    __shared__ __nv_bfloat16 sVh[64*72], sVl[64*72], sAh[64*72], sAl[64*72];
    int t = threadIdx.x, lane = t & 31, warp = t >> 5;
    int wm = warp & 1, wn = warp >> 1;
    for (int idx = t; idx < 4096; idx += 128) {
        int r = idx >> 6, c = idx & 63;
        float v = V[idx];
        __nv_bfloat16 vh = __float2bfloat16(v);
        sVh[r*72 + c] = vh; sVl[r*72 + c] = __float2bfloat16(v - __bfloat162float(vh));
        float a = A[idx];
        __nv_bfloat16 ahv = __float2bfloat16(a);
        sAh[r*72 + c] = ahv; sAl[r*72 + c] = __float2bfloat16(a - __bfloat162float(ahv));
    }
    __syncthreads();
    float acc[2][4][4];
#pragma unroll
    for (int fm = 0; fm < 2; fm++)
#pragma unroll
        for (int fn = 0; fn < 4; fn++)
#pragma unroll
            for (int k = 0; k < 4; k++) acc[fm][fn][k] = 0.f;

    const uint32_t aVh = smem_u32(sVh), aVl = smem_u32(sVl);
    const uint32_t aAh = smem_u32(sAh), aAl = smem_u32(sAl);
    const int arow = wm * 32 + (lane & 15), akoff = (lane >> 4) * 16;
    const int l8 = lane & 7, grp = lane >> 3;
    const int brow = wn * 32 + l8 + (grp >> 1) * 8, bkoff = (grp & 1) * 16;
#pragma unroll
    for (int ks = 0; ks < 4; ks++) {
        const int kb = ks * 32;
        uint32_t ah[2][4], al[2][4];
#pragma unroll
        for (int fm = 0; fm < 2; fm++) {
            ldsm_x4(ah[fm], aVh + (arow + fm*16) * 144 + akoff + kb);
            ldsm_x4(al[fm], aVl + (arow + fm*16) * 144 + akoff + kb);
        }
        uint32_t bh[4][2], bl[4][2];
#pragma unroll
        for (int fp = 0; fp < 2; fp++) {
            uint32_t r[4];
            ldsm_x4(r, aAh + (brow + fp*16) * 144 + bkoff + kb);
            bh[fp*2][0] = r[0]; bh[fp*2][1] = r[1];
            bh[fp*2+1][0] = r[2]; bh[fp*2+1][1] = r[3];
            ldsm_x4(r, aAl + (brow + fp*16) * 144 + bkoff + kb);
            bl[fp*2][0] = r[0]; bl[fp*2][1] = r[1];
            bl[fp*2+1][0] = r[2]; bl[fp*2+1][1] = r[3];
        }
#pragma unroll
        for (int fm = 0; fm < 2; fm++)
#pragma unroll
            for (int fn = 0; fn < 4; fn++) {
                mma16816(acc[fm][fn], ah[fm], bh[fn]);
                mma16816(acc[fm][fn], ah[fm], bl[fn]);
                mma16816(acc[fm][fn], al[fm], bh[fn]);
            }
    }
    const int r0 = lane >> 2, c0 = (lane & 3) * 2;
    float* op = agg + ((size_t)(b * 512 + h * 64 + i)) * PP;
#pragma unroll
    for (int fm = 0; fm < 2; fm++) {
        int d0 = wm * 32 + fm * 16 + r0;
#pragma unroll
        for (int fn = 0; fn < 4; fn++) {
            int w = wn * 32 + fn * 8 + c0;
            op[d0*64 + w]       = acc[fm][fn][0];
            op[d0*64 + w + 1]   = acc[fm][fn][1];
            op[(d0+8)*64 + w]   = acc[fm][fn][2];
            op[(d0+8)*64 + w+1] = acc[fm][fn][3];
        }
    }
}

// ---- FFMA 3x3 conv (edge net: Cin=4 -> 64 only) ----
#define CI_CHUNK 8
template<int ACT>
__global__ __launch_bounds__(128) void conv3x3_k(
    const float* __restrict__ in1, int Cin,
    const float* __restrict__ wgt, const float* __restrict__ bias,
    float* __restrict__ out, int Cout)
{
    const int bh = blockIdx.x, b = bh >> 6, h = bh & 63;
    const int co0 = blockIdx.y * 64;
    const int t = threadIdx.x, tx = t & 7, ty = t >> 3;
    __shared__ float sIn[CI_CHUNK][3][66];
    __shared__ float sW[64][CI_CHUNK * 9];
    float acc[4][8];
#pragma unroll
    for (int a = 0; a < 4; a++)
#pragma unroll
        for (int j = 0; j < 8; j++) acc[a][j] = 0.f;

    for (int cb = 0; cb < Cin; cb += CI_CHUNK) {
        __syncthreads();
        for (int idx = t; idx < CI_CHUNK * 3 * 66; idx += 128) {
            int ci = idx / 198, rem = idx - ci * 198, r = rem / 66, col = rem - r * 66;
            int cg = cb + ci;
            float v = 0.f;
            int gh = h - 1 + r, gw = col - 1;
            if (cg < Cin && (unsigned)gh < 64u && (unsigned)gw < 64u)
                v = in1[((size_t)(b * Cin + cg)) * PP + gh * 64 + gw];
            sIn[ci][r][col] = v;
        }
        for (int idx = t; idx < 64 * CI_CHUNK * 9; idx += 128) {
            int co = idx / (CI_CHUNK * 9), rem = idx - co * (CI_CHUNK * 9);
            int ci = rem / 9, kk = rem - ci * 9, cg = cb + ci;
            sW[co][ci * 9 + kk] = (cg < Cin) ? wgt[((size_t)(co0 + co) * Cin + cg) * 9 + kk] : 0.f;
        }
        __syncthreads();
#pragma unroll 2
        for (int ci = 0; ci < CI_CHUNK; ci++) {
#pragma unroll
            for (int r = 0; r < 3; r++) {
                float iv[10];
#pragma unroll
                for (int j = 0; j < 10; j++) iv[j] = sIn[ci][r][tx * 8 + j];
#pragma unroll
                for (int cj = 0; cj < 4; cj++) {
                    float w0 = sW[ty * 4 + cj][ci * 9 + r * 3 + 0];
                    float w1 = sW[ty * 4 + cj][ci * 9 + r * 3 + 1];
                    float w2 = sW[ty * 4 + cj][ci * 9 + r * 3 + 2];
#pragma unroll
                    for (int wj = 0; wj < 8; wj++) {
                        acc[cj][wj] = fmaf(w0, iv[wj + 0], acc[cj][wj]);
                        acc[cj][wj] = fmaf(w1, iv[wj + 1], acc[cj][wj]);
                        acc[cj][wj] = fmaf(w2, iv[wj + 2], acc[cj][wj]);
                    }
                }
            }
        }
    }
#pragma unroll
    for (int cj = 0; cj < 4; cj++) {
        int co = co0 + ty * 4 + cj;
        float bv = bias[co];
#pragma unroll
        for (int wj = 0; wj < 8; wj++) {
            float v = acc[cj][wj] + bv;
            if (ACT == 1) v = geluf(v);
            out[(((size_t)b * Cout + co) * 64 + h) * 64 + tx * 8 + wj] = v;
        }
    }
}

template<int ACT>
__global__ void conv1x1_small_k(const float* __restrict__ in, const float* __restrict__ wgt,
                                const float* __restrict__ bias, float* __restrict__ out,
                                int Cin, int Cout)
{
    int bc = blockIdx.x, b = bc / Cout, co = bc - b * Cout;
    int p = blockIdx.y * 256 + threadIdx.x;
    float acc = bias[co];
    const float* ip = in + (size_t)b * Cin * PP + p;
    const float* wp = wgt + (size_t)co * Cin;
    for (int ci = 0; ci < Cin; ci++)
        acc = fmaf(wp[ci], ip[(size_t)ci * PP], acc);
    if (ACT == 2) acc = sigm(acc);
    out[((size_t)b * Cout + co) * PP + p] = acc;
}

// ---- GroupNorm ----
__global__ void gn_stats_k(const float* __restrict__ x, float* __restrict__ stats)
{
    int bg = blockIdx.x, b = bg >> 3, g = bg & 7;
    const float* p = x + ((size_t)b * 64 + g * 8) * PP;
    float s = 0.f, s2 = 0.f;
    for (int i = threadIdx.x; i < 8 * PP; i += 256) {
        float v = p[i]; s += v; s2 += v * v;
    }
    __shared__ float rs[8], rs2[8];
#pragma unroll
    for (int o = 16; o > 0; o >>= 1) {
        s += __shfl_down_sync(0xffffffffu, s, o);
        s2 += __shfl_down_sync(0xffffffffu, s2, o);
    }
    int w = threadIdx.x >> 5, l = threadIdx.x & 31;
    if (l == 0) { rs[w] = s; rs2[w] = s2; }
    __syncthreads();
    if (w == 0) {
        s = (l < 8) ? rs[l] : 0.f; s2 = (l < 8) ? rs2[l] : 0.f;
#pragma unroll
        for (int o = 4; o > 0; o >>= 1) {
            s += __shfl_down_sync(0xffffffffu, s, o);
            s2 += __shfl_down_sync(0xffffffffu, s2, o);
        }
        if (l == 0) {
            float m = s / 32768.f;
            stats[bg * 2] = m;
            stats[bg * 2 + 1] = s2 / 32768.f - m * m;
        }
    }
}

__global__ void gn_apply_k(float* __restrict__ x, const float* __restrict__ stats,
                           const float* __restrict__ gamma, const float* __restrict__ beta)
{
    size_t idx = (size_t)blockIdx.x * 256 + threadIdx.x;
    int c = (int)((idx >> 12) & 63);
    int b = (int)(idx >> 18);
    int bg = b * 8 + (c >> 3);
    float m = stats[bg * 2], v = stats[bg * 2 + 1];
    float xn = (x[idx] - m) * rsqrtf(v + 1e-5f) * gamma[c] + beta[c];
    x[idx] = geluf(xn);
}

// ---- softmax over i ----
__global__ __launch_bounds__(128) void softmax_i_k(float* __restrict__ attn)
{
    int n = blockIdx.x * 128 + threadIdx.x;
    int bh = n >> 12, ww = n & 4095;
    float* p = attn + (size_t)bh * 262144 + ww;
    float x[64], mx = -1e30f;
#pragma unroll
    for (int i = 0; i < 64; i++) { x[i] = p[(size_t)i * 4096]; mx = fmaxf(mx, x[i]); }
    float s = 0.f;
#pragma unroll
    for (int i = 0; i < 64; i++) { x[i] = __expf(x[i] - mx); s += x[i]; }
    float inv = 1.f / s;
#pragma unroll
    for (int i = 0; i < 64; i++) p[(size_t)i * 4096] = x[i] * inv;
}

// ---- BatchNorm ----
__global__ void bn_stats_k(const float* __restrict__ y, float* __restrict__ stats)
{
    int c = blockIdx.x;
    float s = 0.f, s2 = 0.f;
    for (int n = threadIdx.x; n < 32768; n += 256) {
        int b = n >> 12, p = n & 4095;
        float v = y[((size_t)b * CC + c) * PP + p];
        s += v; s2 += v * v;
    }
    __shared__ float rs[8], rs2[8];
#pragma unroll
    for (int o = 16; o > 0; o >>= 1) {
        s += __shfl_down_sync(0xffffffffu, s, o);
        s2 += __shfl_down_sync(0xffffffffu, s2, o);
    }
    int w = threadIdx.x >> 5, l = threadIdx.x & 31;
    if (l == 0) { rs[w] = s; rs2[w] = s2; }
    __syncthreads();
    if (w == 0) {
        s = (l < 8) ? rs[l] : 0.f; s2 = (l < 8) ? rs2[l] : 0.f;
#pragma unroll
        for (int o = 4; o > 0; o >>= 1) {
            s += __shfl_down_sync(0xffffffffu, s, o);
            s2 += __shfl_down_sync(0xffffffffu, s2, o);
        }
        if (l == 0) {
            float m = s / 32768.f;
            stats[c * 2] = m;
            stats[c * 2 + 1] = s2 / 32768.f - m * m;
        }
    }
}

__global__ void bn_apply_k(const float* __restrict__ y, const float* __restrict__ stats,
                           const float* __restrict__ g, const float* __restrict__ bt,
                           float* __restrict__ out)
{
    size_t idx = (size_t)blockIdx.x * 256 + threadIdx.x;
    int c = (int)((idx >> 12) & 511);
    float m = stats[c * 2], v = stats[c * 2 + 1];
    float yn = (y[idx] - m) * rsqrtf(v + 1e-5f) * g[c] + bt[c];
    out[idx] = yn * (1.f / (1.f + __expf(-yn)));
}

// ---- launch ----
extern "C" void kernel_launch(void* const* d_in, const int* in_sizes, int n_in,
                              void* d_out, int out_size)
{
    const float* x       = (const float*)d_in[0];
    const float* box_w1  = (const float*)d_in[1];
    const float* box_b1  = (const float*)d_in[2];
    const float* box_w2  = (const float*)d_in[3];
    const float* box_b2  = (const float*)d_in[4];
    const float* edge_w1 = (const float*)d_in[5];
    const float* edge_b1 = (const float*)d_in[6];
    const float* gn_g    = (const float*)d_in[7];
    const float* gn_b    = (const float*)d_in[8];
    const float* edge_w2 = (const float*)d_in[9];
    const float* edge_b2 = (const float*)d_in[10];
    const float* qkv_w   = (const float*)d_in[11];
    const float* qkv_b   = (const float*)d_in[12];
    const float* fus_w   = (const float*)d_in[13];
    const float* fus_b   = (const float*)d_in[14];
    const float* bn_g    = (const float*)d_in[15];
    const float* bn_b    = (const float*)d_in[16];
    float* out = (float*)d_out;

    float *box1, *boxes, *edge1, *edge, *qkv, *attn, *agg, *y, *gnst, *bnst;
    __nv_bfloat16 *xhi, *xlo, *wfhi, *wflo, *wbhi, *wblo, *wqhi, *wqlo;
    cudaGetSymbolAddress((void**)&box1,  g_box1);
    cudaGetSymbolAddress((void**)&boxes, g_boxes);
    cudaGetSymbolAddress((void**)&edge1, g_edge1);
    cudaGetSymbolAddress((void**)&edge,  g_edge);
    cudaGetSymbolAddress((void**)&qkv,   g_qkv);
    cudaGetSymbolAddress((void**)&attn,  g_attn);
    cudaGetSymbolAddress((void**)&agg,   g_agg);
    cudaGetSymbolAddress((void**)&y,     g_y);
    cudaGetSymbolAddress((void**)&gnst,  g_gnstats);
    cudaGetSymbolAddress((void**)&bnst,  g_bnstats);
    cudaGetSymbolAddress((void**)&xhi,   g_xhi);
    cudaGetSymbolAddress((void**)&xlo,   g_xlo);
    cudaGetSymbolAddress((void**)&wfhi,  g_wfhi);
    cudaGetSymbolAddress((void**)&wflo,  g_wflo);
    cudaGetSymbolAddress((void**)&wbhi,  g_wbhi);
    cudaGetSymbolAddress((void**)&wblo,  g_wblo);
    cudaGetSymbolAddress((void**)&wqhi,  g_wqhi);
    cudaGetSymbolAddress((void**)&wqlo,  g_wqlo);

    cudaFuncSetAttribute((const void*)mma_mm<1, 0, 128, 128, 128>, cudaFuncAttributeMaxDynamicSharedMemorySize, 147456);
    cudaFuncSetAttribute((const void*)mma_mm<9, 1, 64, 64, 256>,   cudaFuncAttributeMaxDynamicSharedMemorySize, 184320);
    cudaFuncSetAttribute((const void*)fus_mm, cudaFuncAttributeMaxDynamicSharedMemorySize, FUS_SMEM);

    // preprocessing (bf16 hi/lo splits)
    split_k<<<dim3(16, 128, 8), dim3(32, 8)>>>(x, xhi, xlo, 512, 0);
    wsplit_k<<<(512 * 1024 * 9 + 255) / 256, 256>>>(fus_w, wfhi, wflo, 1024, 9, (size_t)512 * 1024 * 9);
    wsplit_k<<<(64 * 512 * 9 + 255) / 256, 256>>>(box_w1, wbhi, wblo, 512, 9, (size_t)64 * 512 * 9);
    wsplit_k<<<(1536 * 512 + 255) / 256, 256>>>(qkv_w, wqhi, wqlo, 512, 1, (size_t)1536 * 512);

    // box conv3x3(512->64)+GELU, M=64 x N=256 tiles
    mma_mm<9, 1, 64, 64, 256><<<dim3(128, 1), 256, 184320>>>(wbhi, wblo, xhi, xlo, box_b1, box1, 512, 64);

    // qkv 1x1 (512->1536)
    mma_mm<1, 0, 128, 128, 128><<<dim3(256, 12), 256, 147456>>>(wqhi, wqlo, xhi, xlo, qkv_b, qkv, 512, 1536);

    // box tail + edge net
    conv1x1_small_k<2><<<dim3(32, 16), 256>>>(box1, box_w2, box_b2, boxes, 64, 4);
    conv3x3_k<0><<<dim3(512, 1), 128>>>(boxes, 4, edge_w1, edge_b1, edge1, 64);
    gn_stats_k<<<64, 256>>>(edge1, gnst);
    gn_apply_k<<<8192, 256>>>(edge1, gnst, gn_g, gn_b);
    conv1x1_small_k<0><<<dim3(64, 16), 256>>>(edge1, edge_w2, edge_b2, edge, 64, 8);

    // attention (tensor cores)
    attn_qk_mma<<<4096, 128>>>(qkv, edge, attn);
    softmax_i_k<<<2048, 128>>>(attn);
    attn_av_mma<<<4096, 128>>>(qkv, attn, agg);

    // split agg into ci[512:1024) of the bf16 buffer
    split_k<<<dim3(16, 128, 8), dim3(32, 8)>>>(agg, xhi, xlo, 512, 512);

    // fusion conv3x3 (1024->512), B-halo reuse
    fus_mm<<<dim3(256, 4), 256, FUS_SMEM>>>(wfhi, wflo, xhi, xlo, fus_b, y);

    // batchnorm + SiLU
    bn_stats_k<<<512, 256>>>(y, bnst);
    bn_apply_k<<<65536, 256>>>(y, bnst, bn_g, bn_b, out);
}

// round 10
// speedup vs baseline: 5.4664x; 1.3187x over previous
#include <cuda_runtime.h>
#include <cuda_fp16.h>
#include <cstdint>
#include <math.h>

#define BB 8
#define CC 512
#define PP 4096
#define NHH 8

// ---- scratch (static device globals; no allocation) ----
__device__ float g_box1[BB*64*PP];
__device__ float g_boxes[BB*4*PP];
__device__ float g_edge1[BB*64*PP];
__device__ float g_edge[BB*NHH*PP];
__device__ float g_qkv[(size_t)BB*1536*PP];
__device__ float g_attn[(size_t)BB*NHH*64*64*64];
__device__ float g_agg[(size_t)BB*CC*PP];
__device__ float g_y[(size_t)BB*CC*PP];
__device__ float g_gnstats[BB*8*2];
__device__ float g_bnstats[CC*2];
__device__ __half g_xhi[(size_t)BB*PP*1024];   // [b][p][ci]
__device__ __half g_xlo[(size_t)BB*PP*1024];
__device__ __half g_wfhi[512*9*1024];          // [co][tap][ci] (fusion: hi only used)
__device__ __half g_wflo[512*9*1024];
__device__ __half g_wbhi[64*9*512];
__device__ __half g_wblo[64*9*512];
__device__ __half g_wqhi[1536*512];
__device__ __half g_wqlo[1536*512];

__device__ __forceinline__ float geluf(float x) {
    return 0.5f * x * (1.0f + erff(x * 0.70710678118654752440f));
}
__device__ __forceinline__ float sigm(float x) { return 1.0f / (1.0f + __expf(-x)); }

// ---- arch-neutral tensor-core helpers (sm_80+ PTX only) ----
__device__ __forceinline__ uint32_t smem_u32(const void* p) {
    uint32_t a;
    asm("{ .reg .u64 t; cvta.to.shared.u64 t, %1; cvt.u32.u64 %0, t; }" : "=r"(a) : "l"(p));
    return a;
}
__device__ __forceinline__ void ldsm_x4(uint32_t* r, uint32_t addr) {
    asm volatile("ldmatrix.sync.aligned.m8n8.x4.shared.b16 {%0,%1,%2,%3}, [%4];"
        : "=r"(r[0]), "=r"(r[1]), "=r"(r[2]), "=r"(r[3]) : "r"(addr));
}
__device__ __forceinline__ void mma16816(float* d, const uint32_t* a, const uint32_t* b) {
    asm volatile("mma.sync.aligned.m16n8k16.row.col.f32.f16.f16.f32 "
        "{%0,%1,%2,%3}, {%4,%5,%6,%7}, {%8,%9}, {%0,%1,%2,%3};"
        : "+f"(d[0]), "+f"(d[1]), "+f"(d[2]), "+f"(d[3])
        : "r"(a[0]), "r"(a[1]), "r"(a[2]), "r"(a[3]), "r"(b[0]), "r"(b[1]));
}
__device__ __forceinline__ void cpa16(uint32_t dst, const void* src, uint32_t sz) {
    asm volatile("cp.async.cg.shared.global [%0], [%1], 16, %2;\n" :: "r"(dst), "l"(src), "r"(sz));
}
#define CP_COMMIT() asm volatile("cp.async.commit_group;\n" ::: "memory")
#define CP_WAIT1()  asm volatile("cp.async.wait_group 1;\n" ::: "memory")
#define CP_WAIT0()  asm volatile("cp.async.wait_group 0;\n" ::: "memory")

// ---- split / transpose: NCHW fp32 -> [b][p][ci] fp16 hi/lo ----
__global__ void split_k(const float* __restrict__ src, __half* __restrict__ xhi,
                        __half* __restrict__ xlo, int Cn, int cibase)
{
    __shared__ float tile[32][33];
    int bz = blockIdx.z, c0 = blockIdx.x * 32, p0 = blockIdx.y * 32;
    int tx = threadIdx.x, ty = threadIdx.y;
#pragma unroll
    for (int i = 0; i < 32; i += 8)
        tile[ty + i][tx] = src[((size_t)bz * Cn + c0 + ty + i) * 4096 + p0 + tx];
    __syncthreads();
#pragma unroll
    for (int i = 0; i < 32; i += 8) {
        float v = tile[tx][ty + i];
        __half h = __float2half_rn(v);
        size_t o = ((size_t)bz * 4096 + p0 + ty + i) * 1024 + cibase + c0 + tx;
        xhi[o] = h;
        xlo[o] = __float2half_rn(v - __half2float(h));
    }
}

// OIHW fp32 -> [co][tap][ci] fp16 hi/lo
__global__ void wsplit_k(const float* __restrict__ w, __half* __restrict__ whi,
                         __half* __restrict__ wlo, int Cin, int taps, size_t total)
{
    size_t i = (size_t)blockIdx.x * 256 + threadIdx.x;
    if (i >= total) return;
    int tap = (int)(i % taps);
    size_t t2 = i / taps;
    int ci = (int)(t2 % Cin);
    int co = (int)(t2 / Cin);
    float v = w[i];
    __half h = __float2half_rn(v);
    size_t dst = ((size_t)co * taps + tap) * Cin + ci;
    whi[dst] = h;
    wlo[dst] = __float2half_rn(v - __half2float(h));
}

// ================= fusion conv3x3 (1024->512): B-halo reuse + 2-term fp16 ==========
// CTA: 128 co x 128 px. A (W-hi only) double-buffered per (ci,tap) chunk;
// B: haloed pixel tile (4 h-rows x 66 w, hi+lo) per ci-chunk, serves all 9 taps.
#define FA_ST 18432            // A stage: 128 rows x 144B (hi only)
#define FB0   36864            // B stages start (= 2*FA_ST)
#define FB_ST 76032            // B stage: 2(hl) x 264 rows x 144B
#define FB_HL 38016
#define FUS_SMEM 188928        // 2*FA_ST + 2*FB_ST

__device__ __forceinline__ void fus_loadA(uint32_t sb, int t,
    const __half* __restrict__ whi, int co0, int c)
{
    int cik = c / 9, tap = c - cik * 9, ci0 = cik * 64;
#pragma unroll
    for (int i = 0; i < 4; i++) {          // 128 rows x 8 segs
        int idx = t + i * 256;
        int row = idx >> 3, seg = idx & 7;
        const __half* src = whi + ((size_t)(co0 + row) * 9 + tap) * 1024 + ci0 + seg * 8;
        cpa16(sb + row * 144 + seg * 16, src, 16u);
    }
}

__device__ __forceinline__ void fus_loadB(uint32_t sb, int t,
    const __half* __restrict__ xhi, const __half* __restrict__ xlo,
    int b, int h0, int cik)
{
    int ci0 = cik * 64;
    for (int idx = t; idx < 4224; idx += 256) {     // 2(hl) x 264 rows x 8 segs
        int hl = idx / 2112, rem = idx % 2112, row = rem >> 3, seg = rem & 7;
        int hrel = row / 66, wrel = row - hrel * 66;
        int h = h0 - 1 + hrel, w = wrel - 1;
        bool ok = ((unsigned)h < 64u) && ((unsigned)w < 64u);
        const __half* src = (hl ? xlo : xhi)
            + ((size_t)(b * 4096 + (ok ? h * 64 + w : 0))) * 1024 + ci0 + seg * 8;
        cpa16(sb + hl * FB_HL + row * 144 + seg * 16, src, ok ? 16u : 0u);
    }
}

__global__ __launch_bounds__(256) void fus_mm(
    const __half* __restrict__ whi,
    const __half* __restrict__ xhi, const __half* __restrict__ xlo,
    const float* __restrict__ bias, float* __restrict__ out)
{
    extern __shared__ char dynsmem[];
    const int b = blockIdx.x >> 5;
    const int pbase = (blockIdx.x & 31) * 128;
    const int h0 = pbase >> 6;
    const int co0 = blockIdx.y * 128;
    const int t = threadIdx.x, lane = t & 31, warp = t >> 5;
    const int wm = warp & 1, wn = warp >> 1;
    const uint32_t sb = smem_u32(dynsmem);

    float acc[4][4][4];
#pragma unroll
    for (int fm = 0; fm < 4; fm++)
#pragma unroll
        for (int fn = 0; fn < 4; fn++)
#pragma unroll
            for (int k = 0; k < 4; k++) acc[fm][fn][k] = 0.f;

    // prologue: B(ci0)+A0 | A1
    fus_loadB(sb + FB0, t, xhi, xlo, b, h0, 0);
    fus_loadA(sb, t, whi, co0, 0);
    CP_COMMIT();
    fus_loadA(sb + FA_ST, t, whi, co0, 1);
    CP_COMMIT();

    const int arow = wm * 64 + (lane & 15);
    const int akoff = (lane >> 4) * 16;
    const int l8 = lane & 7, grp = lane >> 3;
    const int bprel = wn * 32 + l8 + (grp >> 1) * 8;
    const int bkoff = (grp & 1) * 16;
    const int bhw = (bprel >> 6) * 66 + (bprel & 63);

    for (int c = 0; c < 144; c++) {
        if (c == 143) { CP_WAIT0(); } else { CP_WAIT1(); }
        __syncthreads();
        const int cik = c / 9, tap = c - cik * 9;
        const int tapoff = (tap / 3) * 66 + (tap % 3);
        const uint32_t Ast = sb + (c & 1) * FA_ST;
        const uint32_t Bst = sb + FB0 + (cik & 1) * FB_ST;
        const uint32_t abase = Ast + arow * 144 + akoff;
        const uint32_t bbase = Bst + (bhw + tapoff) * 144 + bkoff;
#pragma unroll
        for (int ks = 0; ks < 4; ks++) {
            const int kb = ks * 32;
            uint32_t ah[4][4];
#pragma unroll
            for (int fm = 0; fm < 4; fm++)
                ldsm_x4(ah[fm], abase + fm * 16 * 144 + kb);
            uint32_t bh[4][2], bl[4][2];
#pragma unroll
            for (int fp = 0; fp < 2; fp++) {
                uint32_t r[4];
                uint32_t addr = bbase + fp * 16 * 144 + kb;
                ldsm_x4(r, addr);
                bh[fp*2][0] = r[0]; bh[fp*2][1] = r[1];
                bh[fp*2+1][0] = r[2]; bh[fp*2+1][1] = r[3];
                ldsm_x4(r, addr + FB_HL);
                bl[fp*2][0] = r[0]; bl[fp*2][1] = r[1];
                bl[fp*2+1][0] = r[2]; bl[fp*2+1][1] = r[3];
            }
#pragma unroll
            for (int fm = 0; fm < 4; fm++)
#pragma unroll
                for (int fn = 0; fn < 4; fn++) {
                    mma16816(acc[fm][fn], ah[fm], bh[fn]);
                    mma16816(acc[fm][fn], ah[fm], bl[fn]);
                }
        }
        __syncthreads();
        if (c + 2 < 144)
            fus_loadA(Ast, t, whi, co0, c + 2);
        if (tap == 0 && cik + 1 < 16)
            fus_loadB(sb + FB0 + ((cik + 1) & 1) * FB_ST, t, xhi, xlo, b, h0, cik + 1);
        CP_COMMIT();
    }

    const int r0 = lane >> 2, c0 = (lane & 3) * 2;
#pragma unroll
    for (int fm = 0; fm < 4; fm++) {
        int co = co0 + wm * 64 + fm * 16 + r0;
        float bv0 = bias[co], bv8 = bias[co + 8];
        float* op0 = out + ((size_t)b * 512 + co) * 4096 + pbase;
        float* op8 = op0 + (size_t)8 * 4096;
#pragma unroll
        for (int fn = 0; fn < 4; fn++) {
            int p = wn * 32 + fn * 8 + c0;
            *(float2*)(op0 + p) = make_float2(acc[fm][fn][0] + bv0, acc[fm][fn][1] + bv0);
            *(float2*)(op8 + p) = make_float2(acc[fm][fn][2] + bv8, acc[fm][fn][3] + bv8);
        }
    }
}

// ---- generic mma.sync implicit GEMM (qkv 1x1, box conv), 3-term fp16 ----
template<int TAPS, int COUTV, int ROWSA, int ROWSB>
__device__ __forceinline__ void mm_load(uint32_t sb, int t,
    const __half* __restrict__ whi, const __half* __restrict__ wlo,
    const __half* __restrict__ xhi, const __half* __restrict__ xlo,
    int co0, int WCin, int b, int pbase, int c)
{
    const int A_LO_ = ROWSA * 144;
    const int B_HI_ = 2 * ROWSA * 144;
    const int B_LO_D = ROWSB * 144;
    int cik = c / TAPS, tap = c - cik * TAPS;
    int dh = (TAPS == 9) ? tap / 3 - 1 : 0;
    int dw = (TAPS == 9) ? tap % 3 - 1 : 0;
    int ci0 = cik * 64;
#pragma unroll
    for (int i = 0; i < ROWSA / 16; i++) {
        int idx = t + i * 256;
        int hl = idx / (ROWSA * 8), rem = idx % (ROWSA * 8), row = rem >> 3, seg = rem & 7;
        int rr = (COUTV < ROWSA && row >= COUTV) ? 0 : row;
        const __half* src = (hl ? wlo : whi)
            + ((size_t)(co0 + rr) * TAPS + tap) * WCin + ci0 + seg * 8;
        cpa16(sb + hl * A_LO_ + row * 144 + seg * 16, src,
              (COUTV < ROWSA && row >= COUTV) ? 0u : 16u);
    }
#pragma unroll
    for (int i = 0; i < ROWSB / 16; i++) {
        int idx = t + i * 256;
        int hl = idx / (ROWSB * 8), rem = idx % (ROWSB * 8), row = rem >> 3, seg = rem & 7;
        int p = pbase + row;
        int ih = (p >> 6) + dh, iw = (p & 63) + dw;
        bool ok = (TAPS == 1) || (((unsigned)ih < 64u) && ((unsigned)iw < 64u));
        const __half* src = (hl ? xlo : xhi)
            + ((size_t)(b * 4096 + (ok ? ih * 64 + iw : 0))) * 1024 + ci0 + seg * 8;
        cpa16(sb + B_HI_ + hl * B_LO_D + row * 144 + seg * 16, src, ok ? 16u : 0u);
    }
}

template<int TAPS, int ACT, int COUTV, int ROWSA, int ROWSB>
__global__ __launch_bounds__(256) void mma_mm(
    const __half* __restrict__ whi, const __half* __restrict__ wlo,
    const __half* __restrict__ xhi, const __half* __restrict__ xlo,
    const float* __restrict__ bias, float* __restrict__ out, int WCin, int Cout)
{
    extern __shared__ char dynsmem[];
    const int A_LO_ = ROWSA * 144;
    const int B_HI_ = 2 * ROWSA * 144;
    const int B_LO_D = ROWSB * 144;
    const int MSTAGE_ = 2 * (ROWSA + ROWSB) * 144;
    const int NPT = 4096 / ROWSB;
    const int b = blockIdx.x / NPT;
    const int pbase = (blockIdx.x % NPT) * ROWSB;
    const int co0 = blockIdx.y * ROWSA;
    const int t = threadIdx.x, lane = t & 31, warp = t >> 5;
    const int wm = (ROWSA == 128) ? (warp & 1) : 0;
    const int wn = (ROWSA == 128) ? (warp >> 1) : warp;
    const uint32_t sb0 = smem_u32(dynsmem);
    const int NCH = (WCin / 64) * TAPS;

    float acc[4][4][4];
#pragma unroll
    for (int fm = 0; fm < 4; fm++)
#pragma unroll
        for (int fn = 0; fn < 4; fn++)
#pragma unroll
            for (int k = 0; k < 4; k++) acc[fm][fn][k] = 0.f;

    mm_load<TAPS, COUTV, ROWSA, ROWSB>(sb0, t, whi, wlo, xhi, xlo, co0, WCin, b, pbase, 0); CP_COMMIT();
    mm_load<TAPS, COUTV, ROWSA, ROWSB>(sb0 + MSTAGE_, t, whi, wlo, xhi, xlo, co0, WCin, b, pbase, 1); CP_COMMIT();

    const int arow = wm * 64 + (lane & 15);
    const int akoff = (lane >> 4) * 16;
    const int l8 = lane & 7, grp = lane >> 3;
    const int brow = wn * 32 + l8 + (grp >> 1) * 8;
    const int bkoff = (grp & 1) * 16;

    for (int c = 0; c < NCH; c++) {
        const uint32_t sb = sb0 + (c & 1) * MSTAGE_;
        if (c == NCH - 1) { CP_WAIT0(); } else { CP_WAIT1(); }
        __syncthreads();
        const uint32_t abase = sb + arow * 144 + akoff;
        const uint32_t bbase = sb + B_HI_ + brow * 144 + bkoff;
#pragma unroll
        for (int ks = 0; ks < 4; ks++) {
            const int kb = ks * 32;
            uint32_t ah[4][4], al[4][4];
#pragma unroll
            for (int fm = 0; fm < 4; fm++) {
                ldsm_x4(ah[fm], abase + fm * 16 * 144 + kb);
                ldsm_x4(al[fm], abase + A_LO_ + fm * 16 * 144 + kb);
            }
            uint32_t bh[4][2], bl[4][2];
#pragma unroll
            for (int fp = 0; fp < 2; fp++) {
                uint32_t r[4];
                uint32_t addr = bbase + fp * 16 * 144 + kb;
                ldsm_x4(r, addr);
                bh[fp*2][0] = r[0]; bh[fp*2][1] = r[1];
                bh[fp*2+1][0] = r[2]; bh[fp*2+1][1] = r[3];
                ldsm_x4(r, addr + B_LO_D);
                bl[fp*2][0] = r[0]; bl[fp*2][1] = r[1];
                bl[fp*2+1][0] = r[2]; bl[fp*2+1][1] = r[3];
            }
#pragma unroll
            for (int fm = 0; fm < 4; fm++)
#pragma unroll
                for (int fn = 0; fn < 4; fn++) {
                    mma16816(acc[fm][fn], ah[fm], bh[fn]);
                    mma16816(acc[fm][fn], ah[fm], bl[fn]);
                    mma16816(acc[fm][fn], al[fm], bh[fn]);
                }
        }
        __syncthreads();
        if (c + 2 < NCH) {
            mm_load<TAPS, COUTV, ROWSA, ROWSB>(sb, t, whi, wlo, xhi, xlo, co0, WCin, b, pbase, c + 2);
            CP_COMMIT();
        }
    }

    const int r0 = lane >> 2, c0 = (lane & 3) * 2;
#pragma unroll
    for (int fm = 0; fm < 4; fm++) {
        int co = co0 + wm * 64 + fm * 16 + r0;
        bool v0ok = (COUTV >= ROWSA) || (co < COUTV);
        bool v8ok = (COUTV >= ROWSA) || (co + 8 < COUTV);
        float bv0 = v0ok ? bias[co] : 0.f;
        float bv8 = v8ok ? bias[co + 8] : 0.f;
        float* op0 = out + ((size_t)b * Cout + co) * 4096 + pbase;
        float* op8 = op0 + (size_t)8 * 4096;
#pragma unroll
        for (int fn = 0; fn < 4; fn++) {
            int p = wn * 32 + fn * 8 + c0;
            float a0 = acc[fm][fn][0] + bv0, a1 = acc[fm][fn][1] + bv0;
            float a2 = acc[fm][fn][2] + bv8, a3 = acc[fm][fn][3] + bv8;
            if (ACT == 1) { a0 = geluf(a0); a1 = geluf(a1); a2 = geluf(a2); a3 = geluf(a3); }
            if (v0ok) *(float2*)(op0 + p) = make_float2(a0, a1);
            if (v8ok) *(float2*)(op8 + p) = make_float2(a2, a3);
        }
    }
}

// ---- attention QK logits via mma (3-term fp16) ----
__global__ __launch_bounds__(128) void attn_qk_mma(
    const float* __restrict__ qkv, const float* __restrict__ edge, float* __restrict__ attn)
{
    int id = blockIdx.x;
    int i = id & 63, h = (id >> 6) & 7, b = id >> 9;
    const float* Q = qkv + ((size_t)(b * 1536 + h * 64 + i)) * PP;
    const float* K = qkv + ((size_t)(b * 1536 + 512 + h * 64 + i)) * PP;
    __shared__ __half sQh[64*72], sQl[64*72], sKh[64*72], sKl[64*72];
    int t = threadIdx.x, lane = t & 31, warp = t >> 5;
    int wm = warp & 1, wn = warp >> 1;
    for (int idx = t; idx < 4096; idx += 128) {
        int y = idx >> 6, c = idx & 63;
        float q = Q[idx];
        __half qh = __float2half_rn(q);
        sQh[c*72 + y] = qh; sQl[c*72 + y] = __float2half_rn(q - __half2float(qh));
        float k = K[idx];
        __half kh = __float2half_rn(k);
        sKh[c*72 + y] = kh; sKl[c*72 + y] = __float2half_rn(k - __half2float(kh));
    }
    __syncthreads();
    float acc[2][4][4];
#pragma unroll
    for (int fm = 0; fm < 2; fm++)
#pragma unroll
        for (int fn = 0; fn < 4; fn++)
#pragma unroll
            for (int k = 0; k < 4; k++) acc[fm][fn][k] = 0.f;

    const uint32_t aQh = smem_u32(sQh), aQl = smem_u32(sQl);
    const uint32_t aKh = smem_u32(sKh), aKl = smem_u32(sKl);
    const int arow = wm * 32 + (lane & 15), akoff = (lane >> 4) * 16;
    const int l8 = lane & 7, grp = lane >> 3;
    const int brow = wn * 32 + l8 + (grp >> 1) * 8, bkoff = (grp & 1) * 16;
#pragma unroll
    for (int ks = 0; ks < 4; ks++) {
        const int kb = ks * 32;
        uint32_t ah[2][4], al[2][4];
#pragma unroll
        for (int fm = 0; fm < 2; fm++) {
            ldsm_x4(ah[fm], aQh + (arow + fm*16) * 144 + akoff + kb);
            ldsm_x4(al[fm], aQl + (arow + fm*16) * 144 + akoff + kb);
        }
        uint32_t bh[4][2], bl[4][2];
#pragma unroll
        for (int fp = 0; fp < 2; fp++) {
            uint32_t r[4];
            ldsm_x4(r, aKh + (brow + fp*16) * 144 + bkoff + kb);
            bh[fp*2][0] = r[0]; bh[fp*2][1] = r[1];
            bh[fp*2+1][0] = r[2]; bh[fp*2+1][1] = r[3];
            ldsm_x4(r, aKl + (brow + fp*16) * 144 + bkoff + kb);
            bl[fp*2][0] = r[0]; bl[fp*2][1] = r[1];
            bl[fp*2+1][0] = r[2]; bl[fp*2+1][1] = r[3];
        }
#pragma unroll
        for (int fm = 0; fm < 2; fm++)
#pragma unroll
            for (int fn = 0; fn < 4; fn++) {
                mma16816(acc[fm][fn], ah[fm], bh[fn]);
                mma16816(acc[fm][fn], ah[fm], bl[fn]);
                mma16816(acc[fm][fn], al[fm], bh[fn]);
            }
    }
    const int r0 = lane >> 2, c0 = (lane & 3) * 2;
    float* op = attn + (size_t)id * 4096;
    const float* ep = edge + (size_t)id * 64;
#pragma unroll
    for (int fm = 0; fm < 2; fm++) {
        int w0 = wm * 32 + fm * 16 + r0;
        float e0 = ep[w0], e8 = ep[w0 + 8];
#pragma unroll
        for (int fn = 0; fn < 4; fn++) {
            int Wp = wn * 32 + fn * 8 + c0;
            op[w0*64 + Wp]       = acc[fm][fn][0] * 0.125f + e0;
            op[w0*64 + Wp + 1]   = acc[fm][fn][1] * 0.125f + e0;
            op[(w0+8)*64 + Wp]   = acc[fm][fn][2] * 0.125f + e8;
            op[(w0+8)*64 + Wp+1] = acc[fm][fn][3] * 0.125f + e8;
        }
    }
}

// ---- attention AV via mma (3-term fp16) ----
__global__ __launch_bounds__(128) void attn_av_mma(
    const float* __restrict__ qkv, const float* __restrict__ attn, float* __restrict__ agg)
{
    int id = blockIdx.x;
    int i = id & 63, h = (id >> 6) & 7, b = id >> 9;
    const float* V = qkv + ((size_t)(b * 1536 + 1024 + h * 64 + i)) * PP;
    const float* A = attn + (size_t)id * 4096;
    __shared__ __half sVh[64*72], sVl[64*72], sAh[64*72], sAl[64*72];
    int t = threadIdx.x, lane = t & 31, warp = t >> 5;
    int wm = warp & 1, wn = warp >> 1;
    for (int idx = t; idx < 4096; idx += 128) {
        int r = idx >> 6, c = idx & 63;
        float v = V[idx];
        __half vh = __float2half_rn(v);
        sVh[r*72 + c] = vh; sVl[r*72 + c] = __float2half_rn(v - __half2float(vh));
        float a = A[idx];
        __half ahv = __float2half_rn(a);
        sAh[r*72 + c] = ahv; sAl[r*72 + c] = __float2half_rn(a - __half2float(ahv));
    }
    __syncthreads();
    float acc[2][4][4];
#pragma unroll
    for (int fm = 0; fm < 2; fm++)
#pragma unroll
        for (int fn = 0; fn < 4; fn++)
#pragma unroll
            for (int k = 0; k < 4; k++) acc[fm][fn][k] = 0.f;

    const uint32_t aVh = smem_u32(sVh), aVl = smem_u32(sVl);
    const uint32_t aAh = smem_u32(sAh), aAl = smem_u32(sAl);
    const int arow = wm * 32 + (lane & 15), akoff = (lane >> 4) * 16;
    const int l8 = lane & 7, grp = lane >> 3;
    const int brow = wn * 32 + l8 + (grp >> 1) * 8, bkoff = (grp & 1) * 16;
#pragma unroll
    for (int ks = 0; ks < 4; ks++) {
        const int kb = ks * 32;
        uint32_t ah[2][4], al[2][4];
#pragma unroll
        for (int fm = 0; fm < 2; fm++) {
            ldsm_x4(ah[fm], aVh + (arow + fm*16) * 144 + akoff + kb);
            ldsm_x4(al[fm], aVl + (arow + fm*16) * 144 + akoff + kb);
        }
        uint32_t bh[4][2], bl[4][2];
#pragma unroll
        for (int fp = 0; fp < 2; fp++) {
            uint32_t r[4];
            ldsm_x4(r, aAh + (brow + fp*16) * 144 + bkoff + kb);
            bh[fp*2][0] = r[0]; bh[fp*2][1] = r[1];
            bh[fp*2+1][0] = r[2]; bh[fp*2+1][1] = r[3];
            ldsm_x4(r, aAl + (brow + fp*16) * 144 + bkoff + kb);
            bl[fp*2][0] = r[0]; bl[fp*2][1] = r[1];
            bl[fp*2+1][0] = r[2]; bl[fp*2+1][1] = r[3];
        }
#pragma unroll
        for (int fm = 0; fm < 2; fm++)
#pragma unroll
            for (int fn = 0; fn < 4; fn++) {
                mma16816(acc[fm][fn], ah[fm], bh[fn]);
                mma16816(acc[fm][fn], ah[fm], bl[fn]);
                mma16816(acc[fm][fn], al[fm], bh[fn]);
            }
    }
    const int r0 = lane >> 2, c0 = (lane & 3) * 2;
    float* op = agg + ((size_t)(b * 512 + h * 64 + i)) * PP;
#pragma unroll
    for (int fm = 0; fm < 2; fm++) {
        int d0 = wm * 32 + fm * 16 + r0;
#pragma unroll
        for (int fn = 0; fn < 4; fn++) {
            int w = wn * 32 + fn * 8 + c0;
            op[d0*64 + w]       = acc[fm][fn][0];
            op[d0*64 + w + 1]   = acc[fm][fn][1];
            op[(d0+8)*64 + w]   = acc[fm][fn][2];
            op[(d0+8)*64 + w+1] = acc[fm][fn][3];
        }
    }
}

// ---- FFMA 3x3 conv (edge net: Cin=4 -> 64 only) ----
#define CI_CHUNK 8
template<int ACT>
__global__ __launch_bounds__(128) void conv3x3_k(
    const float* __restrict__ in1, int Cin,
    const float* __restrict__ wgt, const float* __restrict__ bias,
    float* __restrict__ out, int Cout)
{
    const int bh = blockIdx.x, b = bh >> 6, h = bh & 63;
    const int co0 = blockIdx.y * 64;
    const int t = threadIdx.x, tx = t & 7, ty = t >> 3;
    __shared__ float sIn[CI_CHUNK][3][66];
    __shared__ float sW[64][CI_CHUNK * 9];
    float acc[4][8];
#pragma unroll
    for (int a = 0; a < 4; a++)
#pragma unroll
        for (int j = 0; j < 8; j++) acc[a][j] = 0.f;

    for (int cb = 0; cb < Cin; cb += CI_CHUNK) {
        __syncthreads();
        for (int idx = t; idx < CI_CHUNK * 3 * 66; idx += 128) {
            int ci = idx / 198, rem = idx - ci * 198, r = rem / 66, col = rem - r * 66;
            int cg = cb + ci;
            float v = 0.f;
            int gh = h - 1 + r, gw = col - 1;
            if (cg < Cin && (unsigned)gh < 64u && (unsigned)gw < 64u)
                v = in1[((size_t)(b * Cin + cg)) * PP + gh * 64 + gw];
            sIn[ci][r][col] = v;
        }
        for (int idx = t; idx < 64 * CI_CHUNK * 9; idx += 128) {
            int co = idx / (CI_CHUNK * 9), rem = idx - co * (CI_CHUNK * 9);
            int ci = rem / 9, kk = rem - ci * 9, cg = cb + ci;
            sW[co][ci * 9 + kk] = (cg < Cin) ? wgt[((size_t)(co0 + co) * Cin + cg) * 9 + kk] : 0.f;
        }
        __syncthreads();
#pragma unroll 2
        for (int ci = 0; ci < CI_CHUNK; ci++) {
#pragma unroll
            for (int r = 0; r < 3; r++) {
                float iv[10];
#pragma unroll
                for (int j = 0; j < 10; j++) iv[j] = sIn[ci][r][tx * 8 + j];
#pragma unroll
                for (int cj = 0; cj < 4; cj++) {
                    float w0 = sW[ty * 4 + cj][ci * 9 + r * 3 + 0];
                    float w1 = sW[ty * 4 + cj][ci * 9 + r * 3 + 1];
                    float w2 = sW[ty * 4 + cj][ci * 9 + r * 3 + 2];
#pragma unroll
                    for (int wj = 0; wj < 8; wj++) {
                        acc[cj][wj] = fmaf(w0, iv[wj + 0], acc[cj][wj]);
                        acc[cj][wj] = fmaf(w1, iv[wj + 1], acc[cj][wj]);
                        acc[cj][wj] = fmaf(w2, iv[wj + 2], acc[cj][wj]);
                    }
                }
            }
        }
    }
#pragma unroll
    for (int cj = 0; cj < 4; cj++) {
        int co = co0 + ty * 4 + cj;
        float bv = bias[co];
#pragma unroll
        for (int wj = 0; wj < 8; wj++) {
            float v = acc[cj][wj] + bv;
            if (ACT == 1) v = geluf(v);
            out[(((size_t)b * Cout + co) * 64 + h) * 64 + tx * 8 + wj] = v;
        }
    }
}

template<int ACT>
__global__ void conv1x1_small_k(const float* __restrict__ in, const float* __restrict__ wgt,
                                const float* __restrict__ bias, float* __restrict__ out,
                                int Cin, int Cout)
{
    int bc = blockIdx.x, b = bc / Cout, co = bc - b * Cout;
    int p = blockIdx.y * 256 + threadIdx.x;
    float acc = bias[co];
    const float* ip = in + (size_t)b * Cin * PP + p;
    const float* wp = wgt + (size_t)co * Cin;
    for (int ci = 0; ci < Cin; ci++)
        acc = fmaf(wp[ci], ip[(size_t)ci * PP], acc);
    if (ACT == 2) acc = sigm(acc);
    out[((size_t)b * Cout + co) * PP + p] = acc;
}

// ---- GroupNorm ----
__global__ void gn_stats_k(const float* __restrict__ x, float* __restrict__ stats)
{
    int bg = blockIdx.x, b = bg >> 3, g = bg & 7;
    const float* p = x + ((size_t)b * 64 + g * 8) * PP;
    float s = 0.f, s2 = 0.f;
    for (int i = threadIdx.x; i < 8 * PP; i += 256) {
        float v = p[i]; s += v; s2 += v * v;
    }
    __shared__ float rs[8], rs2[8];
#pragma unroll
    for (int o = 16; o > 0; o >>= 1) {
        s += __shfl_down_sync(0xffffffffu, s, o);
        s2 += __shfl_down_sync(0xffffffffu, s2, o);
    }
    int w = threadIdx.x >> 5, l = threadIdx.x & 31;
    if (l == 0) { rs[w] = s; rs2[w] = s2; }
    __syncthreads();
    if (w == 0) {
        s = (l < 8) ? rs[l] : 0.f; s2 = (l < 8) ? rs2[l] : 0.f;
#pragma unroll
        for (int o = 4; o > 0; o >>= 1) {
            s += __shfl_down_sync(0xffffffffu, s, o);
            s2 += __shfl_down_sync(0xffffffffu, s2, o);
        }
        if (l == 0) {
            float m = s / 32768.f;
            stats[bg * 2] = m;
            stats[bg * 2 + 1] = s2 / 32768.f - m * m;
        }
    }
}

__global__ void gn_apply_k(float* __restrict__ x, const float* __restrict__ stats,
                           const float* __restrict__ gamma, const float* __restrict__ beta)
{
    size_t idx = (size_t)blockIdx.x * 256 + threadIdx.x;
    int c = (int)((idx >> 12) & 63);
    int b = (int)(idx >> 18);
    int bg = b * 8 + (c >> 3);
    float m = stats[bg * 2], v = stats[bg * 2 + 1];
    float xn = (x[idx] - m) * rsqrtf(v + 1e-5f) * gamma[c] + beta[c];
    x[idx] = geluf(xn);
}

// ---- softmax over i ----
__global__ __launch_bounds__(128) void softmax_i_k(float* __restrict__ attn)
{
    int n = blockIdx.x * 128 + threadIdx.x;
    int bh = n >> 12, ww = n & 4095;
    float* p = attn + (size_t)bh * 262144 + ww;
    float x[64], mx = -1e30f;
#pragma unroll
    for (int i = 0; i < 64; i++) { x[i] = p[(size_t)i * 4096]; mx = fmaxf(mx, x[i]); }
    float s = 0.f;
#pragma unroll
    for (int i = 0; i < 64; i++) { x[i] = __expf(x[i] - mx); s += x[i]; }
    float inv = 1.f / s;
#pragma unroll
    for (int i = 0; i < 64; i++) p[(size_t)i * 4096] = x[i] * inv;
}

// ---- BatchNorm ----
__global__ void bn_stats_k(const float* __restrict__ y, float* __restrict__ stats)
{
    int c = blockIdx.x;
    float s = 0.f, s2 = 0.f;
    for (int n = threadIdx.x; n < 32768; n += 256) {
        int b = n >> 12, p = n & 4095;
        float v = y[((size_t)b * CC + c) * PP + p];
        s += v; s2 += v * v;
    }
    __shared__ float rs[8], rs2[8];
#pragma unroll
    for (int o = 16; o > 0; o >>= 1) {
        s += __shfl_down_sync(0xffffffffu, s, o);
        s2 += __shfl_down_sync(0xffffffffu, s2, o);
    }
    int w = threadIdx.x >> 5, l = threadIdx.x & 31;
    if (l == 0) { rs[w] = s; rs2[w] = s2; }
    __syncthreads();
    if (w == 0) {
        s = (l < 8) ? rs[l] : 0.f; s2 = (l < 8) ? rs2[l] : 0.f;
#pragma unroll
        for (int o = 4; o > 0; o >>= 1) {
            s += __shfl_down_sync(0xffffffffu, s, o);
            s2 += __shfl_down_sync(0xffffffffu, s2, o);
        }
        if (l == 0) {
            float m = s / 32768.f;
            stats[c * 2] = m;
            stats[c * 2 + 1] = s2 / 32768.f - m * m;
        }
    }
}

__global__ void bn_apply_k(const float* __restrict__ y, const float* __restrict__ stats,
                           const float* __restrict__ g, const float* __restrict__ bt,
                           float* __restrict__ out)
{
    size_t idx = (size_t)blockIdx.x * 256 + threadIdx.x;
    int c = (int)((idx >> 12) & 511);
    float m = stats[c * 2], v = stats[c * 2 + 1];
    float yn = (y[idx] - m) * rsqrtf(v + 1e-5f) * g[c] + bt[c];
    out[idx] = yn * (1.f / (1.f + __expf(-yn)));
}

// ---- launch ----
extern "C" void kernel_launch(void* const* d_in, const int* in_sizes, int n_in,
                              void* d_out, int out_size)
{
    const float* x       = (const float*)d_in[0];
    const float* box_w1  = (const float*)d_in[1];
    const float* box_b1  = (const float*)d_in[2];
    const float* box_w2  = (const float*)d_in[3];
    const float* box_b2  = (const float*)d_in[4];
    const float* edge_w1 = (const float*)d_in[5];
    const float* edge_b1 = (const float*)d_in[6];
    const float* gn_g    = (const float*)d_in[7];
    const float* gn_b    = (const float*)d_in[8];
    const float* edge_w2 = (const float*)d_in[9];
    const float* edge_b2 = (const float*)d_in[10];
    const float* qkv_w   = (const float*)d_in[11];
    const float* qkv_b   = (const float*)d_in[12];
    const float* fus_w   = (const float*)d_in[13];
    const float* fus_b   = (const float*)d_in[14];
    const float* bn_g    = (const float*)d_in[15];
    const float* bn_b    = (const float*)d_in[16];
    float* out = (float*)d_out;

    float *box1, *boxes, *edge1, *edge, *qkv, *attn, *agg, *y, *gnst, *bnst;
    __half *xhi, *xlo, *wfhi, *wflo, *wbhi, *wblo, *wqhi, *wqlo;
    cudaGetSymbolAddress((void**)&box1,  g_box1);
    cudaGetSymbolAddress((void**)&boxes, g_boxes);
    cudaGetSymbolAddress((void**)&edge1, g_edge1);
    cudaGetSymbolAddress((void**)&edge,  g_edge);
    cudaGetSymbolAddress((void**)&qkv,   g_qkv);
    cudaGetSymbolAddress((void**)&attn,  g_attn);
    cudaGetSymbolAddress((void**)&agg,   g_agg);
    cudaGetSymbolAddress((void**)&y,     g_y);
    cudaGetSymbolAddress((void**)&gnst,  g_gnstats);
    cudaGetSymbolAddress((void**)&bnst,  g_bnstats);
    cudaGetSymbolAddress((void**)&xhi,   g_xhi);
    cudaGetSymbolAddress((void**)&xlo,   g_xlo);
    cudaGetSymbolAddress((void**)&wfhi,  g_wfhi);
    cudaGetSymbolAddress((void**)&wflo,  g_wflo);
    cudaGetSymbolAddress((void**)&wbhi,  g_wbhi);
    cudaGetSymbolAddress((void**)&wblo,  g_wblo);
    cudaGetSymbolAddress((void**)&wqhi,  g_wqhi);
    cudaGetSymbolAddress((void**)&wqlo,  g_wqlo);

    cudaFuncSetAttribute((const void*)mma_mm<1, 0, 128, 128, 128>, cudaFuncAttributeMaxDynamicSharedMemorySize, 147456);
    cudaFuncSetAttribute((const void*)mma_mm<9, 1, 64, 64, 256>,   cudaFuncAttributeMaxDynamicSharedMemorySize, 184320);
    cudaFuncSetAttribute((const void*)fus_mm, cudaFuncAttributeMaxDynamicSharedMemorySize, FUS_SMEM);

    // preprocessing (fp16 hi/lo splits)
    split_k<<<dim3(16, 128, 8), dim3(32, 8)>>>(x, xhi, xlo, 512, 0);
    wsplit_k<<<(512 * 1024 * 9 + 255) / 256, 256>>>(fus_w, wfhi, wflo, 1024, 9, (size_t)512 * 1024 * 9);
    wsplit_k<<<(64 * 512 * 9 + 255) / 256, 256>>>(box_w1, wbhi, wblo, 512, 9, (size_t)64 * 512 * 9);
    wsplit_k<<<(1536 * 512 + 255) / 256, 256>>>(qkv_w, wqhi, wqlo, 512, 1, (size_t)1536 * 512);

    // box conv3x3(512->64)+GELU, M=64 x N=256 tiles (3-term)
    mma_mm<9, 1, 64, 64, 256><<<dim3(128, 1), 256, 184320>>>(wbhi, wblo, xhi, xlo, box_b1, box1, 512, 64);

    // qkv 1x1 (512->1536) (3-term)
    mma_mm<1, 0, 128, 128, 128><<<dim3(256, 12), 256, 147456>>>(wqhi, wqlo, xhi, xlo, qkv_b, qkv, 512, 1536);

    // box tail + edge net
    conv1x1_small_k<2><<<dim3(32, 16), 256>>>(box1, box_w2, box_b2, boxes, 64, 4);
    conv3x3_k<0><<<dim3(512, 1), 128>>>(boxes, 4, edge_w1, edge_b1, edge1, 64);
    gn_stats_k<<<64, 256>>>(edge1, gnst);
    gn_apply_k<<<8192, 256>>>(edge1, gnst, gn_g, gn_b);
    conv1x1_small_k<0><<<dim3(64, 16), 256>>>(edge1, edge_w2, edge_b2, edge, 64, 8);

    // attention (tensor cores, 3-term)
    attn_qk_mma<<<4096, 128>>>(qkv, edge, attn);
    softmax_i_k<<<2048, 128>>>(attn);
    attn_av_mma<<<4096, 128>>>(qkv, attn, agg);

    // split agg into ci[512:1024) of the fp16 buffer
    split_k<<<dim3(16, 128, 8), dim3(32, 8)>>>(agg, xhi, xlo, 512, 512);

    // fusion conv3x3 (1024->512), B-halo reuse + 2-term fp16
    fus_mm<<<dim3(256, 4), 256, FUS_SMEM>>>(wfhi, xhi, xlo, fus_b, y);

    // batchnorm + SiLU
    bn_stats_k<<<512, 256>>>(y, bnst);
    bn_apply_k<<<65536, 256>>>(y, bnst, bn_g, bn_b, out);
}

// round 11
// speedup vs baseline: 8.4318x; 1.5425x over previous
#include <cuda_runtime.h>
#include <cuda_fp16.h>
#include <cstdint>
#include <math.h>

#define BB 8
#define CC 512
#define PP 4096
#define NHH 8

// ---- scratch (static device globals; no allocation) ----
__device__ float g_box1[BB*64*PP];
__device__ float g_boxes[BB*4*PP];
__device__ float g_edge1[BB*64*PP];
__device__ float g_edge[BB*NHH*PP];
__device__ float g_qkv[(size_t)BB*1536*PP];
__device__ float g_attn[(size_t)BB*NHH*64*64*64];
__device__ float g_agg[(size_t)BB*CC*PP];
__device__ float g_y[(size_t)BB*CC*PP];
__device__ float g_gnstats[BB*8*2];
__device__ float g_bnstats[CC*2];
__device__ __half g_xhi[(size_t)BB*PP*1024];   // [b][p][ci]
__device__ __half g_xlo[(size_t)BB*PP*1024];
__device__ __half g_wfhi[512*9*1024];          // [co][tap][ci]
__device__ __half g_wbhi[64*9*512];
__device__ __half g_wblo[64*9*512];            // unused (2-term) but kept for layout
__device__ __half g_wqhi[1536*512];
__device__ __half g_wqlo[1536*512];            // unused (2-term)

__device__ __forceinline__ float geluf(float x) {
    return 0.5f * x * (1.0f + erff(x * 0.70710678118654752440f));
}
__device__ __forceinline__ float sigm(float x) { return 1.0f / (1.0f + __expf(-x)); }

// ---- arch-neutral tensor-core helpers (sm_80+ PTX only) ----
__device__ __forceinline__ uint32_t smem_u32(const void* p) {
    uint32_t a;
    asm("{ .reg .u64 t; cvta.to.shared.u64 t, %1; cvt.u32.u64 %0, t; }" : "=r"(a) : "l"(p));
    return a;
}
__device__ __forceinline__ void ldsm_x4(uint32_t* r, uint32_t addr) {
    asm volatile("ldmatrix.sync.aligned.m8n8.x4.shared.b16 {%0,%1,%2,%3}, [%4];"
        : "=r"(r[0]), "=r"(r[1]), "=r"(r[2]), "=r"(r[3]) : "r"(addr));
}
__device__ __forceinline__ void mma16816(float* d, const uint32_t* a, const uint32_t* b) {
    asm volatile("mma.sync.aligned.m16n8k16.row.col.f32.f16.f16.f32 "
        "{%0,%1,%2,%3}, {%4,%5,%6,%7}, {%8,%9}, {%0,%1,%2,%3};"
        : "+f"(d[0]), "+f"(d[1]), "+f"(d[2]), "+f"(d[3])
        : "r"(a[0]), "r"(a[1]), "r"(a[2]), "r"(a[3]), "r"(b[0]), "r"(b[1]));
}
__device__ __forceinline__ void cpa16(uint32_t dst, const void* src, uint32_t sz) {
    asm volatile("cp.async.cg.shared.global [%0], [%1], 16, %2;\n" :: "r"(dst), "l"(src), "r"(sz));
}
#define CP_COMMIT() asm volatile("cp.async.commit_group;\n" ::: "memory")
#define CP_WAIT1()  asm volatile("cp.async.wait_group 1;\n" ::: "memory")
#define CP_WAIT0()  asm volatile("cp.async.wait_group 0;\n" ::: "memory")

// ---- split / transpose: NCHW fp32 -> [b][p][ci] fp16 hi/lo ----
__global__ void split_k(const float* __restrict__ src, __half* __restrict__ xhi,
                        __half* __restrict__ xlo, int Cn, int cibase)
{
    __shared__ float tile[32][33];
    int bz = blockIdx.z, c0 = blockIdx.x * 32, p0 = blockIdx.y * 32;
    int tx = threadIdx.x, ty = threadIdx.y;
#pragma unroll
    for (int i = 0; i < 32; i += 8)
        tile[ty + i][tx] = src[((size_t)bz * Cn + c0 + ty + i) * 4096 + p0 + tx];
    __syncthreads();
#pragma unroll
    for (int i = 0; i < 32; i += 8) {
        float v = tile[tx][ty + i];
        __half h = __float2half_rn(v);
        size_t o = ((size_t)bz * 4096 + p0 + ty + i) * 1024 + cibase + c0 + tx;
        xhi[o] = h;
        xlo[o] = __float2half_rn(v - __half2float(h));
    }
}

// OIHW fp32 -> [co][tap][ci] fp16 (hi only)
__global__ void wsplit_k(const float* __restrict__ w, __half* __restrict__ whi,
                         int Cin, int taps, size_t total)
{
    size_t i = (size_t)blockIdx.x * 256 + threadIdx.x;
    if (i >= total) return;
    int tap = (int)(i % taps);
    size_t t2 = i / taps;
    int ci = (int)(t2 % Cin);
    int co = (int)(t2 / Cin);
    size_t dst = ((size_t)co * taps + tap) * Cin + ci;
    whi[dst] = __float2half_rn(w[i]);
}

// ================= fusion conv3x3 (1024->512): B-halo reuse + 1-term fp16 ==========
// CTA: 128 co x 128 px. A (W-hi) double-buffered per (ci,tap); B haloed hi-only tile
// (4 h-rows x 66 w) per ci-chunk serves all 9 taps.
#define FA_ST 18432            // A stage: 128 rows x 144B
#define FB0   36864            // B stages start (= 2*FA_ST)
#define FB_ST 38016            // B stage: 264 rows x 144B (hi only)
#define FUS_SMEM 112896        // 2*FA_ST + 2*FB_ST

__device__ __forceinline__ void fus_loadA(uint32_t sb, int t,
    const __half* __restrict__ whi, int co0, int c)
{
    int cik = c / 9, tap = c - cik * 9, ci0 = cik * 64;
#pragma unroll
    for (int i = 0; i < 4; i++) {          // 128 rows x 8 segs
        int idx = t + i * 256;
        int row = idx >> 3, seg = idx & 7;
        const __half* src = whi + ((size_t)(co0 + row) * 9 + tap) * 1024 + ci0 + seg * 8;
        cpa16(sb + row * 144 + seg * 16, src, 16u);
    }
}

__device__ __forceinline__ void fus_loadB(uint32_t sb, int t,
    const __half* __restrict__ xhi, int b, int h0, int cik)
{
    int ci0 = cik * 64;
    for (int idx = t; idx < 2112; idx += 256) {     // 264 rows x 8 segs (hi only)
        int row = idx >> 3, seg = idx & 7;
        int hrel = row / 66, wrel = row - hrel * 66;
        int h = h0 - 1 + hrel, w = wrel - 1;
        bool ok = ((unsigned)h < 64u) && ((unsigned)w < 64u);
        const __half* src = xhi
            + ((size_t)(b * 4096 + (ok ? h * 64 + w : 0))) * 1024 + ci0 + seg * 8;
        cpa16(sb + row * 144 + seg * 16, src, ok ? 16u : 0u);
    }
}

__global__ __launch_bounds__(256) void fus_mm(
    const __half* __restrict__ whi, const __half* __restrict__ xhi,
    const float* __restrict__ bias, float* __restrict__ out)
{
    extern __shared__ char dynsmem[];
    const int b = blockIdx.x >> 5;
    const int pbase = (blockIdx.x & 31) * 128;
    const int h0 = pbase >> 6;
    const int co0 = blockIdx.y * 128;
    const int t = threadIdx.x, lane = t & 31, warp = t >> 5;
    const int wm = warp & 1, wn = warp >> 1;
    const uint32_t sb = smem_u32(dynsmem);

    float acc[4][4][4];
#pragma unroll
    for (int fm = 0; fm < 4; fm++)
#pragma unroll
        for (int fn = 0; fn < 4; fn++)
#pragma unroll
            for (int k = 0; k < 4; k++) acc[fm][fn][k] = 0.f;

    // prologue: B(ci0)+A0 | A1
    fus_loadB(sb + FB0, t, xhi, b, h0, 0);
    fus_loadA(sb, t, whi, co0, 0);
    CP_COMMIT();
    fus_loadA(sb + FA_ST, t, whi, co0, 1);
    CP_COMMIT();

    const int arow = wm * 64 + (lane & 15);
    const int akoff = (lane >> 4) * 16;
    const int l8 = lane & 7, grp = lane >> 3;
    const int bprel = wn * 32 + l8 + (grp >> 1) * 8;
    const int bkoff = (grp & 1) * 16;
    const int bhw = (bprel >> 6) * 66 + (bprel & 63);

    for (int c = 0; c < 144; c++) {
        if (c == 143) { CP_WAIT0(); } else { CP_WAIT1(); }
        __syncthreads();
        const int cik = c / 9, tap = c - cik * 9;
        const int tapoff = (tap / 3) * 66 + (tap % 3);
        const uint32_t Ast = sb + (c & 1) * FA_ST;
        const uint32_t Bst = sb + FB0 + (cik & 1) * FB_ST;
        const uint32_t abase = Ast + arow * 144 + akoff;
        const uint32_t bbase = Bst + (bhw + tapoff) * 144 + bkoff;
#pragma unroll
        for (int ks = 0; ks < 4; ks++) {
            const int kb = ks * 32;
            uint32_t ah[4][4];
#pragma unroll
            for (int fm = 0; fm < 4; fm++)
                ldsm_x4(ah[fm], abase + fm * 16 * 144 + kb);
            uint32_t bh[4][2];
#pragma unroll
            for (int fp = 0; fp < 2; fp++) {
                uint32_t r[4];
                ldsm_x4(r, bbase + fp * 16 * 144 + kb);
                bh[fp*2][0] = r[0]; bh[fp*2][1] = r[1];
                bh[fp*2+1][0] = r[2]; bh[fp*2+1][1] = r[3];
            }
#pragma unroll
            for (int fm = 0; fm < 4; fm++)
#pragma unroll
                for (int fn = 0; fn < 4; fn++)
                    mma16816(acc[fm][fn], ah[fm], bh[fn]);
        }
        __syncthreads();
        if (c + 2 < 144)
            fus_loadA(Ast, t, whi, co0, c + 2);
        if (tap == 0 && cik + 1 < 16)
            fus_loadB(sb + FB0 + ((cik + 1) & 1) * FB_ST, t, xhi, b, h0, cik + 1);
        CP_COMMIT();
    }

    const int r0 = lane >> 2, c0 = (lane & 3) * 2;
#pragma unroll
    for (int fm = 0; fm < 4; fm++) {
        int co = co0 + wm * 64 + fm * 16 + r0;
        float bv0 = bias[co], bv8 = bias[co + 8];
        float* op0 = out + ((size_t)b * 512 + co) * 4096 + pbase;
        float* op8 = op0 + (size_t)8 * 4096;
#pragma unroll
        for (int fn = 0; fn < 4; fn++) {
            int p = wn * 32 + fn * 8 + c0;
            *(float2*)(op0 + p) = make_float2(acc[fm][fn][0] + bv0, acc[fm][fn][1] + bv0);
            *(float2*)(op8 + p) = make_float2(acc[fm][fn][2] + bv8, acc[fm][fn][3] + bv8);
        }
    }
}

// ---- generic mma.sync implicit GEMM (qkv 1x1, box conv), 2-term fp16 ----
// D = Wh*Xh + Wh*Xl  (A-lo never loaded)
template<int TAPS, int COUTV, int ROWSA, int ROWSB>
__device__ __forceinline__ void mm_load(uint32_t sb, int t,
    const __half* __restrict__ whi,
    const __half* __restrict__ xhi, const __half* __restrict__ xlo,
    int co0, int WCin, int b, int pbase, int c)
{
    const int B_HI_ = ROWSA * 144;           // A hi only, then B hi, B lo
    const int B_LO_D = ROWSB * 144;
    int cik = c / TAPS, tap = c - cik * TAPS;
    int dh = (TAPS == 9) ? tap / 3 - 1 : 0;
    int dw = (TAPS == 9) ? tap % 3 - 1 : 0;
    int ci0 = cik * 64;
#pragma unroll
    for (int i = 0; i < ROWSA / 32; i++) {   // A hi: ROWSA rows x 8 segs
        int idx = t + i * 256;
        int row = idx >> 3, seg = idx & 7;
        int rr = (COUTV < ROWSA && row >= COUTV) ? 0 : row;
        const __half* src = whi
            + ((size_t)(co0 + rr) * TAPS + tap) * WCin + ci0 + seg * 8;
        cpa16(sb + row * 144 + seg * 16, src,
              (COUTV < ROWSA && row >= COUTV) ? 0u : 16u);
    }
#pragma unroll
    for (int i = 0; i < ROWSB / 16; i++) {   // B: 2(hl) x ROWSB rows x 8 segs
        int idx = t + i * 256;
        int hl = idx / (ROWSB * 8), rem = idx % (ROWSB * 8), row = rem >> 3, seg = rem & 7;
        int p = pbase + row;
        int ih = (p >> 6) + dh, iw = (p & 63) + dw;
        bool ok = (TAPS == 1) || (((unsigned)ih < 64u) && ((unsigned)iw < 64u));
        const __half* src = (hl ? xlo : xhi)
            + ((size_t)(b * 4096 + (ok ? ih * 64 + iw : 0))) * 1024 + ci0 + seg * 8;
        cpa16(sb + B_HI_ + hl * B_LO_D + row * 144 + seg * 16, src, ok ? 16u : 0u);
    }
}

template<int TAPS, int ACT, int COUTV, int ROWSA, int ROWSB>
__global__ __launch_bounds__(256) void mma_mm(
    const __half* __restrict__ whi,
    const __half* __restrict__ xhi, const __half* __restrict__ xlo,
    const float* __restrict__ bias, float* __restrict__ out, int WCin, int Cout)
{
    extern __shared__ char dynsmem[];
    const int B_HI_ = ROWSA * 144;
    const int B_LO_D = ROWSB * 144;
    const int MSTAGE_ = (ROWSA + 2 * ROWSB) * 144;
    const int NPT = 4096 / ROWSB;
    const int b = blockIdx.x / NPT;
    const int pbase = (blockIdx.x % NPT) * ROWSB;
    const int co0 = blockIdx.y * ROWSA;
    const int t = threadIdx.x, lane = t & 31, warp = t >> 5;
    const int wm = (ROWSA == 128) ? (warp & 1) : 0;
    const int wn = (ROWSA == 128) ? (warp >> 1) : warp;
    const uint32_t sb0 = smem_u32(dynsmem);
    const int NCH = (WCin / 64) * TAPS;

    float acc[4][4][4];
#pragma unroll
    for (int fm = 0; fm < 4; fm++)
#pragma unroll
        for (int fn = 0; fn < 4; fn++)
#pragma unroll
            for (int k = 0; k < 4; k++) acc[fm][fn][k] = 0.f;

    mm_load<TAPS, COUTV, ROWSA, ROWSB>(sb0, t, whi, xhi, xlo, co0, WCin, b, pbase, 0); CP_COMMIT();
    mm_load<TAPS, COUTV, ROWSA, ROWSB>(sb0 + MSTAGE_, t, whi, xhi, xlo, co0, WCin, b, pbase, 1); CP_COMMIT();

    const int arow = wm * 64 + (lane & 15);
    const int akoff = (lane >> 4) * 16;
    const int l8 = lane & 7, grp = lane >> 3;
    const int brow = wn * 32 + l8 + (grp >> 1) * 8;
    const int bkoff = (grp & 1) * 16;

    for (int c = 0; c < NCH; c++) {
        const uint32_t sb = sb0 + (c & 1) * MSTAGE_;
        if (c == NCH - 1) { CP_WAIT0(); } else { CP_WAIT1(); }
        __syncthreads();
        const uint32_t abase = sb + arow * 144 + akoff;
        const uint32_t bbase = sb + B_HI_ + brow * 144 + bkoff;
#pragma unroll
        for (int ks = 0; ks < 4; ks++) {
            const int kb = ks * 32;
            uint32_t ah[4][4];
#pragma unroll
            for (int fm = 0; fm < 4; fm++)
                ldsm_x4(ah[fm], abase + fm * 16 * 144 + kb);
            uint32_t bh[4][2], bl[4][2];
#pragma unroll
            for (int fp = 0; fp < 2; fp++) {
                uint32_t r[4];
                uint32_t addr = bbase + fp * 16 * 144 + kb;
                ldsm_x4(r, addr);
                bh[fp*2][0] = r[0]; bh[fp*2][1] = r[1];
                bh[fp*2+1][0] = r[2]; bh[fp*2+1][1] = r[3];
                ldsm_x4(r, addr + B_LO_D);
                bl[fp*2][0] = r[0]; bl[fp*2][1] = r[1];
                bl[fp*2+1][0] = r[2]; bl[fp*2+1][1] = r[3];
            }
#pragma unroll
            for (int fm = 0; fm < 4; fm++)
#pragma unroll
                for (int fn = 0; fn < 4; fn++) {
                    mma16816(acc[fm][fn], ah[fm], bh[fn]);
                    mma16816(acc[fm][fn], ah[fm], bl[fn]);
                }
        }
        __syncthreads();
        if (c + 2 < NCH) {
            mm_load<TAPS, COUTV, ROWSA, ROWSB>(sb, t, whi, xhi, xlo, co0, WCin, b, pbase, c + 2);
            CP_COMMIT();
        }
    }

    const int r0 = lane >> 2, c0 = (lane & 3) * 2;
#pragma unroll
    for (int fm = 0; fm < 4; fm++) {
        int co = co0 + wm * 64 + fm * 16 + r0;
        bool v0ok = (COUTV >= ROWSA) || (co < COUTV);
        bool v8ok = (COUTV >= ROWSA) || (co + 8 < COUTV);
        float bv0 = v0ok ? bias[co] : 0.f;
        float bv8 = v8ok ? bias[co + 8] : 0.f;
        float* op0 = out + ((size_t)b * Cout + co) * 4096 + pbase;
        float* op8 = op0 + (size_t)8 * 4096;
#pragma unroll
        for (int fn = 0; fn < 4; fn++) {
            int p = wn * 32 + fn * 8 + c0;
            float a0 = acc[fm][fn][0] + bv0, a1 = acc[fm][fn][1] + bv0;
            float a2 = acc[fm][fn][2] + bv8, a3 = acc[fm][fn][3] + bv8;
            if (ACT == 1) { a0 = geluf(a0); a1 = geluf(a1); a2 = geluf(a2); a3 = geluf(a3); }
            if (v0ok) *(float2*)(op0 + p) = make_float2(a0, a1);
            if (v8ok) *(float2*)(op8 + p) = make_float2(a2, a3);
        }
    }
}

// ---- attention QK logits via mma (3-term fp16) ----
__global__ __launch_bounds__(128) void attn_qk_mma(
    const float* __restrict__ qkv, const float* __restrict__ edge, float* __restrict__ attn)
{
    int id = blockIdx.x;
    int i = id & 63, h = (id >> 6) & 7, b = id >> 9;
    const float* Q = qkv + ((size_t)(b * 1536 + h * 64 + i)) * PP;
    const float* K = qkv + ((size_t)(b * 1536 + 512 + h * 64 + i)) * PP;
    __shared__ __half sQh[64*72], sQl[64*72], sKh[64*72], sKl[64*72];
    int t = threadIdx.x, lane = t & 31, warp = t >> 5;
    int wm = warp & 1, wn = warp >> 1;
    for (int idx = t; idx < 4096; idx += 128) {
        int y = idx >> 6, c = idx & 63;
        float q = Q[idx];
        __half qh = __float2half_rn(q);
        sQh[c*72 + y] = qh; sQl[c*72 + y] = __float2half_rn(q - __half2float(qh));
        float k = K[idx];
        __half kh = __float2half_rn(k);
        sKh[c*72 + y] = kh; sKl[c*72 + y] = __float2half_rn(k - __half2float(kh));
    }
    __syncthreads();
    float acc[2][4][4];
#pragma unroll
    for (int fm = 0; fm < 2; fm++)
#pragma unroll
        for (int fn = 0; fn < 4; fn++)
#pragma unroll
            for (int k = 0; k < 4; k++) acc[fm][fn][k] = 0.f;

    const uint32_t aQh = smem_u32(sQh), aQl = smem_u32(sQl);
    const uint32_t aKh = smem_u32(sKh), aKl = smem_u32(sKl);
    const int arow = wm * 32 + (lane & 15), akoff = (lane >> 4) * 16;
    const int l8 = lane & 7, grp = lane >> 3;
    const int brow = wn * 32 + l8 + (grp >> 1) * 8, bkoff = (grp & 1) * 16;
#pragma unroll
    for (int ks = 0; ks < 4; ks++) {
        const int kb = ks * 32;
        uint32_t ah[2][4], al[2][4];
#pragma unroll
        for (int fm = 0; fm < 2; fm++) {
            ldsm_x4(ah[fm], aQh + (arow + fm*16) * 144 + akoff + kb);
            ldsm_x4(al[fm], aQl + (arow + fm*16) * 144 + akoff + kb);
        }
        uint32_t bh[4][2], bl[4][2];
#pragma unroll
        for (int fp = 0; fp < 2; fp++) {
            uint32_t r[4];
            ldsm_x4(r, aKh + (brow + fp*16) * 144 + bkoff + kb);
            bh[fp*2][0] = r[0]; bh[fp*2][1] = r[1];
            bh[fp*2+1][0] = r[2]; bh[fp*2+1][1] = r[3];
            ldsm_x4(r, aKl + (brow + fp*16) * 144 + bkoff + kb);
            bl[fp*2][0] = r[0]; bl[fp*2][1] = r[1];
            bl[fp*2+1][0] = r[2]; bl[fp*2+1][1] = r[3];
        }
#pragma unroll
        for (int fm = 0; fm < 2; fm++)
#pragma unroll
            for (int fn = 0; fn < 4; fn++) {
                mma16816(acc[fm][fn], ah[fm], bh[fn]);
                mma16816(acc[fm][fn], ah[fm], bl[fn]);
                mma16816(acc[fm][fn], al[fm], bh[fn]);
            }
    }
    const int r0 = lane >> 2, c0 = (lane & 3) * 2;
    float* op = attn + (size_t)id * 4096;
    const float* ep = edge + (size_t)id * 64;
#pragma unroll
    for (int fm = 0; fm < 2; fm++) {
        int w0 = wm * 32 + fm * 16 + r0;
        float e0 = ep[w0], e8 = ep[w0 + 8];
#pragma unroll
        for (int fn = 0; fn < 4; fn++) {
            int Wp = wn * 32 + fn * 8 + c0;
            op[w0*64 + Wp]       = acc[fm][fn][0] * 0.125f + e0;
            op[w0*64 + Wp + 1]   = acc[fm][fn][1] * 0.125f + e0;
            op[(w0+8)*64 + Wp]   = acc[fm][fn][2] * 0.125f + e8;
            op[(w0+8)*64 + Wp+1] = acc[fm][fn][3] * 0.125f + e8;
        }
    }
}

// ---- attention AV via mma (3-term fp16) ----
__global__ __launch_bounds__(128) void attn_av_mma(
    const float* __restrict__ qkv, const float* __restrict__ attn, float* __restrict__ agg)
{
    int id = blockIdx.x;
    int i = id & 63, h = (id >> 6) & 7, b = id >> 9;
    const float* V = qkv + ((size_t)(b * 1536 + 1024 + h * 64 + i)) * PP;
    const float* A = attn + (size_t)id * 4096;
    __shared__ __half sVh[64*72], sVl[64*72], sAh[64*72], sAl[64*72];
    int t = threadIdx.x, lane = t & 31, warp = t >> 5;
    int wm = warp & 1, wn = warp >> 1;
    for (int idx = t; idx < 4096; idx += 128) {
        int r = idx >> 6, c = idx & 63;
        float v = V[idx];
        __half vh = __float2half_rn(v);
        sVh[r*72 + c] = vh; sVl[r*72 + c] = __float2half_rn(v - __half2float(vh));
        float a = A[idx];
        __half ahv = __float2half_rn(a);
        sAh[r*72 + c] = ahv; sAl[r*72 + c] = __float2half_rn(a - __half2float(ahv));
    }
    __syncthreads();
    float acc[2][4][4];
#pragma unroll
    for (int fm = 0; fm < 2; fm++)
#pragma unroll
        for (int fn = 0; fn < 4; fn++)
#pragma unroll
            for (int k = 0; k < 4; k++) acc[fm][fn][k] = 0.f;

    const uint32_t aVh = smem_u32(sVh), aVl = smem_u32(sVl);
    const uint32_t aAh = smem_u32(sAh), aAl = smem_u32(sAl);
    const int arow = wm * 32 + (lane & 15), akoff = (lane >> 4) * 16;
    const int l8 = lane & 7, grp = lane >> 3;
    const int brow = wn * 32 + l8 + (grp >> 1) * 8, bkoff = (grp & 1) * 16;
#pragma unroll
    for (int ks = 0; ks < 4; ks++) {
        const int kb = ks * 32;
        uint32_t ah[2][4], al[2][4];
#pragma unroll
        for (int fm = 0; fm < 2; fm++) {
            ldsm_x4(ah[fm], aVh + (arow + fm*16) * 144 + akoff + kb);
            ldsm_x4(al[fm], aVl + (arow + fm*16) * 144 + akoff + kb);
        }
        uint32_t bh[4][2], bl[4][2];
#pragma unroll
        for (int fp = 0; fp < 2; fp++) {
            uint32_t r[4];
            ldsm_x4(r, aAh + (brow + fp*16) * 144 + bkoff + kb);
            bh[fp*2][0] = r[0]; bh[fp*2][1] = r[1];
            bh[fp*2+1][0] = r[2]; bh[fp*2+1][1] = r[3];
            ldsm_x4(r, aAl + (brow + fp*16) * 144 + bkoff + kb);
            bl[fp*2][0] = r[0]; bl[fp*2][1] = r[1];
            bl[fp*2+1][0] = r[2]; bl[fp*2+1][1] = r[3];
        }
#pragma unroll
        for (int fm = 0; fm < 2; fm++)
#pragma unroll
            for (int fn = 0; fn < 4; fn++) {
                mma16816(acc[fm][fn], ah[fm], bh[fn]);
                mma16816(acc[fm][fn], ah[fm], bl[fn]);
                mma16816(acc[fm][fn], al[fm], bh[fn]);
            }
    }
    const int r0 = lane >> 2, c0 = (lane & 3) * 2;
    float* op = agg + ((size_t)(b * 512 + h * 64 + i)) * PP;
#pragma unroll
    for (int fm = 0; fm < 2; fm++) {
        int d0 = wm * 32 + fm * 16 + r0;
#pragma unroll
        for (int fn = 0; fn < 4; fn++) {
            int w = wn * 32 + fn * 8 + c0;
            op[d0*64 + w]       = acc[fm][fn][0];
            op[d0*64 + w + 1]   = acc[fm][fn][1];
            op[(d0+8)*64 + w]   = acc[fm][fn][2];
            op[(d0+8)*64 + w+1] = acc[fm][fn][3];
        }
    }
}

// ---- FFMA 3x3 conv (edge net: Cin=4 -> 64 only) ----
#define CI_CHUNK 8
template<int ACT>
__global__ __launch_bounds__(128) void conv3x3_k(
    const float* __restrict__ in1, int Cin,
    const float* __restrict__ wgt, const float* __restrict__ bias,
    float* __restrict__ out, int Cout)
{
    const int bh = blockIdx.x, b = bh >> 6, h = bh & 63;
    const int co0 = blockIdx.y * 64;
    const int t = threadIdx.x, tx = t & 7, ty = t >> 3;
    __shared__ float sIn[CI_CHUNK][3][66];
    __shared__ float sW[64][CI_CHUNK * 9];
    float acc[4][8];
#pragma unroll
    for (int a = 0; a < 4; a++)
#pragma unroll
        for (int j = 0; j < 8; j++) acc[a][j] = 0.f;

    for (int cb = 0; cb < Cin; cb += CI_CHUNK) {
        __syncthreads();
        for (int idx = t; idx < CI_CHUNK * 3 * 66; idx += 128) {
            int ci = idx / 198, rem = idx - ci * 198, r = rem / 66, col = rem - r * 66;
            int cg = cb + ci;
            float v = 0.f;
            int gh = h - 1 + r, gw = col - 1;
            if (cg < Cin && (unsigned)gh < 64u && (unsigned)gw < 64u)
                v = in1[((size_t)(b * Cin + cg)) * PP + gh * 64 + gw];
            sIn[ci][r][col] = v;
        }
        for (int idx = t; idx < 64 * CI_CHUNK * 9; idx += 128) {
            int co = idx / (CI_CHUNK * 9), rem = idx - co * (CI_CHUNK * 9);
            int ci = rem / 9, kk = rem - ci * 9, cg = cb + ci;
            sW[co][ci * 9 + kk] = (cg < Cin) ? wgt[((size_t)(co0 + co) * Cin + cg) * 9 + kk] : 0.f;
        }
        __syncthreads();
#pragma unroll 2
        for (int ci = 0; ci < CI_CHUNK; ci++) {
#pragma unroll
            for (int r = 0; r < 3; r++) {
                float iv[10];
#pragma unroll
                for (int j = 0; j < 10; j++) iv[j] = sIn[ci][r][tx * 8 + j];
#pragma unroll
                for (int cj = 0; cj < 4; cj++) {
                    float w0 = sW[ty * 4 + cj][ci * 9 + r * 3 + 0];
                    float w1 = sW[ty * 4 + cj][ci * 9 + r * 3 + 1];
                    float w2 = sW[ty * 4 + cj][ci * 9 + r * 3 + 2];
#pragma unroll
                    for (int wj = 0; wj < 8; wj++) {
                        acc[cj][wj] = fmaf(w0, iv[wj + 0], acc[cj][wj]);
                        acc[cj][wj] = fmaf(w1, iv[wj + 1], acc[cj][wj]);
                        acc[cj][wj] = fmaf(w2, iv[wj + 2], acc[cj][wj]);
                    }
                }
            }
        }
    }
#pragma unroll
    for (int cj = 0; cj < 4; cj++) {
        int co = co0 + ty * 4 + cj;
        float bv = bias[co];
#pragma unroll
        for (int wj = 0; wj < 8; wj++) {
            float v = acc[cj][wj] + bv;
            if (ACT == 1) v = geluf(v);
            out[(((size_t)b * Cout + co) * 64 + h) * 64 + tx * 8 + wj] = v;
        }
    }
}

template<int ACT>
__global__ void conv1x1_small_k(const float* __restrict__ in, const float* __restrict__ wgt,
                                const float* __restrict__ bias, float* __restrict__ out,
                                int Cin, int Cout)
{
    int bc = blockIdx.x, b = bc / Cout, co = bc - b * Cout;
    int p = blockIdx.y * 256 + threadIdx.x;
    float acc = bias[co];
    const float* ip = in + (size_t)b * Cin * PP + p;
    const float* wp = wgt + (size_t)co * Cin;
    for (int ci = 0; ci < Cin; ci++)
        acc = fmaf(wp[ci], ip[(size_t)ci * PP], acc);
    if (ACT == 2) acc = sigm(acc);
    out[((size_t)b * Cout + co) * PP + p] = acc;
}

// ---- GroupNorm ----
__global__ void gn_stats_k(const float* __restrict__ x, float* __restrict__ stats)
{
    int bg = blockIdx.x, b = bg >> 3, g = bg & 7;
    const float* p = x + ((size_t)b * 64 + g * 8) * PP;
    float s = 0.f, s2 = 0.f;
    for (int i = threadIdx.x; i < 8 * PP; i += 256) {
        float v = p[i]; s += v; s2 += v * v;
    }
    __shared__ float rs[8], rs2[8];
#pragma unroll
    for (int o = 16; o > 0; o >>= 1) {
        s += __shfl_down_sync(0xffffffffu, s, o);
        s2 += __shfl_down_sync(0xffffffffu, s2, o);
    }
    int w = threadIdx.x >> 5, l = threadIdx.x & 31;
    if (l == 0) { rs[w] = s; rs2[w] = s2; }
    __syncthreads();
    if (w == 0) {
        s = (l < 8) ? rs[l] : 0.f; s2 = (l < 8) ? rs2[l] : 0.f;
#pragma unroll
        for (int o = 4; o > 0; o >>= 1) {
            s += __shfl_down_sync(0xffffffffu, s, o);
            s2 += __shfl_down_sync(0xffffffffu, s2, o);
        }
        if (l == 0) {
            float m = s / 32768.f;
            stats[bg * 2] = m;
            stats[bg * 2 + 1] = s2 / 32768.f - m * m;
        }
    }
}

__global__ void gn_apply_k(float* __restrict__ x, const float* __restrict__ stats,
                           const float* __restrict__ gamma, const float* __restrict__ beta)
{
    size_t idx = (size_t)blockIdx.x * 256 + threadIdx.x;
    int c = (int)((idx >> 12) & 63);
    int b = (int)(idx >> 18);
    int bg = b * 8 + (c >> 3);
    float m = stats[bg * 2], v = stats[bg * 2 + 1];
    float xn = (x[idx] - m) * rsqrtf(v + 1e-5f) * gamma[c] + beta[c];
    x[idx] = geluf(xn);
}

// ---- softmax over i ----
__global__ __launch_bounds__(128) void softmax_i_k(float* __restrict__ attn)
{
    int n = blockIdx.x * 128 + threadIdx.x;
    int bh = n >> 12, ww = n & 4095;
    float* p = attn + (size_t)bh * 262144 + ww;
    float x[64], mx = -1e30f;
#pragma unroll
    for (int i = 0; i < 64; i++) { x[i] = p[(size_t)i * 4096]; mx = fmaxf(mx, x[i]); }
    float s = 0.f;
#pragma unroll
    for (int i = 0; i < 64; i++) { x[i] = __expf(x[i] - mx); s += x[i]; }
    float inv = 1.f / s;
#pragma unroll
    for (int i = 0; i < 64; i++) p[(size_t)i * 4096] = x[i] * inv;
}

// ---- BatchNorm ----
__global__ void bn_stats_k(const float* __restrict__ y, float* __restrict__ stats)
{
    int c = blockIdx.x;
    float s = 0.f, s2 = 0.f;
    for (int n = threadIdx.x; n < 32768; n += 256) {
        int b = n >> 12, p = n & 4095;
        float v = y[((size_t)b * CC + c) * PP + p];
        s += v; s2 += v * v;
    }
    __shared__ float rs[8], rs2[8];
#pragma unroll
    for (int o = 16; o > 0; o >>= 1) {
        s += __shfl_down_sync(0xffffffffu, s, o);
        s2 += __shfl_down_sync(0xffffffffu, s2, o);
    }
    int w = threadIdx.x >> 5, l = threadIdx.x & 31;
    if (l == 0) { rs[w] = s; rs2[w] = s2; }
    __syncthreads();
    if (w == 0) {
        s = (l < 8) ? rs[l] : 0.f; s2 = (l < 8) ? rs2[l] : 0.f;
#pragma unroll
        for (int o = 4; o > 0; o >>= 1) {
            s += __shfl_down_sync(0xffffffffu, s, o);
            s2 += __shfl_down_sync(0xffffffffu, s2, o);
        }
        if (l == 0) {
            float m = s / 32768.f;
            stats[c * 2] = m;
            stats[c * 2 + 1] = s2 / 32768.f - m * m;
        }
    }
}

__global__ void bn_apply_k(const float* __restrict__ y, const float* __restrict__ stats,
                           const float* __restrict__ g, const float* __restrict__ bt,
                           float* __restrict__ out)
{
    size_t idx = (size_t)blockIdx.x * 256 + threadIdx.x;
    int c = (int)((idx >> 12) & 511);
    float m = stats[c * 2], v = stats[c * 2 + 1];
    float yn = (y[idx] - m) * rsqrtf(v + 1e-5f) * g[c] + bt[c];
    out[idx] = yn * (1.f / (1.f + __expf(-yn)));
}

// ---- launch ----
extern "C" void kernel_launch(void* const* d_in, const int* in_sizes, int n_in,
                              void* d_out, int out_size)
{
    const float* x       = (const float*)d_in[0];
    const float* box_w1  = (const float*)d_in[1];
    const float* box_b1  = (const float*)d_in[2];
    const float* box_w2  = (const float*)d_in[3];
    const float* box_b2  = (const float*)d_in[4];
    const float* edge_w1 = (const float*)d_in[5];
    const float* edge_b1 = (const float*)d_in[6];
    const float* gn_g    = (const float*)d_in[7];
    const float* gn_b    = (const float*)d_in[8];
    const float* edge_w2 = (const float*)d_in[9];
    const float* edge_b2 = (const float*)d_in[10];
    const float* qkv_w   = (const float*)d_in[11];
    const float* qkv_b   = (const float*)d_in[12];
    const float* fus_w   = (const float*)d_in[13];
    const float* fus_b   = (const float*)d_in[14];
    const float* bn_g    = (const float*)d_in[15];
    const float* bn_b    = (const float*)d_in[16];
    float* out = (float*)d_out;

    float *box1, *boxes, *edge1, *edge, *qkv, *attn, *agg, *y, *gnst, *bnst;
    __half *xhi, *xlo, *wfhi, *wbhi, *wqhi;
    cudaGetSymbolAddress((void**)&box1,  g_box1);
    cudaGetSymbolAddress((void**)&boxes, g_boxes);
    cudaGetSymbolAddress((void**)&edge1, g_edge1);
    cudaGetSymbolAddress((void**)&edge,  g_edge);
    cudaGetSymbolAddress((void**)&qkv,   g_qkv);
    cudaGetSymbolAddress((void**)&attn,  g_attn);
    cudaGetSymbolAddress((void**)&agg,   g_agg);
    cudaGetSymbolAddress((void**)&y,     g_y);
    cudaGetSymbolAddress((void**)&gnst,  g_gnstats);
    cudaGetSymbolAddress((void**)&bnst,  g_bnstats);
    cudaGetSymbolAddress((void**)&xhi,   g_xhi);
    cudaGetSymbolAddress((void**)&xlo,   g_xlo);
    cudaGetSymbolAddress((void**)&wfhi,  g_wfhi);
    cudaGetSymbolAddress((void**)&wbhi,  g_wbhi);
    cudaGetSymbolAddress((void**)&wqhi,  g_wqhi);

    cudaFuncSetAttribute((const void*)mma_mm<1, 0, 128, 128, 128>, cudaFuncAttributeMaxDynamicSharedMemorySize, 2 * (128 + 2 * 128) * 144);
    cudaFuncSetAttribute((const void*)mma_mm<9, 1, 64, 64, 256>,   cudaFuncAttributeMaxDynamicSharedMemorySize, 2 * (64 + 2 * 256) * 144);
    cudaFuncSetAttribute((const void*)fus_mm, cudaFuncAttributeMaxDynamicSharedMemorySize, FUS_SMEM);

    // preprocessing (fp16 splits; weights hi-only)
    split_k<<<dim3(16, 128, 8), dim3(32, 8)>>>(x, xhi, xlo, 512, 0);
    wsplit_k<<<(512 * 1024 * 9 + 255) / 256, 256>>>(fus_w, wfhi, 1024, 9, (size_t)512 * 1024 * 9);
    wsplit_k<<<(64 * 512 * 9 + 255) / 256, 256>>>(box_w1, wbhi, 512, 9, (size_t)64 * 512 * 9);
    wsplit_k<<<(1536 * 512 + 255) / 256, 256>>>(qkv_w, wqhi, 512, 1, (size_t)1536 * 512);

    // box conv3x3(512->64)+GELU, M=64 x N=256 tiles (2-term)
    mma_mm<9, 1, 64, 64, 256><<<dim3(128, 1), 256, 2 * (64 + 2 * 256) * 144>>>(
        wbhi, xhi, xlo, box_b1, box1, 512, 64);

    // qkv 1x1 (512->1536) (2-term)
    mma_mm<1, 0, 128, 128, 128><<<dim3(256, 12), 256, 2 * (128 + 2 * 128) * 144>>>(
        wqhi, xhi, xlo, qkv_b, qkv, 512, 1536);

    // box tail + edge net
    conv1x1_small_k<2><<<dim3(32, 16), 256>>>(box1, box_w2, box_b2, boxes, 64, 4);
    conv3x3_k<0><<<dim3(512, 1), 128>>>(boxes, 4, edge_w1, edge_b1, edge1, 64);
    gn_stats_k<<<64, 256>>>(edge1, gnst);
    gn_apply_k<<<8192, 256>>>(edge1, gnst, gn_g, gn_b);
    conv1x1_small_k<0><<<dim3(64, 16), 256>>>(edge1, edge_w2, edge_b2, edge, 64, 8);

    // attention (tensor cores, 3-term)
    attn_qk_mma<<<4096, 128>>>(qkv, edge, attn);
    softmax_i_k<<<2048, 128>>>(attn);
    attn_av_mma<<<4096, 128>>>(qkv, attn, agg);

    // split agg into ci[512:1024) of the fp16 buffer
    split_k<<<dim3(16, 128, 8), dim3(32, 8)>>>(agg, xhi, xlo, 512, 512);

    // fusion conv3x3 (1024->512), B-halo reuse + 1-term fp16
    fus_mm<<<dim3(256, 4), 256, FUS_SMEM>>>(wfhi, xhi, fus_b, y);

    // batchnorm + SiLU
    bn_stats_k<<<512, 256>>>(y, bnst);
    bn_apply_k<<<65536, 256>>>(y, bnst, bn_g, bn_b, out);
}

// round 12
// speedup vs baseline: 9.9028x; 1.1745x over previous
#include <cuda_runtime.h>
#include <cuda_fp16.h>
#include <cstdint>
#include <math.h>

#define BB 8
#define CC 512
#define PP 4096
#define NHH 8

// ---- scratch (static device globals; no allocation) ----
__device__ float g_box1[BB*64*PP];
__device__ float g_boxes[BB*4*PP];
__device__ float g_edge1[BB*64*PP];
__device__ float g_edge[BB*NHH*PP];
__device__ float g_qkv[(size_t)BB*1536*PP];
__device__ float g_attn[(size_t)BB*NHH*64*64*64];
__device__ float g_agg[(size_t)BB*CC*PP];
__device__ float g_y[(size_t)BB*CC*PP];
__device__ float g_gnstats[BB*8*2];
__device__ float g_bnstats[CC*2];
__device__ __half g_xhi[(size_t)BB*PP*1024];   // [b][p][ci]  (hi only; 1-term everywhere)
__device__ __half g_wfhi[512*9*1024];          // [co][tap][ci]
__device__ __half g_wbhi[64*9*512];
__device__ __half g_wqhi[1536*512];

__device__ __forceinline__ float geluf(float x) {
    return 0.5f * x * (1.0f + erff(x * 0.70710678118654752440f));
}
__device__ __forceinline__ float sigm(float x) { return 1.0f / (1.0f + __expf(-x)); }

// ---- arch-neutral tensor-core helpers (sm_80+ PTX only) ----
__device__ __forceinline__ uint32_t smem_u32(const void* p) {
    uint32_t a;
    asm("{ .reg .u64 t; cvta.to.shared.u64 t, %1; cvt.u32.u64 %0, t; }" : "=r"(a) : "l"(p));
    return a;
}
__device__ __forceinline__ void ldsm_x4(uint32_t* r, uint32_t addr) {
    asm volatile("ldmatrix.sync.aligned.m8n8.x4.shared.b16 {%0,%1,%2,%3}, [%4];"
        : "=r"(r[0]), "=r"(r[1]), "=r"(r[2]), "=r"(r[3]) : "r"(addr));
}
__device__ __forceinline__ void mma16816(float* d, const uint32_t* a, const uint32_t* b) {
    asm volatile("mma.sync.aligned.m16n8k16.row.col.f32.f16.f16.f32 "
        "{%0,%1,%2,%3}, {%4,%5,%6,%7}, {%8,%9}, {%0,%1,%2,%3};"
        : "+f"(d[0]), "+f"(d[1]), "+f"(d[2]), "+f"(d[3])
        : "r"(a[0]), "r"(a[1]), "r"(a[2]), "r"(a[3]), "r"(b[0]), "r"(b[1]));
}
__device__ __forceinline__ void cpa16(uint32_t dst, const void* src, uint32_t sz) {
    asm volatile("cp.async.cg.shared.global [%0], [%1], 16, %2;\n" :: "r"(dst), "l"(src), "r"(sz));
}
#define CP_COMMIT() asm volatile("cp.async.commit_group;\n" ::: "memory")
#define CP_WAIT1()  asm volatile("cp.async.wait_group 1;\n" ::: "memory")
#define CP_WAIT0()  asm volatile("cp.async.wait_group 0;\n" ::: "memory")

// ---- convert / transpose: NCHW fp32 -> [b][p][ci] fp16 (hi only) ----
__global__ void split_k(const float* __restrict__ src, __half* __restrict__ xhi,
                        int Cn, int cibase)
{
    __shared__ float tile[32][33];
    int bz = blockIdx.z, c0 = blockIdx.x * 32, p0 = blockIdx.y * 32;
    int tx = threadIdx.x, ty = threadIdx.y;
#pragma unroll
    for (int i = 0; i < 32; i += 8)
        tile[ty + i][tx] = src[((size_t)bz * Cn + c0 + ty + i) * 4096 + p0 + tx];
    __syncthreads();
#pragma unroll
    for (int i = 0; i < 32; i += 8) {
        size_t o = ((size_t)bz * 4096 + p0 + ty + i) * 1024 + cibase + c0 + tx;
        xhi[o] = __float2half_rn(tile[tx][ty + i]);
    }
}

// OIHW fp32 -> [co][tap][ci] fp16
__global__ void wsplit_k(const float* __restrict__ w, __half* __restrict__ whi,
                         int Cin, int taps, size_t total)
{
    size_t i = (size_t)blockIdx.x * 256 + threadIdx.x;
    if (i >= total) return;
    int tap = (int)(i % taps);
    size_t t2 = i / taps;
    int ci = (int)(t2 % Cin);
    int co = (int)(t2 / Cin);
    whi[((size_t)co * taps + tap) * Cin + ci] = __float2half_rn(w[i]);
}

// ================= fusion conv3x3 (1024->512): B-halo reuse + 1-term fp16 ==========
#define FA_ST 18432            // A stage: 128 rows x 144B
#define FB0   36864
#define FB_ST 38016            // B stage: 264 rows x 144B
#define FUS_SMEM 112896

__device__ __forceinline__ void fus_loadA(uint32_t sb, int t,
    const __half* __restrict__ whi, int co0, int c)
{
    int cik = c / 9, tap = c - cik * 9, ci0 = cik * 64;
#pragma unroll
    for (int i = 0; i < 4; i++) {
        int idx = t + i * 256;
        int row = idx >> 3, seg = idx & 7;
        const __half* src = whi + ((size_t)(co0 + row) * 9 + tap) * 1024 + ci0 + seg * 8;
        cpa16(sb + row * 144 + seg * 16, src, 16u);
    }
}

__device__ __forceinline__ void fus_loadB(uint32_t sb, int t,
    const __half* __restrict__ xhi, int b, int h0, int cik)
{
    int ci0 = cik * 64;
    for (int idx = t; idx < 2112; idx += 256) {
        int row = idx >> 3, seg = idx & 7;
        int hrel = row / 66, wrel = row - hrel * 66;
        int h = h0 - 1 + hrel, w = wrel - 1;
        bool ok = ((unsigned)h < 64u) && ((unsigned)w < 64u);
        const __half* src = xhi
            + ((size_t)(b * 4096 + (ok ? h * 64 + w : 0))) * 1024 + ci0 + seg * 8;
        cpa16(sb + row * 144 + seg * 16, src, ok ? 16u : 0u);
    }
}

__global__ __launch_bounds__(256) void fus_mm(
    const __half* __restrict__ whi, const __half* __restrict__ xhi,
    const float* __restrict__ bias, float* __restrict__ out)
{
    extern __shared__ char dynsmem[];
    const int b = blockIdx.x >> 5;
    const int pbase = (blockIdx.x & 31) * 128;
    const int h0 = pbase >> 6;
    const int co0 = blockIdx.y * 128;
    const int t = threadIdx.x, lane = t & 31, warp = t >> 5;
    const int wm = warp & 1, wn = warp >> 1;
    const uint32_t sb = smem_u32(dynsmem);

    float acc[4][4][4];
#pragma unroll
    for (int fm = 0; fm < 4; fm++)
#pragma unroll
        for (int fn = 0; fn < 4; fn++)
#pragma unroll
            for (int k = 0; k < 4; k++) acc[fm][fn][k] = 0.f;

    fus_loadB(sb + FB0, t, xhi, b, h0, 0);
    fus_loadA(sb, t, whi, co0, 0);
    CP_COMMIT();
    fus_loadA(sb + FA_ST, t, whi, co0, 1);
    CP_COMMIT();

    const int arow = wm * 64 + (lane & 15);
    const int akoff = (lane >> 4) * 16;
    const int l8 = lane & 7, grp = lane >> 3;
    const int bprel = wn * 32 + l8 + (grp >> 1) * 8;
    const int bkoff = (grp & 1) * 16;
    const int bhw = (bprel >> 6) * 66 + (bprel & 63);

    for (int c = 0; c < 144; c++) {
        if (c == 143) { CP_WAIT0(); } else { CP_WAIT1(); }
        __syncthreads();
        const int cik = c / 9, tap = c - cik * 9;
        const int tapoff = (tap / 3) * 66 + (tap % 3);
        const uint32_t Ast = sb + (c & 1) * FA_ST;
        const uint32_t Bst = sb + FB0 + (cik & 1) * FB_ST;
        const uint32_t abase = Ast + arow * 144 + akoff;
        const uint32_t bbase = Bst + (bhw + tapoff) * 144 + bkoff;
#pragma unroll
        for (int ks = 0; ks < 4; ks++) {
            const int kb = ks * 32;
            uint32_t ah[4][4];
#pragma unroll
            for (int fm = 0; fm < 4; fm++)
                ldsm_x4(ah[fm], abase + fm * 16 * 144 + kb);
            uint32_t bh[4][2];
#pragma unroll
            for (int fp = 0; fp < 2; fp++) {
                uint32_t r[4];
                ldsm_x4(r, bbase + fp * 16 * 144 + kb);
                bh[fp*2][0] = r[0]; bh[fp*2][1] = r[1];
                bh[fp*2+1][0] = r[2]; bh[fp*2+1][1] = r[3];
            }
#pragma unroll
            for (int fm = 0; fm < 4; fm++)
#pragma unroll
                for (int fn = 0; fn < 4; fn++)
                    mma16816(acc[fm][fn], ah[fm], bh[fn]);
        }
        __syncthreads();
        if (c + 2 < 144)
            fus_loadA(Ast, t, whi, co0, c + 2);
        if (tap == 0 && cik + 1 < 16)
            fus_loadB(sb + FB0 + ((cik + 1) & 1) * FB_ST, t, xhi, b, h0, cik + 1);
        CP_COMMIT();
    }

    const int r0 = lane >> 2, c0 = (lane & 3) * 2;
#pragma unroll
    for (int fm = 0; fm < 4; fm++) {
        int co = co0 + wm * 64 + fm * 16 + r0;
        float bv0 = bias[co], bv8 = bias[co + 8];
        float* op0 = out + ((size_t)b * 512 + co) * 4096 + pbase;
        float* op8 = op0 + (size_t)8 * 4096;
#pragma unroll
        for (int fn = 0; fn < 4; fn++) {
            int p = wn * 32 + fn * 8 + c0;
            *(float2*)(op0 + p) = make_float2(acc[fm][fn][0] + bv0, acc[fm][fn][1] + bv0);
            *(float2*)(op8 + p) = make_float2(acc[fm][fn][2] + bv8, acc[fm][fn][3] + bv8);
        }
    }
}

// ---- generic mma.sync implicit GEMM (qkv 1x1, box conv), 1-term fp16 ----
template<int TAPS, int COUTV, int ROWSA, int ROWSB>
__device__ __forceinline__ void mm_load(uint32_t sb, int t,
    const __half* __restrict__ whi, const __half* __restrict__ xhi,
    int co0, int WCin, int b, int pbase, int c)
{
    const int B_HI_ = ROWSA * 144;
    int cik = c / TAPS, tap = c - cik * TAPS;
    int dh = (TAPS == 9) ? tap / 3 - 1 : 0;
    int dw = (TAPS == 9) ? tap % 3 - 1 : 0;
    int ci0 = cik * 64;
#pragma unroll
    for (int i = 0; i < ROWSA / 32; i++) {   // A: ROWSA rows x 8 segs
        int idx = t + i * 256;
        int row = idx >> 3, seg = idx & 7;
        int rr = (COUTV < ROWSA && row >= COUTV) ? 0 : row;
        const __half* src = whi
            + ((size_t)(co0 + rr) * TAPS + tap) * WCin + ci0 + seg * 8;
        cpa16(sb + row * 144 + seg * 16, src,
              (COUTV < ROWSA && row >= COUTV) ? 0u : 16u);
    }
#pragma unroll
    for (int i = 0; i < ROWSB / 32; i++) {   // B: ROWSB rows x 8 segs
        int idx = t + i * 256;
        int row = idx >> 3, seg = idx & 7;
        int p = pbase + row;
        int ih = (p >> 6) + dh, iw = (p & 63) + dw;
        bool ok = (TAPS == 1) || (((unsigned)ih < 64u) && ((unsigned)iw < 64u));
        const __half* src = xhi
            + ((size_t)(b * 4096 + (ok ? ih * 64 + iw : 0))) * 1024 + ci0 + seg * 8;
        cpa16(sb + B_HI_ + row * 144 + seg * 16, src, ok ? 16u : 0u);
    }
}

template<int TAPS, int ACT, int COUTV, int ROWSA, int ROWSB>
__global__ __launch_bounds__(256) void mma_mm(
    const __half* __restrict__ whi, const __half* __restrict__ xhi,
    const float* __restrict__ bias, float* __restrict__ out, int WCin, int Cout)
{
    extern __shared__ char dynsmem[];
    const int B_HI_ = ROWSA * 144;
    const int MSTAGE_ = (ROWSA + ROWSB) * 144;
    const int NPT = 4096 / ROWSB;
    const int b = blockIdx.x / NPT;
    const int pbase = (blockIdx.x % NPT) * ROWSB;
    const int co0 = blockIdx.y * ROWSA;
    const int t = threadIdx.x, lane = t & 31, warp = t >> 5;
    const int wm = (ROWSA == 128) ? (warp & 1) : 0;
    const int wn = (ROWSA == 128) ? (warp >> 1) : warp;
    const uint32_t sb0 = smem_u32(dynsmem);
    const int NCH = (WCin / 64) * TAPS;

    float acc[4][4][4];
#pragma unroll
    for (int fm = 0; fm < 4; fm++)
#pragma unroll
        for (int fn = 0; fn < 4; fn++)
#pragma unroll
            for (int k = 0; k < 4; k++) acc[fm][fn][k] = 0.f;

    mm_load<TAPS, COUTV, ROWSA, ROWSB>(sb0, t, whi, xhi, co0, WCin, b, pbase, 0); CP_COMMIT();
    mm_load<TAPS, COUTV, ROWSA, ROWSB>(sb0 + MSTAGE_, t, whi, xhi, co0, WCin, b, pbase, 1); CP_COMMIT();

    const int arow = wm * 64 + (lane & 15);
    const int akoff = (lane >> 4) * 16;
    const int l8 = lane & 7, grp = lane >> 3;
    const int brow = wn * 32 + l8 + (grp >> 1) * 8;
    const int bkoff = (grp & 1) * 16;

    for (int c = 0; c < NCH; c++) {
        const uint32_t sb = sb0 + (c & 1) * MSTAGE_;
        if (c == NCH - 1) { CP_WAIT0(); } else { CP_WAIT1(); }
        __syncthreads();
        const uint32_t abase = sb + arow * 144 + akoff;
        const uint32_t bbase = sb + B_HI_ + brow * 144 + bkoff;
#pragma unroll
        for (int ks = 0; ks < 4; ks++) {
            const int kb = ks * 32;
            uint32_t ah[4][4];
#pragma unroll
            for (int fm = 0; fm < 4; fm++)
                ldsm_x4(ah[fm], abase + fm * 16 * 144 + kb);
            uint32_t bh[4][2];
#pragma unroll
            for (int fp = 0; fp < 2; fp++) {
                uint32_t r[4];
                ldsm_x4(r, bbase + fp * 16 * 144 + kb);
                bh[fp*2][0] = r[0]; bh[fp*2][1] = r[1];
                bh[fp*2+1][0] = r[2]; bh[fp*2+1][1] = r[3];
            }
#pragma unroll
            for (int fm = 0; fm < 4; fm++)
#pragma unroll
                for (int fn = 0; fn < 4; fn++)
                    mma16816(acc[fm][fn], ah[fm], bh[fn]);
        }
        __syncthreads();
        if (c + 2 < NCH) {
            mm_load<TAPS, COUTV, ROWSA, ROWSB>(sb, t, whi, xhi, co0, WCin, b, pbase, c + 2);
            CP_COMMIT();
        }
    }

    const int r0 = lane >> 2, c0 = (lane & 3) * 2;
#pragma unroll
    for (int fm = 0; fm < 4; fm++) {
        int co = co0 + wm * 64 + fm * 16 + r0;
        bool v0ok = (COUTV >= ROWSA) || (co < COUTV);
        bool v8ok = (COUTV >= ROWSA) || (co + 8 < COUTV);
        float bv0 = v0ok ? bias[co] : 0.f;
        float bv8 = v8ok ? bias[co + 8] : 0.f;
        float* op0 = out + ((size_t)b * Cout + co) * 4096 + pbase;
        float* op8 = op0 + (size_t)8 * 4096;
#pragma unroll
        for (int fn = 0; fn < 4; fn++) {
            int p = wn * 32 + fn * 8 + c0;
            float a0 = acc[fm][fn][0] + bv0, a1 = acc[fm][fn][1] + bv0;
            float a2 = acc[fm][fn][2] + bv8, a3 = acc[fm][fn][3] + bv8;
            if (ACT == 1) { a0 = geluf(a0); a1 = geluf(a1); a2 = geluf(a2); a3 = geluf(a3); }
            if (v0ok) *(float2*)(op0 + p) = make_float2(a0, a1);
            if (v8ok) *(float2*)(op8 + p) = make_float2(a2, a3);
        }
    }
}

// ---- attention QK logits via mma (3-term fp16) ----
__global__ __launch_bounds__(128) void attn_qk_mma(
    const float* __restrict__ qkv, const float* __restrict__ edge, float* __restrict__ attn)
{
    int id = blockIdx.x;
    int i = id & 63, h = (id >> 6) & 7, b = id >> 9;
    const float* Q = qkv + ((size_t)(b * 1536 + h * 64 + i)) * PP;
    const float* K = qkv + ((size_t)(b * 1536 + 512 + h * 64 + i)) * PP;
    __shared__ __half sQh[64*72], sQl[64*72], sKh[64*72], sKl[64*72];
    int t = threadIdx.x, lane = t & 31, warp = t >> 5;
    int wm = warp & 1, wn = warp >> 1;
    for (int idx = t; idx < 4096; idx += 128) {
        int y = idx >> 6, c = idx & 63;
        float q = Q[idx];
        __half qh = __float2half_rn(q);
        sQh[c*72 + y] = qh; sQl[c*72 + y] = __float2half_rn(q - __half2float(qh));
        float k = K[idx];
        __half kh = __float2half_rn(k);
        sKh[c*72 + y] = kh; sKl[c*72 + y] = __float2half_rn(k - __half2float(kh));
    }
    __syncthreads();
    float acc[2][4][4];
#pragma unroll
    for (int fm = 0; fm < 2; fm++)
#pragma unroll
        for (int fn = 0; fn < 4; fn++)
#pragma unroll
            for (int k = 0; k < 4; k++) acc[fm][fn][k] = 0.f;

    const uint32_t aQh = smem_u32(sQh), aQl = smem_u32(sQl);
    const uint32_t aKh = smem_u32(sKh), aKl = smem_u32(sKl);
    const int arow = wm * 32 + (lane & 15), akoff = (lane >> 4) * 16;
    const int l8 = lane & 7, grp = lane >> 3;
    const int brow = wn * 32 + l8 + (grp >> 1) * 8, bkoff = (grp & 1) * 16;
#pragma unroll
    for (int ks = 0; ks < 4; ks++) {
        const int kb = ks * 32;
        uint32_t ah[2][4], al[2][4];
#pragma unroll
        for (int fm = 0; fm < 2; fm++) {
            ldsm_x4(ah[fm], aQh + (arow + fm*16) * 144 + akoff + kb);
            ldsm_x4(al[fm], aQl + (arow + fm*16) * 144 + akoff + kb);
        }
        uint32_t bh[4][2], bl[4][2];
#pragma unroll
        for (int fp = 0; fp < 2; fp++) {
            uint32_t r[4];
            ldsm_x4(r, aKh + (brow + fp*16) * 144 + bkoff + kb);
            bh[fp*2][0] = r[0]; bh[fp*2][1] = r[1];
            bh[fp*2+1][0] = r[2]; bh[fp*2+1][1] = r[3];
            ldsm_x4(r, aKl + (brow + fp*16) * 144 + bkoff + kb);
            bl[fp*2][0] = r[0]; bl[fp*2][1] = r[1];
            bl[fp*2+1][0] = r[2]; bl[fp*2+1][1] = r[3];
        }
#pragma unroll
        for (int fm = 0; fm < 2; fm++)
#pragma unroll
            for (int fn = 0; fn < 4; fn++) {
                mma16816(acc[fm][fn], ah[fm], bh[fn]);
                mma16816(acc[fm][fn], ah[fm], bl[fn]);
                mma16816(acc[fm][fn], al[fm], bh[fn]);
            }
    }
    const int r0 = lane >> 2, c0 = (lane & 3) * 2;
    float* op = attn + (size_t)id * 4096;
    const float* ep = edge + (size_t)id * 64;
#pragma unroll
    for (int fm = 0; fm < 2; fm++) {
        int w0 = wm * 32 + fm * 16 + r0;
        float e0 = ep[w0], e8 = ep[w0 + 8];
#pragma unroll
        for (int fn = 0; fn < 4; fn++) {
            int Wp = wn * 32 + fn * 8 + c0;
            op[w0*64 + Wp]       = acc[fm][fn][0] * 0.125f + e0;
            op[w0*64 + Wp + 1]   = acc[fm][fn][1] * 0.125f + e0;
            op[(w0+8)*64 + Wp]   = acc[fm][fn][2] * 0.125f + e8;
            op[(w0+8)*64 + Wp+1] = acc[fm][fn][3] * 0.125f + e8;
        }
    }
}

// ---- attention AV via mma (3-term fp16) ----
__global__ __launch_bounds__(128) void attn_av_mma(
    const float* __restrict__ qkv, const float* __restrict__ attn, float* __restrict__ agg)
{
    int id = blockIdx.x;
    int i = id & 63, h = (id >> 6) & 7, b = id >> 9;
    const float* V = qkv + ((size_t)(b * 1536 + 1024 + h * 64 + i)) * PP;
    const float* A = attn + (size_t)id * 4096;
    __shared__ __half sVh[64*72], sVl[64*72], sAh[64*72], sAl[64*72];
    int t = threadIdx.x, lane = t & 31, warp = t >> 5;
    int wm = warp & 1, wn = warp >> 1;
    for (int idx = t; idx < 4096; idx += 128) {
        int r = idx >> 6, c = idx & 63;
        float v = V[idx];
        __half vh = __float2half_rn(v);
        sVh[r*72 + c] = vh; sVl[r*72 + c] = __float2half_rn(v - __half2float(vh));
        float a = A[idx];
        __half ahv = __float2half_rn(a);
        sAh[r*72 + c] = ahv; sAl[r*72 + c] = __float2half_rn(a - __half2float(ahv));
    }
    __syncthreads();
    float acc[2][4][4];
#pragma unroll
    for (int fm = 0; fm < 2; fm++)
#pragma unroll
        for (int fn = 0; fn < 4; fn++)
#pragma unroll
            for (int k = 0; k < 4; k++) acc[fm][fn][k] = 0.f;

    const uint32_t aVh = smem_u32(sVh), aVl = smem_u32(sVl);
    const uint32_t aAh = smem_u32(sAh), aAl = smem_u32(sAl);
    const int arow = wm * 32 + (lane & 15), akoff = (lane >> 4) * 16;
    const int l8 = lane & 7, grp = lane >> 3;
    const int brow = wn * 32 + l8 + (grp >> 1) * 8, bkoff = (grp & 1) * 16;
#pragma unroll
    for (int ks = 0; ks < 4; ks++) {
        const int kb = ks * 32;
        uint32_t ah[2][4], al[2][4];
#pragma unroll
        for (int fm = 0; fm < 2; fm++) {
            ldsm_x4(ah[fm], aVh + (arow + fm*16) * 144 + akoff + kb);
            ldsm_x4(al[fm], aVl + (arow + fm*16) * 144 + akoff + kb);
        }
        uint32_t bh[4][2], bl[4][2];
#pragma unroll
        for (int fp = 0; fp < 2; fp++) {
            uint32_t r[4];
            ldsm_x4(r, aAh + (brow + fp*16) * 144 + bkoff + kb);
            bh[fp*2][0] = r[0]; bh[fp*2][1] = r[1];
            bh[fp*2+1][0] = r[2]; bh[fp*2+1][1] = r[3];
            ldsm_x4(r, aAl + (brow + fp*16) * 144 + bkoff + kb);
            bl[fp*2][0] = r[0]; bl[fp*2][1] = r[1];
            bl[fp*2+1][0] = r[2]; bl[fp*2+1][1] = r[3];
        }
#pragma unroll
        for (int fm = 0; fm < 2; fm++)
#pragma unroll
            for (int fn = 0; fn < 4; fn++) {
                mma16816(acc[fm][fn], ah[fm], bh[fn]);
                mma16816(acc[fm][fn], ah[fm], bl[fn]);
                mma16816(acc[fm][fn], al[fm], bh[fn]);
            }
    }
    const int r0 = lane >> 2, c0 = (lane & 3) * 2;
    float* op = agg + ((size_t)(b * 512 + h * 64 + i)) * PP;
#pragma unroll
    for (int fm = 0; fm < 2; fm++) {
        int d0 = wm * 32 + fm * 16 + r0;
#pragma unroll
        for (int fn = 0; fn < 4; fn++) {
            int w = wn * 32 + fn * 8 + c0;
            op[d0*64 + w]       = acc[fm][fn][0];
            op[d0*64 + w + 1]   = acc[fm][fn][1];
            op[(d0+8)*64 + w]   = acc[fm][fn][2];
            op[(d0+8)*64 + w+1] = acc[fm][fn][3];
        }
    }
}

// ---- FFMA 3x3 conv (edge net: Cin=4 -> 64 only) ----
#define CI_CHUNK 8
template<int ACT>
__global__ __launch_bounds__(128) void conv3x3_k(
    const float* __restrict__ in1, int Cin,
    const float* __restrict__ wgt, const float* __restrict__ bias,
    float* __restrict__ out, int Cout)
{
    const int bh = blockIdx.x, b = bh >> 6, h = bh & 63;
    const int co0 = blockIdx.y * 64;
    const int t = threadIdx.x, tx = t & 7, ty = t >> 3;
    __shared__ float sIn[CI_CHUNK][3][66];
    __shared__ float sW[64][CI_CHUNK * 9];
    float acc[4][8];
#pragma unroll
    for (int a = 0; a < 4; a++)
#pragma unroll
        for (int j = 0; j < 8; j++) acc[a][j] = 0.f;

    for (int cb = 0; cb < Cin; cb += CI_CHUNK) {
        __syncthreads();
        for (int idx = t; idx < CI_CHUNK * 3 * 66; idx += 128) {
            int ci = idx / 198, rem = idx - ci * 198, r = rem / 66, col = rem - r * 66;
            int cg = cb + ci;
            float v = 0.f;
            int gh = h - 1 + r, gw = col - 1;
            if (cg < Cin && (unsigned)gh < 64u && (unsigned)gw < 64u)
                v = in1[((size_t)(b * Cin + cg)) * PP + gh * 64 + gw];
            sIn[ci][r][col] = v;
        }
        for (int idx = t; idx < 64 * CI_CHUNK * 9; idx += 128) {
            int co = idx / (CI_CHUNK * 9), rem = idx - co * (CI_CHUNK * 9);
            int ci = rem / 9, kk = rem - ci * 9, cg = cb + ci;
            sW[co][ci * 9 + kk] = (cg < Cin) ? wgt[((size_t)(co0 + co) * Cin + cg) * 9 + kk] : 0.f;
        }
        __syncthreads();
#pragma unroll 2
        for (int ci = 0; ci < CI_CHUNK; ci++) {
#pragma unroll
            for (int r = 0; r < 3; r++) {
                float iv[10];
#pragma unroll
                for (int j = 0; j < 10; j++) iv[j] = sIn[ci][r][tx * 8 + j];
#pragma unroll
                for (int cj = 0; cj < 4; cj++) {
                    float w0 = sW[ty * 4 + cj][ci * 9 + r * 3 + 0];
                    float w1 = sW[ty * 4 + cj][ci * 9 + r * 3 + 1];
                    float w2 = sW[ty * 4 + cj][ci * 9 + r * 3 + 2];
#pragma unroll
                    for (int wj = 0; wj < 8; wj++) {
                        acc[cj][wj] = fmaf(w0, iv[wj + 0], acc[cj][wj]);
                        acc[cj][wj] = fmaf(w1, iv[wj + 1], acc[cj][wj]);
                        acc[cj][wj] = fmaf(w2, iv[wj + 2], acc[cj][wj]);
                    }
                }
            }
        }
    }
#pragma unroll
    for (int cj = 0; cj < 4; cj++) {
        int co = co0 + ty * 4 + cj;
        float bv = bias[co];
#pragma unroll
        for (int wj = 0; wj < 8; wj++) {
            float v = acc[cj][wj] + bv;
            if (ACT == 1) v = geluf(v);
            out[(((size_t)b * Cout + co) * 64 + h) * 64 + tx * 8 + wj] = v;
        }
    }
}

template<int ACT>
__global__ void conv1x1_small_k(const float* __restrict__ in, const float* __restrict__ wgt,
                                const float* __restrict__ bias, float* __restrict__ out,
                                int Cin, int Cout)
{
    int bc = blockIdx.x, b = bc / Cout, co = bc - b * Cout;
    int p = blockIdx.y * 256 + threadIdx.x;
    float acc = bias[co];
    const float* ip = in + (size_t)b * Cin * PP + p;
    const float* wp = wgt + (size_t)co * Cin;
    for (int ci = 0; ci < Cin; ci++)
        acc = fmaf(wp[ci], ip[(size_t)ci * PP], acc);
    if (ACT == 2) acc = sigm(acc);
    out[((size_t)b * Cout + co) * PP + p] = acc;
}

// ---- GroupNorm ----
__global__ void gn_stats_k(const float* __restrict__ x, float* __restrict__ stats)
{
    int bg = blockIdx.x, b = bg >> 3, g = bg & 7;
    const float* p = x + ((size_t)b * 64 + g * 8) * PP;
    float s = 0.f, s2 = 0.f;
    for (int i = threadIdx.x; i < 8 * PP; i += 256) {
        float v = p[i]; s += v; s2 += v * v;
    }
    __shared__ float rs[8], rs2[8];
#pragma unroll
    for (int o = 16; o > 0; o >>= 1) {
        s += __shfl_down_sync(0xffffffffu, s, o);
        s2 += __shfl_down_sync(0xffffffffu, s2, o);
    }
    int w = threadIdx.x >> 5, l = threadIdx.x & 31;
    if (l == 0) { rs[w] = s; rs2[w] = s2; }
    __syncthreads();
    if (w == 0) {
        s = (l < 8) ? rs[l] : 0.f; s2 = (l < 8) ? rs2[l] : 0.f;
#pragma unroll
        for (int o = 4; o > 0; o >>= 1) {
            s += __shfl_down_sync(0xffffffffu, s, o);
            s2 += __shfl_down_sync(0xffffffffu, s2, o);
        }
        if (l == 0) {
            float m = s / 32768.f;
            stats[bg * 2] = m;
            stats[bg * 2 + 1] = s2 / 32768.f - m * m;
        }
    }
}

__global__ void gn_apply_k(float* __restrict__ x, const float* __restrict__ stats,
                           const float* __restrict__ gamma, const float* __restrict__ beta)
{
    size_t idx = (size_t)blockIdx.x * 256 + threadIdx.x;
    int c = (int)((idx >> 12) & 63);
    int b = (int)(idx >> 18);
    int bg = b * 8 + (c >> 3);
    float m = stats[bg * 2], v = stats[bg * 2 + 1];
    float xn = (x[idx] - m) * rsqrtf(v + 1e-5f) * gamma[c] + beta[c];
    x[idx] = geluf(xn);
}

// ---- softmax over i ----
__global__ __launch_bounds__(128) void softmax_i_k(float* __restrict__ attn)
{
    int n = blockIdx.x * 128 + threadIdx.x;
    int bh = n >> 12, ww = n & 4095;
    float* p = attn + (size_t)bh * 262144 + ww;
    float x[64], mx = -1e30f;
#pragma unroll
    for (int i = 0; i < 64; i++) { x[i] = p[(size_t)i * 4096]; mx = fmaxf(mx, x[i]); }
    float s = 0.f;
#pragma unroll
    for (int i = 0; i < 64; i++) { x[i] = __expf(x[i] - mx); s += x[i]; }
    float inv = 1.f / s;
#pragma unroll
    for (int i = 0; i < 64; i++) p[(size_t)i * 4096] = x[i] * inv;
}

// ---- BatchNorm ----
__global__ void bn_stats_k(const float* __restrict__ y, float* __restrict__ stats)
{
    int c = blockIdx.x;
    float s = 0.f, s2 = 0.f;
    for (int n = threadIdx.x; n < 32768; n += 256) {
        int b = n >> 12, p = n & 4095;
        float v = y[((size_t)b * CC + c) * PP + p];
        s += v; s2 += v * v;
    }
    __shared__ float rs[8], rs2[8];
#pragma unroll
    for (int o = 16; o > 0; o >>= 1) {
        s += __shfl_down_sync(0xffffffffu, s, o);
        s2 += __shfl_down_sync(0xffffffffu, s2, o);
    }
    int w = threadIdx.x >> 5, l = threadIdx.x & 31;
    if (l == 0) { rs[w] = s; rs2[w] = s2; }
    __syncthreads();
    if (w == 0) {
        s = (l < 8) ? rs[l] : 0.f; s2 = (l < 8) ? rs2[l] : 0.f;
#pragma unroll
        for (int o = 4; o > 0; o >>= 1) {
            s += __shfl_down_sync(0xffffffffu, s, o);
            s2 += __shfl_down_sync(0xffffffffu, s2, o);
        }
        if (l == 0) {
            float m = s / 32768.f;
            stats[c * 2] = m;
            stats[c * 2 + 1] = s2 / 32768.f - m * m;
        }
    }
}

__global__ void bn_apply_k(const float* __restrict__ y, const float* __restrict__ stats,
                           const float* __restrict__ g, const float* __restrict__ bt,
                           float* __restrict__ out)
{
    size_t idx = (size_t)blockIdx.x * 256 + threadIdx.x;
    int c = (int)((idx >> 12) & 511);
    float m = stats[c * 2], v = stats[c * 2 + 1];
    float yn = (y[idx] - m) * rsqrtf(v + 1e-5f) * g[c] + bt[c];
    out[idx] = yn * (1.f / (1.f + __expf(-yn)));
}

// ---- launch ----
extern "C" void kernel_launch(void* const* d_in, const int* in_sizes, int n_in,
                              void* d_out, int out_size)
{
    const float* x       = (const float*)d_in[0];
    const float* box_w1  = (const float*)d_in[1];
    const float* box_b1  = (const float*)d_in[2];
    const float* box_w2  = (const float*)d_in[3];
    const float* box_b2  = (const float*)d_in[4];
    const float* edge_w1 = (const float*)d_in[5];
    const float* edge_b1 = (const float*)d_in[6];
    const float* gn_g    = (const float*)d_in[7];
    const float* gn_b    = (const float*)d_in[8];
    const float* edge_w2 = (const float*)d_in[9];
    const float* edge_b2 = (const float*)d_in[10];
    const float* qkv_w   = (const float*)d_in[11];
    const float* qkv_b   = (const float*)d_in[12];
    const float* fus_w   = (const float*)d_in[13];
    const float* fus_b   = (const float*)d_in[14];
    const float* bn_g    = (const float*)d_in[15];
    const float* bn_b    = (const float*)d_in[16];
    float* out = (float*)d_out;

    float *box1, *boxes, *edge1, *edge, *qkv, *attn, *agg, *y, *gnst, *bnst;
    __half *xhi, *wfhi, *wbhi, *wqhi;
    cudaGetSymbolAddress((void**)&box1,  g_box1);
    cudaGetSymbolAddress((void**)&boxes, g_boxes);
    cudaGetSymbolAddress((void**)&edge1, g_edge1);
    cudaGetSymbolAddress((void**)&edge,  g_edge);
    cudaGetSymbolAddress((void**)&qkv,   g_qkv);
    cudaGetSymbolAddress((void**)&attn,  g_attn);
    cudaGetSymbolAddress((void**)&agg,   g_agg);
    cudaGetSymbolAddress((void**)&y,     g_y);
    cudaGetSymbolAddress((void**)&gnst,  g_gnstats);
    cudaGetSymbolAddress((void**)&bnst,  g_bnstats);
    cudaGetSymbolAddress((void**)&xhi,   g_xhi);
    cudaGetSymbolAddress((void**)&wfhi,  g_wfhi);
    cudaGetSymbolAddress((void**)&wbhi,  g_wbhi);
    cudaGetSymbolAddress((void**)&wqhi,  g_wqhi);

    cudaFuncSetAttribute((const void*)mma_mm<1, 0, 128, 128, 128>, cudaFuncAttributeMaxDynamicSharedMemorySize, 2 * (128 + 128) * 144);
    cudaFuncSetAttribute((const void*)mma_mm<9, 1, 64, 64, 256>,   cudaFuncAttributeMaxDynamicSharedMemorySize, 2 * (64 + 256) * 144);
    cudaFuncSetAttribute((const void*)fus_mm, cudaFuncAttributeMaxDynamicSharedMemorySize, FUS_SMEM);

    // preprocessing (fp16 hi conversions)
    split_k<<<dim3(16, 128, 8), dim3(32, 8)>>>(x, xhi, 512, 0);
    wsplit_k<<<(512 * 1024 * 9 + 255) / 256, 256>>>(fus_w, wfhi, 1024, 9, (size_t)512 * 1024 * 9);
    wsplit_k<<<(64 * 512 * 9 + 255) / 256, 256>>>(box_w1, wbhi, 512, 9, (size_t)64 * 512 * 9);
    wsplit_k<<<(1536 * 512 + 255) / 256, 256>>>(qkv_w, wqhi, 512, 1, (size_t)1536 * 512);

    // box conv3x3(512->64)+GELU (1-term)
    mma_mm<9, 1, 64, 64, 256><<<dim3(128, 1), 256, 2 * (64 + 256) * 144>>>(
        wbhi, xhi, box_b1, box1, 512, 64);

    // qkv 1x1 (512->1536) (1-term)
    mma_mm<1, 0, 128, 128, 128><<<dim3(256, 12), 256, 2 * (128 + 128) * 144>>>(
        wqhi, xhi, qkv_b, qkv, 512, 1536);

    // box tail + edge net
    conv1x1_small_k<2><<<dim3(32, 16), 256>>>(box1, box_w2, box_b2, boxes, 64, 4);
    conv3x3_k<0><<<dim3(512, 1), 128>>>(boxes, 4, edge_w1, edge_b1, edge1, 64);
    gn_stats_k<<<64, 256>>>(edge1, gnst);
    gn_apply_k<<<8192, 256>>>(edge1, gnst, gn_g, gn_b);
    conv1x1_small_k<0><<<dim3(64, 16), 256>>>(edge1, edge_w2, edge_b2, edge, 64, 8);

    // attention (tensor cores, 3-term)
    attn_qk_mma<<<4096, 128>>>(qkv, edge, attn);
    softmax_i_k<<<2048, 128>>>(attn);
    attn_av_mma<<<4096, 128>>>(qkv, attn, agg);

    // convert agg into ci[512:1024) of the fp16 buffer
    split_k<<<dim3(16, 128, 8), dim3(32, 8)>>>(agg, xhi, 512, 512);

    // fusion conv3x3 (1024->512), B-halo reuse + 1-term fp16
    fus_mm<<<dim3(256, 4), 256, FUS_SMEM>>>(wfhi, xhi, fus_b, y);

    // batchnorm + SiLU
    bn_stats_k<<<512, 256>>>(y, bnst);
    bn_apply_k<<<65536, 256>>>(y, bnst, bn_g, bn_b, out);
}

// round 13
// speedup vs baseline: 10.0570x; 1.0156x over previous
#include <cuda_runtime.h>
#include <cuda_fp16.h>
#include <cstdint>
#include <math.h>

#define BB 8
#define CC 512
#define PP 4096
#define NHH 8

// ---- scratch (static device globals; no allocation) ----
__device__ float g_box1[BB*64*PP];
__device__ float g_boxes[BB*4*PP];
__device__ float g_edge1[BB*64*PP];
__device__ float g_edge[BB*NHH*PP];
__device__ float g_qkv[(size_t)BB*1536*PP];
__device__ float g_attn[(size_t)BB*NHH*64*64*64];
__device__ float g_agg[(size_t)BB*CC*PP];
__device__ float g_y[(size_t)BB*CC*PP];
__device__ float g_gnstats[BB*8*2];
__device__ float g_bnstats[CC*2];
__device__ __half g_xhi[(size_t)BB*PP*1024];   // [b][p][ci]
__device__ __half g_wfhi[512*9*1024];          // [co][tap][ci]
__device__ __half g_wbhi[64*9*512];
__device__ __half g_wqhi[1536*512];

__device__ __forceinline__ float geluf(float x) {
    return 0.5f * x * (1.0f + erff(x * 0.70710678118654752440f));
}
__device__ __forceinline__ float sigm(float x) { return 1.0f / (1.0f + __expf(-x)); }

// ---- arch-neutral tensor-core helpers (sm_80+ PTX only) ----
__device__ __forceinline__ uint32_t smem_u32(const void* p) {
    uint32_t a;
    asm("{ .reg .u64 t; cvta.to.shared.u64 t, %1; cvt.u32.u64 %0, t; }" : "=r"(a) : "l"(p));
    return a;
}
__device__ __forceinline__ void ldsm_x4(uint32_t* r, uint32_t addr) {
    asm volatile("ldmatrix.sync.aligned.m8n8.x4.shared.b16 {%0,%1,%2,%3}, [%4];"
        : "=r"(r[0]), "=r"(r[1]), "=r"(r[2]), "=r"(r[3]) : "r"(addr));
}
__device__ __forceinline__ void mma16816(float* d, const uint32_t* a, const uint32_t* b) {
    asm volatile("mma.sync.aligned.m16n8k16.row.col.f32.f16.f16.f32 "
        "{%0,%1,%2,%3}, {%4,%5,%6,%7}, {%8,%9}, {%0,%1,%2,%3};"
        : "+f"(d[0]), "+f"(d[1]), "+f"(d[2]), "+f"(d[3])
        : "r"(a[0]), "r"(a[1]), "r"(a[2]), "r"(a[3]), "r"(b[0]), "r"(b[1]));
}
__device__ __forceinline__ void cpa16(uint32_t dst, const void* src, uint32_t sz) {
    asm volatile("cp.async.cg.shared.global [%0], [%1], 16, %2;\n" :: "r"(dst), "l"(src), "r"(sz));
}
#define CP_COMMIT() asm volatile("cp.async.commit_group;\n" ::: "memory")
#define CP_WAIT1()  asm volatile("cp.async.wait_group 1;\n" ::: "memory")
#define CP_WAIT0()  asm volatile("cp.async.wait_group 0;\n" ::: "memory")

// ---- convert / transpose: NCHW fp32 -> [b][p][ci] fp16 ----
__global__ void split_k(const float* __restrict__ src, __half* __restrict__ xhi,
                        int Cn, int cibase)
{
    __shared__ float tile[32][33];
    int bz = blockIdx.z, c0 = blockIdx.x * 32, p0 = blockIdx.y * 32;
    int tx = threadIdx.x, ty = threadIdx.y;
#pragma unroll
    for (int i = 0; i < 32; i += 8)
        tile[ty + i][tx] = src[((size_t)bz * Cn + c0 + ty + i) * 4096 + p0 + tx];
    __syncthreads();
#pragma unroll
    for (int i = 0; i < 32; i += 8) {
        size_t o = ((size_t)bz * 4096 + p0 + ty + i) * 1024 + cibase + c0 + tx;
        xhi[o] = __float2half_rn(tile[tx][ty + i]);
    }
}

// OIHW fp32 -> [co][tap][ci] fp16
__global__ void wsplit_k(const float* __restrict__ w, __half* __restrict__ whi,
                         int Cin, int taps, size_t total)
{
    size_t i = (size_t)blockIdx.x * 256 + threadIdx.x;
    if (i >= total) return;
    int tap = (int)(i % taps);
    size_t t2 = i / taps;
    int ci = (int)(t2 % Cin);
    int co = (int)(t2 / Cin);
    whi[((size_t)co * taps + tap) * Cin + ci] = __float2half_rn(w[i]);
}

// ================= fusion conv3x3 (1024->512): B-halo reuse + 1-term fp16 ==========
#define FA_ST 18432            // A stage: 128 rows x 144B
#define FB0   36864
#define FB_ST 38016            // B stage: 264 rows x 144B
#define FUS_SMEM 112896

__device__ __forceinline__ void fus_loadA(uint32_t sb, int t,
    const __half* __restrict__ whi, int co0, int c)
{
    int cik = c / 9, tap = c - cik * 9, ci0 = cik * 64;
#pragma unroll
    for (int i = 0; i < 4; i++) {
        int idx = t + i * 256;
        int row = idx >> 3, seg = idx & 7;
        const __half* src = whi + ((size_t)(co0 + row) * 9 + tap) * 1024 + ci0 + seg * 8;
        cpa16(sb + row * 144 + seg * 16, src, 16u);
    }
}

__device__ __forceinline__ void fus_loadB(uint32_t sb, int t,
    const __half* __restrict__ xhi, int b, int h0, int cik)
{
    int ci0 = cik * 64;
    for (int idx = t; idx < 2112; idx += 256) {
        int row = idx >> 3, seg = idx & 7;
        int hrel = row / 66, wrel = row - hrel * 66;
        int h = h0 - 1 + hrel, w = wrel - 1;
        bool ok = ((unsigned)h < 64u) && ((unsigned)w < 64u);
        const __half* src = xhi
            + ((size_t)(b * 4096 + (ok ? h * 64 + w : 0))) * 1024 + ci0 + seg * 8;
        cpa16(sb + row * 144 + seg * 16, src, ok ? 16u : 0u);
    }
}

__global__ __launch_bounds__(256, 2) void fus_mm(
    const __half* __restrict__ whi, const __half* __restrict__ xhi,
    const float* __restrict__ bias, float* __restrict__ out)
{
    extern __shared__ char dynsmem[];
    const int b = blockIdx.x >> 5;
    const int pbase = (blockIdx.x & 31) * 128;
    const int h0 = pbase >> 6;
    const int co0 = blockIdx.y * 128;
    const int t = threadIdx.x, lane = t & 31, warp = t >> 5;
    const int wm = warp & 1, wn = warp >> 1;
    const uint32_t sb = smem_u32(dynsmem);

    float acc[4][4][4];
#pragma unroll
    for (int fm = 0; fm < 4; fm++)
#pragma unroll
        for (int fn = 0; fn < 4; fn++)
#pragma unroll
            for (int k = 0; k < 4; k++) acc[fm][fn][k] = 0.f;

    fus_loadB(sb + FB0, t, xhi, b, h0, 0);
    fus_loadA(sb, t, whi, co0, 0);
    CP_COMMIT();
    fus_loadA(sb + FA_ST, t, whi, co0, 1);
    CP_COMMIT();

    const int arow = wm * 64 + (lane & 15);
    const int akoff = (lane >> 4) * 16;
    const int l8 = lane & 7, grp = lane >> 3;
    const int bprel = wn * 32 + l8 + (grp >> 1) * 8;
    const int bkoff = (grp & 1) * 16;
    const int bhw = (bprel >> 6) * 66 + (bprel & 63);

    for (int c = 0; c < 144; c++) {
        if (c == 143) { CP_WAIT0(); } else { CP_WAIT1(); }
        __syncthreads();
        const int cik = c / 9, tap = c - cik * 9;
        const int tapoff = (tap / 3) * 66 + (tap % 3);
        const uint32_t Ast = sb + (c & 1) * FA_ST;
        const uint32_t Bst = sb + FB0 + (cik & 1) * FB_ST;
        const uint32_t abase = Ast + arow * 144 + akoff;
        const uint32_t bbase = Bst + (bhw + tapoff) * 144 + bkoff;
#pragma unroll
        for (int ks = 0; ks < 4; ks++) {
            const int kb = ks * 32;
            uint32_t ah[4][4];
#pragma unroll
            for (int fm = 0; fm < 4; fm++)
                ldsm_x4(ah[fm], abase + fm * 16 * 144 + kb);
            uint32_t bh[4][2];
#pragma unroll
            for (int fp = 0; fp < 2; fp++) {
                uint32_t r[4];
                ldsm_x4(r, bbase + fp * 16 * 144 + kb);
                bh[fp*2][0] = r[0]; bh[fp*2][1] = r[1];
                bh[fp*2+1][0] = r[2]; bh[fp*2+1][1] = r[3];
            }
#pragma unroll
            for (int fm = 0; fm < 4; fm++)
#pragma unroll
                for (int fn = 0; fn < 4; fn++)
                    mma16816(acc[fm][fn], ah[fm], bh[fn]);
        }
        __syncthreads();
        if (c + 2 < 144)
            fus_loadA(Ast, t, whi, co0, c + 2);
        if (tap == 0 && cik + 1 < 16)
            fus_loadB(sb + FB0 + ((cik + 1) & 1) * FB_ST, t, xhi, b, h0, cik + 1);
        CP_COMMIT();
    }

    const int r0 = lane >> 2, c0 = (lane & 3) * 2;
#pragma unroll
    for (int fm = 0; fm < 4; fm++) {
        int co = co0 + wm * 64 + fm * 16 + r0;
        float bv0 = bias[co], bv8 = bias[co + 8];
        float* op0 = out + ((size_t)b * 512 + co) * 4096 + pbase;
        float* op8 = op0 + (size_t)8 * 4096;
#pragma unroll
        for (int fn = 0; fn < 4; fn++) {
            int p = wn * 32 + fn * 8 + c0;
            *(float2*)(op0 + p) = make_float2(acc[fm][fn][0] + bv0, acc[fm][fn][1] + bv0);
            *(float2*)(op8 + p) = make_float2(acc[fm][fn][2] + bv8, acc[fm][fn][3] + bv8);
        }
    }
}

// ---- generic mma.sync implicit GEMM (qkv 1x1, box conv), 1-term fp16 ----
template<int TAPS, int COUTV, int ROWSA, int ROWSB>
__device__ __forceinline__ void mm_load(uint32_t sb, int t,
    const __half* __restrict__ whi, const __half* __restrict__ xhi,
    int co0, int WCin, int b, int pbase, int c)
{
    const int B_HI_ = ROWSA * 144;
    int cik = c / TAPS, tap = c - cik * TAPS;
    int dh = (TAPS == 9) ? tap / 3 - 1 : 0;
    int dw = (TAPS == 9) ? tap % 3 - 1 : 0;
    int ci0 = cik * 64;
#pragma unroll
    for (int i = 0; i < ROWSA / 32; i++) {
        int idx = t + i * 256;
        int row = idx >> 3, seg = idx & 7;
        int rr = (COUTV < ROWSA && row >= COUTV) ? 0 : row;
        const __half* src = whi
            + ((size_t)(co0 + rr) * TAPS + tap) * WCin + ci0 + seg * 8;
        cpa16(sb + row * 144 + seg * 16, src,
              (COUTV < ROWSA && row >= COUTV) ? 0u : 16u);
    }
#pragma unroll
    for (int i = 0; i < ROWSB / 32; i++) {
        int idx = t + i * 256;
        int row = idx >> 3, seg = idx & 7;
        int p = pbase + row;
        int ih = (p >> 6) + dh, iw = (p & 63) + dw;
        bool ok = (TAPS == 1) || (((unsigned)ih < 64u) && ((unsigned)iw < 64u));
        const __half* src = xhi
            + ((size_t)(b * 4096 + (ok ? ih * 64 + iw : 0))) * 1024 + ci0 + seg * 8;
        cpa16(sb + B_HI_ + row * 144 + seg * 16, src, ok ? 16u : 0u);
    }
}

template<int TAPS, int ACT, int COUTV, int ROWSA, int ROWSB>
__global__ __launch_bounds__(256, 2) void mma_mm(
    const __half* __restrict__ whi, const __half* __restrict__ xhi,
    const float* __restrict__ bias, float* __restrict__ out, int WCin, int Cout)
{
    extern __shared__ char dynsmem[];
    const int B_HI_ = ROWSA * 144;
    const int MSTAGE_ = (ROWSA + ROWSB) * 144;
    const int NPT = 4096 / ROWSB;
    const int b = blockIdx.x / NPT;
    const int pbase = (blockIdx.x % NPT) * ROWSB;
    const int co0 = blockIdx.y * ROWSA;
    const int t = threadIdx.x, lane = t & 31, warp = t >> 5;
    const int wm = (ROWSA == 128) ? (warp & 1) : 0;
    const int wn = (ROWSA == 128) ? (warp >> 1) : warp;
    const uint32_t sb0 = smem_u32(dynsmem);
    const int NCH = (WCin / 64) * TAPS;

    float acc[4][4][4];
#pragma unroll
    for (int fm = 0; fm < 4; fm++)
#pragma unroll
        for (int fn = 0; fn < 4; fn++)
#pragma unroll
            for (int k = 0; k < 4; k++) acc[fm][fn][k] = 0.f;

    mm_load<TAPS, COUTV, ROWSA, ROWSB>(sb0, t, whi, xhi, co0, WCin, b, pbase, 0); CP_COMMIT();
    mm_load<TAPS, COUTV, ROWSA, ROWSB>(sb0 + MSTAGE_, t, whi, xhi, co0, WCin, b, pbase, 1); CP_COMMIT();

    const int arow = wm * 64 + (lane & 15);
    const int akoff = (lane >> 4) * 16;
    const int l8 = lane & 7, grp = lane >> 3;
    const int brow = wn * 32 + l8 + (grp >> 1) * 8;
    const int bkoff = (grp & 1) * 16;

    for (int c = 0; c < NCH; c++) {
        const uint32_t sb = sb0 + (c & 1) * MSTAGE_;
        if (c == NCH - 1) { CP_WAIT0(); } else { CP_WAIT1(); }
        __syncthreads();
        const uint32_t abase = sb + arow * 144 + akoff;
        const uint32_t bbase = sb + B_HI_ + brow * 144 + bkoff;
#pragma unroll
        for (int ks = 0; ks < 4; ks++) {
            const int kb = ks * 32;
            uint32_t ah[4][4];
#pragma unroll
            for (int fm = 0; fm < 4; fm++)
                ldsm_x4(ah[fm], abase + fm * 16 * 144 + kb);
            uint32_t bh[4][2];
#pragma unroll
            for (int fp = 0; fp < 2; fp++) {
                uint32_t r[4];
                ldsm_x4(r, bbase + fp * 16 * 144 + kb);
                bh[fp*2][0] = r[0]; bh[fp*2][1] = r[1];
                bh[fp*2+1][0] = r[2]; bh[fp*2+1][1] = r[3];
            }
#pragma unroll
            for (int fm = 0; fm < 4; fm++)
#pragma unroll
                for (int fn = 0; fn < 4; fn++)
                    mma16816(acc[fm][fn], ah[fm], bh[fn]);
        }
        __syncthreads();
        if (c + 2 < NCH) {
            mm_load<TAPS, COUTV, ROWSA, ROWSB>(sb, t, whi, xhi, co0, WCin, b, pbase, c + 2);
            CP_COMMIT();
        }
    }

    const int r0 = lane >> 2, c0 = (lane & 3) * 2;
#pragma unroll
    for (int fm = 0; fm < 4; fm++) {
        int co = co0 + wm * 64 + fm * 16 + r0;
        bool v0ok = (COUTV >= ROWSA) || (co < COUTV);
        bool v8ok = (COUTV >= ROWSA) || (co + 8 < COUTV);
        float bv0 = v0ok ? bias[co] : 0.f;
        float bv8 = v8ok ? bias[co + 8] : 0.f;
        float* op0 = out + ((size_t)b * Cout + co) * 4096 + pbase;
        float* op8 = op0 + (size_t)8 * 4096;
#pragma unroll
        for (int fn = 0; fn < 4; fn++) {
            int p = wn * 32 + fn * 8 + c0;
            float a0 = acc[fm][fn][0] + bv0, a1 = acc[fm][fn][1] + bv0;
            float a2 = acc[fm][fn][2] + bv8, a3 = acc[fm][fn][3] + bv8;
            if (ACT == 1) { a0 = geluf(a0); a1 = geluf(a1); a2 = geluf(a2); a3 = geluf(a3); }
            if (v0ok) *(float2*)(op0 + p) = make_float2(a0, a1);
            if (v8ok) *(float2*)(op8 + p) = make_float2(a2, a3);
        }
    }
}

// ---- attention QK logits via mma (1-term fp16) ----
__global__ __launch_bounds__(128) void attn_qk_mma(
    const float* __restrict__ qkv, const float* __restrict__ edge, float* __restrict__ attn)
{
    int id = blockIdx.x;
    int i = id & 63, h = (id >> 6) & 7, b = id >> 9;
    const float* Q = qkv + ((size_t)(b * 1536 + h * 64 + i)) * PP;
    const float* K = qkv + ((size_t)(b * 1536 + 512 + h * 64 + i)) * PP;
    __shared__ __half sQh[64*72], sKh[64*72];
    int t = threadIdx.x, lane = t & 31, warp = t >> 5;
    int wm = warp & 1, wn = warp >> 1;
    for (int idx = t; idx < 4096; idx += 128) {
        int y = idx >> 6, c = idx & 63;
        sQh[c*72 + y] = __float2half_rn(Q[idx]);
        sKh[c*72 + y] = __float2half_rn(K[idx]);
    }
    __syncthreads();
    float acc[2][4][4];
#pragma unroll
    for (int fm = 0; fm < 2; fm++)
#pragma unroll
        for (int fn = 0; fn < 4; fn++)
#pragma unroll
            for (int k = 0; k < 4; k++) acc[fm][fn][k] = 0.f;

    const uint32_t aQh = smem_u32(sQh), aKh = smem_u32(sKh);
    const int arow = wm * 32 + (lane & 15), akoff = (lane >> 4) * 16;
    const int l8 = lane & 7, grp = lane >> 3;
    const int brow = wn * 32 + l8 + (grp >> 1) * 8, bkoff = (grp & 1) * 16;
#pragma unroll
    for (int ks = 0; ks < 4; ks++) {
        const int kb = ks * 32;
        uint32_t ah[2][4];
#pragma unroll
        for (int fm = 0; fm < 2; fm++)
            ldsm_x4(ah[fm], aQh + (arow + fm*16) * 144 + akoff + kb);
        uint32_t bh[4][2];
#pragma unroll
        for (int fp = 0; fp < 2; fp++) {
            uint32_t r[4];
            ldsm_x4(r, aKh + (brow + fp*16) * 144 + bkoff + kb);
            bh[fp*2][0] = r[0]; bh[fp*2][1] = r[1];
            bh[fp*2+1][0] = r[2]; bh[fp*2+1][1] = r[3];
        }
#pragma unroll
        for (int fm = 0; fm < 2; fm++)
#pragma unroll
            for (int fn = 0; fn < 4; fn++)
                mma16816(acc[fm][fn], ah[fm], bh[fn]);
    }
    const int r0 = lane >> 2, c0 = (lane & 3) * 2;
    float* op = attn + (size_t)id * 4096;
    const float* ep = edge + (size_t)id * 64;
#pragma unroll
    for (int fm = 0; fm < 2; fm++) {
        int w0 = wm * 32 + fm * 16 + r0;
        float e0 = ep[w0], e8 = ep[w0 + 8];
#pragma unroll
        for (int fn = 0; fn < 4; fn++) {
            int Wp = wn * 32 + fn * 8 + c0;
            op[w0*64 + Wp]       = acc[fm][fn][0] * 0.125f + e0;
            op[w0*64 + Wp + 1]   = acc[fm][fn][1] * 0.125f + e0;
            op[(w0+8)*64 + Wp]   = acc[fm][fn][2] * 0.125f + e8;
            op[(w0+8)*64 + Wp+1] = acc[fm][fn][3] * 0.125f + e8;
        }
    }
}

// ---- attention AV via mma (1-term fp16) ----
__global__ __launch_bounds__(128) void attn_av_mma(
    const float* __restrict__ qkv, const float* __restrict__ attn, float* __restrict__ agg)
{
    int id = blockIdx.x;
    int i = id & 63, h = (id >> 6) & 7, b = id >> 9;
    const float* V = qkv + ((size_t)(b * 1536 + 1024 + h * 64 + i)) * PP;
    const float* A = attn + (size_t)id * 4096;
    __shared__ __half sVh[64*72], sAh[64*72];
    int t = threadIdx.x, lane = t & 31, warp = t >> 5;
    int wm = warp & 1, wn = warp >> 1;
    for (int idx = t; idx < 4096; idx += 128) {
        int r = idx >> 6, c = idx & 63;
        sVh[r*72 + c] = __float2half_rn(V[idx]);
        sAh[r*72 + c] = __float2half_rn(A[idx]);
    }
    __syncthreads();
    float acc[2][4][4];
#pragma unroll
    for (int fm = 0; fm < 2; fm++)
#pragma unroll
        for (int fn = 0; fn < 4; fn++)
#pragma unroll
            for (int k = 0; k < 4; k++) acc[fm][fn][k] = 0.f;

    const uint32_t aVh = smem_u32(sVh), aAh = smem_u32(sAh);
    const int arow = wm * 32 + (lane & 15), akoff = (lane >> 4) * 16;
    const int l8 = lane & 7, grp = lane >> 3;
    const int brow = wn * 32 + l8 + (grp >> 1) * 8, bkoff = (grp & 1) * 16;
#pragma unroll
    for (int ks = 0; ks < 4; ks++) {
        const int kb = ks * 32;
        uint32_t ah[2][4];
#pragma unroll
        for (int fm = 0; fm < 2; fm++)
            ldsm_x4(ah[fm], aVh + (arow + fm*16) * 144 + akoff + kb);
        uint32_t bh[4][2];
#pragma unroll
        for (int fp = 0; fp < 2; fp++) {
            uint32_t r[4];
            ldsm_x4(r, aAh + (brow + fp*16) * 144 + bkoff + kb);
            bh[fp*2][0] = r[0]; bh[fp*2][1] = r[1];
            bh[fp*2+1][0] = r[2]; bh[fp*2+1][1] = r[3];
        }
#pragma unroll
        for (int fm = 0; fm < 2; fm++)
#pragma unroll
            for (int fn = 0; fn < 4; fn++)
                mma16816(acc[fm][fn], ah[fm], bh[fn]);
    }
    const int r0 = lane >> 2, c0 = (lane & 3) * 2;
    float* op = agg + ((size_t)(b * 512 + h * 64 + i)) * PP;
#pragma unroll
    for (int fm = 0; fm < 2; fm++) {
        int d0 = wm * 32 + fm * 16 + r0;
#pragma unroll
        for (int fn = 0; fn < 4; fn++) {
            int w = wn * 32 + fn * 8 + c0;
            op[d0*64 + w]       = acc[fm][fn][0];
            op[d0*64 + w + 1]   = acc[fm][fn][1];
            op[(d0+8)*64 + w]   = acc[fm][fn][2];
            op[(d0+8)*64 + w+1] = acc[fm][fn][3];
        }
    }
}

// ---- FFMA 3x3 conv (edge net: Cin=4 -> 64 only) ----
#define CI_CHUNK 8
template<int ACT>
__global__ __launch_bounds__(128) void conv3x3_k(
    const float* __restrict__ in1, int Cin,
    const float* __restrict__ wgt, const float* __restrict__ bias,
    float* __restrict__ out, int Cout)
{
    const int bh = blockIdx.x, b = bh >> 6, h = bh & 63;
    const int co0 = blockIdx.y * 64;
    const int t = threadIdx.x, tx = t & 7, ty = t >> 3;
    __shared__ float sIn[CI_CHUNK][3][66];
    __shared__ float sW[64][CI_CHUNK * 9];
    float acc[4][8];
#pragma unroll
    for (int a = 0; a < 4; a++)
#pragma unroll
        for (int j = 0; j < 8; j++) acc[a][j] = 0.f;

    for (int cb = 0; cb < Cin; cb += CI_CHUNK) {
        __syncthreads();
        for (int idx = t; idx < CI_CHUNK * 3 * 66; idx += 128) {
            int ci = idx / 198, rem = idx - ci * 198, r = rem / 66, col = rem - r * 66;
            int cg = cb + ci;
            float v = 0.f;
            int gh = h - 1 + r, gw = col - 1;
            if (cg < Cin && (unsigned)gh < 64u && (unsigned)gw < 64u)
                v = in1[((size_t)(b * Cin + cg)) * PP + gh * 64 + gw];
            sIn[ci][r][col] = v;
        }
        for (int idx = t; idx < 64 * CI_CHUNK * 9; idx += 128) {
            int co = idx / (CI_CHUNK * 9), rem = idx - co * (CI_CHUNK * 9);
            int ci = rem / 9, kk = rem - ci * 9, cg = cb + ci;
            sW[co][ci * 9 + kk] = (cg < Cin) ? wgt[((size_t)(co0 + co) * Cin + cg) * 9 + kk] : 0.f;
        }
        __syncthreads();
#pragma unroll 2
        for (int ci = 0; ci < CI_CHUNK; ci++) {
#pragma unroll
            for (int r = 0; r < 3; r++) {
                float iv[10];
#pragma unroll
                for (int j = 0; j < 10; j++) iv[j] = sIn[ci][r][tx * 8 + j];
#pragma unroll
                for (int cj = 0; cj < 4; cj++) {
                    float w0 = sW[ty * 4 + cj][ci * 9 + r * 3 + 0];
                    float w1 = sW[ty * 4 + cj][ci * 9 + r * 3 + 1];
                    float w2 = sW[ty * 4 + cj][ci * 9 + r * 3 + 2];
#pragma unroll
                    for (int wj = 0; wj < 8; wj++) {
                        acc[cj][wj] = fmaf(w0, iv[wj + 0], acc[cj][wj]);
                        acc[cj][wj] = fmaf(w1, iv[wj + 1], acc[cj][wj]);
                        acc[cj][wj] = fmaf(w2, iv[wj + 2], acc[cj][wj]);
                    }
                }
            }
        }
    }
#pragma unroll
    for (int cj = 0; cj < 4; cj++) {
        int co = co0 + ty * 4 + cj;
        float bv = bias[co];
#pragma unroll
        for (int wj = 0; wj < 8; wj++) {
            float v = acc[cj][wj] + bv;
            if (ACT == 1) v = geluf(v);
            out[(((size_t)b * Cout + co) * 64 + h) * 64 + tx * 8 + wj] = v;
        }
    }
}

template<int ACT>
__global__ void conv1x1_small_k(const float* __restrict__ in, const float* __restrict__ wgt,
                                const float* __restrict__ bias, float* __restrict__ out,
                                int Cin, int Cout)
{
    int bc = blockIdx.x, b = bc / Cout, co = bc - b * Cout;
    int p = blockIdx.y * 256 + threadIdx.x;
    float acc = bias[co];
    const float* ip = in + (size_t)b * Cin * PP + p;
    const float* wp = wgt + (size_t)co * Cin;
    for (int ci = 0; ci < Cin; ci++)
        acc = fmaf(wp[ci], ip[(size_t)ci * PP], acc);
    if (ACT == 2) acc = sigm(acc);
    out[((size_t)b * Cout + co) * PP + p] = acc;
}

// ---- GroupNorm ----
__global__ void gn_stats_k(const float* __restrict__ x, float* __restrict__ stats)
{
    int bg = blockIdx.x, b = bg >> 3, g = bg & 7;
    const float* p = x + ((size_t)b * 64 + g * 8) * PP;
    float s = 0.f, s2 = 0.f;
    for (int i = threadIdx.x; i < 8 * PP; i += 256) {
        float v = p[i]; s += v; s2 += v * v;
    }
    __shared__ float rs[8], rs2[8];
#pragma unroll
    for (int o = 16; o > 0; o >>= 1) {
        s += __shfl_down_sync(0xffffffffu, s, o);
        s2 += __shfl_down_sync(0xffffffffu, s2, o);
    }
    int w = threadIdx.x >> 5, l = threadIdx.x & 31;
    if (l == 0) { rs[w] = s; rs2[w] = s2; }
    __syncthreads();
    if (w == 0) {
        s = (l < 8) ? rs[l] : 0.f; s2 = (l < 8) ? rs2[l] : 0.f;
#pragma unroll
        for (int o = 4; o > 0; o >>= 1) {
            s += __shfl_down_sync(0xffffffffu, s, o);
            s2 += __shfl_down_sync(0xffffffffu, s2, o);
        }
        if (l == 0) {
            float m = s / 32768.f;
            stats[bg * 2] = m;
            stats[bg * 2 + 1] = s2 / 32768.f - m * m;
        }
    }
}

__global__ void gn_apply_k(float* __restrict__ x, const float* __restrict__ stats,
                           const float* __restrict__ gamma, const float* __restrict__ beta)
{
    size_t idx = (size_t)blockIdx.x * 256 + threadIdx.x;
    int c = (int)((idx >> 12) & 63);
    int b = (int)(idx >> 18);
    int bg = b * 8 + (c >> 3);
    float m = stats[bg * 2], v = stats[bg * 2 + 1];
    float xn = (x[idx] - m) * rsqrtf(v + 1e-5f) * gamma[c] + beta[c];
    x[idx] = geluf(xn);
}

// ---- softmax over i ----
__global__ __launch_bounds__(128) void softmax_i_k(float* __restrict__ attn)
{
    int n = blockIdx.x * 128 + threadIdx.x;
    int bh = n >> 12, ww = n & 4095;
    float* p = attn + (size_t)bh * 262144 + ww;
    float x[64], mx = -1e30f;
#pragma unroll
    for (int i = 0; i < 64; i++) { x[i] = p[(size_t)i * 4096]; mx = fmaxf(mx, x[i]); }
    float s = 0.f;
#pragma unroll
    for (int i = 0; i < 64; i++) { x[i] = __expf(x[i] - mx); s += x[i]; }
    float inv = 1.f / s;
#pragma unroll
    for (int i = 0; i < 64; i++) p[(size_t)i * 4096] = x[i] * inv;
}

// ---- BatchNorm ----
__global__ void bn_stats_k(const float* __restrict__ y, float* __restrict__ stats)
{
    int c = blockIdx.x;
    float s = 0.f, s2 = 0.f;
    for (int n = threadIdx.x; n < 32768; n += 256) {
        int b = n >> 12, p = n & 4095;
        float v = y[((size_t)b * CC + c) * PP + p];
        s += v; s2 += v * v;
    }
    __shared__ float rs[8], rs2[8];
#pragma unroll
    for (int o = 16; o > 0; o >>= 1) {
        s += __shfl_down_sync(0xffffffffu, s, o);
        s2 += __shfl_down_sync(0xffffffffu, s2, o);
    }
    int w = threadIdx.x >> 5, l = threadIdx.x & 31;
    if (l == 0) { rs[w] = s; rs2[w] = s2; }
    __syncthreads();
    if (w == 0) {
        s = (l < 8) ? rs[l] : 0.f; s2 = (l < 8) ? rs2[l] : 0.f;
#pragma unroll
        for (int o = 4; o > 0; o >>= 1) {
            s += __shfl_down_sync(0xffffffffu, s, o);
            s2 += __shfl_down_sync(0xffffffffu, s2, o);
        }
        if (l == 0) {
            float m = s / 32768.f;
            stats[c * 2] = m;
            stats[c * 2 + 1] = s2 / 32768.f - m * m;
        }
    }
}

__global__ void bn_apply_k(const float* __restrict__ y, const float* __restrict__ stats,
                           const float* __restrict__ g, const float* __restrict__ bt,
                           float* __restrict__ out)
{
    size_t idx = (size_t)blockIdx.x * 256 + threadIdx.x;
    int c = (int)((idx >> 12) & 511);
    float m = stats[c * 2], v = stats[c * 2 + 1];
    float yn = (y[idx] - m) * rsqrtf(v + 1e-5f) * g[c] + bt[c];
    out[idx] = yn * (1.f / (1.f + __expf(-yn)));
}

// ---- launch ----
extern "C" void kernel_launch(void* const* d_in, const int* in_sizes, int n_in,
                              void* d_out, int out_size)
{
    const float* x       = (const float*)d_in[0];
    const float* box_w1  = (const float*)d_in[1];
    const float* box_b1  = (const float*)d_in[2];
    const float* box_w2  = (const float*)d_in[3];
    const float* box_b2  = (const float*)d_in[4];
    const float* edge_w1 = (const float*)d_in[5];
    const float* edge_b1 = (const float*)d_in[6];
    const float* gn_g    = (const float*)d_in[7];
    const float* gn_b    = (const float*)d_in[8];
    const float* edge_w2 = (const float*)d_in[9];
    const float* edge_b2 = (const float*)d_in[10];
    const float* qkv_w   = (const float*)d_in[11];
    const float* qkv_b   = (const float*)d_in[12];
    const float* fus_w   = (const float*)d_in[13];
    const float* fus_b   = (const float*)d_in[14];
    const float* bn_g    = (const float*)d_in[15];
    const float* bn_b    = (const float*)d_in[16];
    float* out = (float*)d_out;

    float *box1, *boxes, *edge1, *edge, *qkv, *attn, *agg, *y, *gnst, *bnst;
    __half *xhi, *wfhi, *wbhi, *wqhi;
    cudaGetSymbolAddress((void**)&box1,  g_box1);
    cudaGetSymbolAddress((void**)&boxes, g_boxes);
    cudaGetSymbolAddress((void**)&edge1, g_edge1);
    cudaGetSymbolAddress((void**)&edge,  g_edge);
    cudaGetSymbolAddress((void**)&qkv,   g_qkv);
    cudaGetSymbolAddress((void**)&attn,  g_attn);
    cudaGetSymbolAddress((void**)&agg,   g_agg);
    cudaGetSymbolAddress((void**)&y,     g_y);
    cudaGetSymbolAddress((void**)&gnst,  g_gnstats);
    cudaGetSymbolAddress((void**)&bnst,  g_bnstats);
    cudaGetSymbolAddress((void**)&xhi,   g_xhi);
    cudaGetSymbolAddress((void**)&wfhi,  g_wfhi);
    cudaGetSymbolAddress((void**)&wbhi,  g_wbhi);
    cudaGetSymbolAddress((void**)&wqhi,  g_wqhi);

    cudaFuncSetAttribute((const void*)mma_mm<1, 0, 128, 128, 128>, cudaFuncAttributeMaxDynamicSharedMemorySize, 2 * (128 + 128) * 144);
    cudaFuncSetAttribute((const void*)mma_mm<9, 1, 64, 64, 256>,   cudaFuncAttributeMaxDynamicSharedMemorySize, 2 * (64 + 256) * 144);
    cudaFuncSetAttribute((const void*)fus_mm, cudaFuncAttributeMaxDynamicSharedMemorySize, FUS_SMEM);

    // preprocessing (fp16 conversions)
    split_k<<<dim3(16, 128, 8), dim3(32, 8)>>>(x, xhi, 512, 0);
    wsplit_k<<<(512 * 1024 * 9 + 255) / 256, 256>>>(fus_w, wfhi, 1024, 9, (size_t)512 * 1024 * 9);
    wsplit_k<<<(64 * 512 * 9 + 255) / 256, 256>>>(box_w1, wbhi, 512, 9, (size_t)64 * 512 * 9);
    wsplit_k<<<(1536 * 512 + 255) / 256, 256>>>(qkv_w, wqhi, 512, 1, (size_t)1536 * 512);

    // box conv3x3(512->64)+GELU (1-term)
    mma_mm<9, 1, 64, 64, 256><<<dim3(128, 1), 256, 2 * (64 + 256) * 144>>>(
        wbhi, xhi, box_b1, box1, 512, 64);

    // qkv 1x1 (512->1536) (1-term)
    mma_mm<1, 0, 128, 128, 128><<<dim3(256, 12), 256, 2 * (128 + 128) * 144>>>(
        wqhi, xhi, qkv_b, qkv, 512, 1536);

    // box tail + edge net
    conv1x1_small_k<2><<<dim3(32, 16), 256>>>(box1, box_w2, box_b2, boxes, 64, 4);
    conv3x3_k<0><<<dim3(512, 1), 128>>>(boxes, 4, edge_w1, edge_b1, edge1, 64);
    gn_stats_k<<<64, 256>>>(edge1, gnst);
    gn_apply_k<<<8192, 256>>>(edge1, gnst, gn_g, gn_b);
    conv1x1_small_k<0><<<dim3(64, 16), 256>>>(edge1, edge_w2, edge_b2, edge, 64, 8);

    // attention (tensor cores, 1-term)
    attn_qk_mma<<<4096, 128>>>(qkv, edge, attn);
    softmax_i_k<<<2048, 128>>>(attn);
    attn_av_mma<<<4096, 128>>>(qkv, attn, agg);

    // convert agg into ci[512:1024) of the fp16 buffer
    split_k<<<dim3(16, 128, 8), dim3(32, 8)>>>(agg, xhi, 512, 512);

    // fusion conv3x3 (1024->512), B-halo reuse + 1-term fp16
    fus_mm<<<dim3(256, 4), 256, FUS_SMEM>>>(wfhi, xhi, fus_b, y);

    // batchnorm + SiLU
    bn_stats_k<<<512, 256>>>(y, bnst);
    bn_apply_k<<<65536, 256>>>(y, bnst, bn_g, bn_b, out);
}